// round 8
// baseline (speedup 1.0000x reference)
#include <cuda_runtime.h>
#include <cuda_bf16.h>
#include <math.h>
#include <stdint.h>

// ---------------------------------------------------------------------------
// TwoStageAttentionLayerCrossSegments  (B=16, TS_D=2, SEG=1024, D=256, H=8,
// DK=32, D_FF=1024)
// GEMMs + attention on mma.sync bf16. x/QKV split hi/lo (2-MMA);
// Att/MLP single-MMA bf16. QKV fused (N=768). Attention 128q x 64k tiles.
// ---------------------------------------------------------------------------

typedef __nv_bfloat16 bf16;

#define Bb   16
#define SEG  1024
#define Dd   256
#define Hh   8
#define DK   32
#define DFF  1024
#define NROWS_HALF (Bb*SEG)        // 16384
#define NROWS_FULL (Bb*2*SEG)      // 32768
#define NQKV 768

// fp32 scratch
__device__ float g_Z [NROWS_FULL * Dd];
__device__ float g_H1[NROWS_FULL * Dd];
__device__ float g_Z2[NROWS_FULL * Dd];

// bf16 activations
__device__ bf16 g_xHi  [NROWS_FULL * Dd],   g_xLo  [NROWS_FULL * Dd];
__device__ bf16 g_QKVHi[NROWS_HALF * NQKV], g_QKVLo[NROWS_HALF * NQKV];
__device__ bf16 g_AttHi[NROWS_FULL * Dd];
__device__ bf16 g_H1Hi [NROWS_FULL * Dd];
__device__ bf16 g_THi  [NROWS_FULL * DFF];

// transposed weights ([N,K] K-major), bf16
__device__ bf16 g_WqkvT[NQKV * Dd];
__device__ bf16 g_WoT[Dd * Dd];
__device__ bf16 g_W1T[DFF * Dd];
__device__ bf16 g_W2T[Dd * DFF];
__device__ float g_bqkv[NQKV];

// ---------------------------------------------------------------------------
// helpers
// ---------------------------------------------------------------------------
__device__ __forceinline__ uint32_t smem_u32(const void* p) {
    uint32_t a;
    asm("{ .reg .u64 t; cvta.to.shared.u64 t, %1; cvt.u32.u64 %0, t; }"
        : "=r"(a) : "l"(p));
    return a;
}

__device__ __forceinline__ void splitf(float v, bf16& h, bf16& l) {
    h = __float2bfloat16(v);
    l = __float2bfloat16(v - __bfloat162float(h));
}

__device__ __forceinline__ void cp16(uint32_t s, const void* g) {
    asm volatile("cp.async.cg.shared.global [%0], [%1], 16;" :: "r"(s), "l"(g));
}
#define CP_COMMIT() asm volatile("cp.async.commit_group;" ::: "memory")
#define CP_WAIT(n)  asm volatile("cp.async.wait_group %0;" :: "n"(n) : "memory")

__device__ __forceinline__ void ldsm4(uint32_t* r, uint32_t addr) {
    asm volatile("ldmatrix.sync.aligned.m8n8.x4.shared.b16 {%0,%1,%2,%3}, [%4];"
        : "=r"(r[0]), "=r"(r[1]), "=r"(r[2]), "=r"(r[3]) : "r"(addr));
}
__device__ __forceinline__ void ldsm4t(uint32_t* r, uint32_t addr) {
    asm volatile("ldmatrix.sync.aligned.m8n8.x4.trans.shared.b16 {%0,%1,%2,%3}, [%4];"
        : "=r"(r[0]), "=r"(r[1]), "=r"(r[2]), "=r"(r[3]) : "r"(addr));
}

__device__ __forceinline__ void mma_bf16(float* d, const uint32_t* a, const uint32_t* b) {
    asm volatile(
        "mma.sync.aligned.m16n8k16.row.col.f32.bf16.bf16.f32 "
        "{%0,%1,%2,%3}, {%4,%5,%6,%7}, {%8,%9}, {%0,%1,%2,%3};"
        : "+f"(d[0]), "+f"(d[1]), "+f"(d[2]), "+f"(d[3])
        : "r"(a[0]), "r"(a[1]), "r"(a[2]), "r"(a[3]), "r"(b[0]), "r"(b[1]));
}

// ---------------------------------------------------------------------------
// fp32 -> bf16 hi/lo split
// ---------------------------------------------------------------------------
__global__ void __launch_bounds__(256)
split_kernel(const float* __restrict__ X,
             bf16* __restrict__ Hi, bf16* __restrict__ Lo)
{
    const long i = ((long)blockIdx.x * 256 + threadIdx.x) * 4;
    float4 v = *(const float4*)(X + i);
    __nv_bfloat162 h0, h1, l0, l1;
    splitf(v.x, h0.x, l0.x); splitf(v.y, h0.y, l0.y);
    splitf(v.z, h1.x, l1.x); splitf(v.w, h1.y, l1.y);
    *(__nv_bfloat162*)(Hi + i)     = h0;
    *(__nv_bfloat162*)(Hi + i + 2) = h1;
    *(__nv_bfloat162*)(Lo + i)     = l0;
    *(__nv_bfloat162*)(Lo + i + 2) = l1;
}

// ---------------------------------------------------------------------------
// All weight transposes (bf16) + QKV bias concat, ONE launch.
// ---------------------------------------------------------------------------
__global__ void __launch_bounds__(256)
transpose_all(const float* __restrict__ Wq, const float* __restrict__ Wk,
              const float* __restrict__ Wv, const float* __restrict__ Wo,
              const float* __restrict__ W1, const float* __restrict__ W2,
              const float* __restrict__ bq, const float* __restrict__ bk,
              const float* __restrict__ bv,
              bf16* __restrict__ dWqkv, bf16* __restrict__ dWo,
              bf16* __restrict__ dW1, bf16* __restrict__ dW2,
              float* __restrict__ dbqkv)
{
    __shared__ float t[32][33];
    const int bid = blockIdx.x;
    const int tix = threadIdx.y * 32 + threadIdx.x;
    if (bid == 0 && tix < 256) {
        dbqkv[tix]       = bq[tix];
        dbqkv[tix + 256] = bk[tix];
        dbqkv[tix + 512] = bv[tix];
    }
    const float* S; bf16* D; int R, Cc, loc;
    if      (bid < 64)  { S = Wq; D = dWqkv;             R = Dd;  Cc = Dd;  loc = bid; }
    else if (bid < 128) { S = Wk; D = dWqkv + 256 * Dd;  R = Dd;  Cc = Dd;  loc = bid - 64; }
    else if (bid < 192) { S = Wv; D = dWqkv + 512 * Dd;  R = Dd;  Cc = Dd;  loc = bid - 128; }
    else if (bid < 256) { S = Wo; D = dWo;               R = Dd;  Cc = Dd;  loc = bid - 192; }
    else if (bid < 512) { S = W1; D = dW1;               R = Dd;  Cc = DFF; loc = bid - 256; }
    else                { S = W2; D = dW2;               R = DFF; Cc = Dd;  loc = bid - 512; }
    const int nbx = Cc / 32;
    const int c0 = (loc % nbx) * 32, r0 = (loc / nbx) * 32;
    #pragma unroll
    for (int i = threadIdx.y; i < 32; i += 8)
        t[i][threadIdx.x] = S[(long)(r0 + i) * Cc + c0 + threadIdx.x];
    __syncthreads();
    #pragma unroll
    for (int i = threadIdx.y; i < 32; i += 8)
        D[(long)(c0 + i) * R + r0 + threadIdx.x]
            = __float2bfloat16(t[threadIdx.x][i]);
}

// ---------------------------------------------------------------------------
// bf16 GEMM (mma.sync m16n8k16): C = (Ahi[+Alo]) @ bf16(W)^T.
// 128x128 tile, BK=32, 8 warps, double-buffered cp.async.
// ---------------------------------------------------------------------------
__global__ void __launch_bounds__(256, 2)
gemm_bf16(const bf16* __restrict__ Ahi, const bf16* __restrict__ Alo,
          const bf16* __restrict__ Bhi,
          const float* __restrict__ bias, const float* __restrict__ res,
          float* __restrict__ Cf,
          bf16* __restrict__ Chi, bf16* __restrict__ Clo,
          int Ntot, int K, int gather, int do_gelu)
{
    extern __shared__ char smem[];
    const uint32_t sb = smem_u32(smem);
    const int tid  = threadIdx.x;
    const int lane = tid & 31, wid = tid >> 5;
    const int wm = wid & 3, wn = wid >> 2;
    const int row0 = blockIdx.x * 128, col0 = blockIdx.y * 128;
    const int hasLo = (Alo != nullptr);
    const uint32_t Boff = hasLo ? 16384u : 8192u;
    const uint32_t ST   = hasLo ? 24576u : 16384u;

    uint32_t dstOff[2];
    long aIdx[2], bIdx[2];
    #pragma unroll
    for (int s = 0; s < 2; s++) {
        const int c  = tid + s * 256;
        const int r  = c >> 2, ch = c & 3;
        dstOff[s] = (uint32_t)(r * 64 + ((ch ^ (r & 3)) << 4));
        const int gA = row0 + r;
        long ar = gA;
        if (gather) {
            const int seg = (col0 >= 256) ? 1024 : 0;
            ar = (long)(gA >> 10) * 2048 + seg + (gA & 1023);
        }
        aIdx[s] = ar * (long)K + ch * 8;
        bIdx[s] = (long)(col0 + r) * K + ch * 8;
    }

    #pragma unroll
    for (int s = 0; s < 2; s++) {
        cp16(sb + 0    + dstOff[s], Ahi + aIdx[s]);
        if (hasLo) cp16(sb + 8192 + dstOff[s], Alo + aIdx[s]);
        cp16(sb + Boff + dstOff[s], Bhi + bIdx[s]);
    }
    CP_COMMIT();

    float acc[2][8][4] = {};
    const int CCH = K >> 5;
    const int rl = lane & 7, tl = lane >> 3;

    for (int c = 0; c < CCH; c++) {
        const uint32_t base = sb + (uint32_t)(c & 1) * ST;
        if (c + 1 < CCH) {
            const uint32_t nb = sb + (uint32_t)((c + 1) & 1) * ST;
            const long k0 = (long)(c + 1) * 32;
            #pragma unroll
            for (int s = 0; s < 2; s++) {
                cp16(nb + 0    + dstOff[s], Ahi + aIdx[s] + k0);
                if (hasLo) cp16(nb + 8192 + dstOff[s], Alo + aIdx[s] + k0);
                cp16(nb + Boff + dstOff[s], Bhi + bIdx[s] + k0);
            }
            CP_COMMIT();
            CP_WAIT(1);
        } else {
            CP_WAIT(0);
        }
        __syncthreads();

        #pragma unroll
        for (int ks = 0; ks < 2; ks++) {
            uint32_t aH[2][4], aL[2][4], bH[4][4];
            #pragma unroll
            for (int i = 0; i < 2; i++) {
                const int arow = wm * 32 + i * 16 + rl + (tl & 1) * 8;
                const int ach  = ks * 2 + (tl >> 1);
                const uint32_t ad = base + (uint32_t)(arow * 64
                                  + ((ach ^ (arow & 3)) << 4));
                ldsm4(aH[i], ad);
                if (hasLo) ldsm4(aL[i], ad + 8192);
            }
            #pragma unroll
            for (int j = 0; j < 4; j++) {
                const int brow = wn * 64 + j * 16 + rl + (tl >> 1) * 8;
                const int bch  = ks * 2 + (tl & 1);
                const uint32_t bd = base + Boff + (uint32_t)(brow * 64
                                  + ((bch ^ (brow & 3)) << 4));
                ldsm4(bH[j], bd);
            }
            #pragma unroll
            for (int i = 0; i < 2; i++) {
                #pragma unroll
                for (int j = 0; j < 4; j++) {
                    mma_bf16(acc[i][2*j],   aH[i], &bH[j][0]);
                    mma_bf16(acc[i][2*j+1], aH[i], &bH[j][2]);
                    if (hasLo) {
                        mma_bf16(acc[i][2*j],   aL[i], &bH[j][0]);
                        mma_bf16(acc[i][2*j+1], aL[i], &bH[j][2]);
                    }
                }
            }
        }
        __syncthreads();
    }

    #pragma unroll
    for (int i = 0; i < 2; i++) {
        const int r_top = row0 + wm * 32 + i * 16 + (lane >> 2);
        #pragma unroll
        for (int j = 0; j < 8; j++) {
            const int col = col0 + wn * 64 + j * 8 + (lane & 3) * 2;
            const float b0 = bias[col], b1 = bias[col + 1];
            float v00 = acc[i][j][0] + b0, v01 = acc[i][j][1] + b1;
            float v10 = acc[i][j][2] + b0, v11 = acc[i][j][3] + b1;
            if (do_gelu) {
                v00 = 0.5f * v00 * (1.0f + erff(v00 * 0.70710678118654752f));
                v01 = 0.5f * v01 * (1.0f + erff(v01 * 0.70710678118654752f));
                v10 = 0.5f * v10 * (1.0f + erff(v10 * 0.70710678118654752f));
                v11 = 0.5f * v11 * (1.0f + erff(v11 * 0.70710678118654752f));
            }
            const long o0 = (long)r_top * Ntot + col;
            const long o1 = (long)(r_top + 8) * Ntot + col;
            if (res) {
                v00 += res[o0]; v01 += res[o0 + 1];
                v10 += res[o1]; v11 += res[o1 + 1];
            }
            if (Cf) {
                *(float2*)(Cf + o0) = make_float2(v00, v01);
                *(float2*)(Cf + o1) = make_float2(v10, v11);
            }
            if (Chi) {
                if (Clo) {
                    __nv_bfloat162 h, l;
                    splitf(v00, h.x, l.x); splitf(v01, h.y, l.y);
                    *(__nv_bfloat162*)(Chi + o0) = h;
                    *(__nv_bfloat162*)(Clo + o0) = l;
                    splitf(v10, h.x, l.x); splitf(v11, h.y, l.y);
                    *(__nv_bfloat162*)(Chi + o1) = h;
                    *(__nv_bfloat162*)(Clo + o1) = l;
                } else {
                    *(__nv_bfloat162*)(Chi + o0) = __floats2bfloat162_rn(v00, v01);
                    *(__nv_bfloat162*)(Chi + o1) = __floats2bfloat162_rn(v10, v11);
                }
            }
        }
    }
}

// ---------------------------------------------------------------------------
// Tensor-core flash attention. Block = 128 queries x one (b,h) x stage;
// 4 warps x 32 q-rows. Keys in 64-row double-buffered tiles.
// Scores 2-MMA (Q hi/lo, K bf16); softmax fp32 (no max shift); PV bf16.
// Output: Att bf16 (hi only).
// ---------------------------------------------------------------------------
__global__ void __launch_bounds__(128)
attn_tc(const bf16* __restrict__ QKVh, const bf16* __restrict__ QKVl,
        bf16* __restrict__ OutHi)
{
    __shared__ bf16 sQ[2 * 4096];        // hi | lo, 128 rows  (16 KB)
    __shared__ bf16 sK[2][2048];         // 64 rows            (8 KB)
    __shared__ bf16 sV[2][2048];         //                    (8 KB)

    const int stage = blockIdx.z;
    const int qoff = stage ? 256 : 0;
    const int koff = stage ? 0 : 256;
    const int voff = stage ? 0 : 512;
    const int out_off = stage ? SEG : 0;

    const int bh = blockIdx.y;
    const int b  = bh >> 3;
    const int h  = bh & 7;
    const int q0 = blockIdx.x * 128;

    const int tid  = threadIdx.x;
    const int lane = tid & 31, warp = tid >> 5;
    const int rl = lane & 7, tl = lane >> 3;

    const uint32_t sQb = smem_u32(sQ);
    const uint32_t sKb[2] = { smem_u32(sK[0]), smem_u32(sK[1]) };
    const uint32_t sVb[2] = { smem_u32(sV[0]), smem_u32(sV[1]) };

    // --- load Q (hi|lo): 1024 chunks, 8 per thread ---
    #pragma unroll
    for (int s = 0; s < 8; s++) {
        const int c   = tid + s * 128;
        const int arr = c >> 9;                  // 0 hi, 1 lo
        const int r   = (c & 511) >> 2, ch = c & 3;
        const uint32_t dst = sQb + (uint32_t)(arr * 8192 + r * 64
                           + ((ch ^ (r & 3)) << 4));
        const bf16* src = (arr ? QKVl : QKVh)
                        + (long)(b * SEG + q0 + r) * NQKV + qoff + h * DK + ch * 8;
        cp16(dst, src);
    }
    CP_COMMIT();

    // --- prefetch key tile 0 (K + V: 512 chunks) ---
    #pragma unroll
    for (int s = 0; s < 4; s++) {
        const int c   = tid + s * 128;
        const int arr = c >> 8;                  // 0 K, 1 V
        const int r   = (c & 255) >> 2, ch = c & 3;
        const uint32_t off = (uint32_t)(r * 64 + ((ch ^ (r & 3)) << 4));
        const uint32_t dst = arr ? (sVb[0] + off) : (sKb[0] + off);
        const int coff = arr ? voff : koff;
        cp16(dst, QKVh + (long)(b * SEG + r) * NQKV + coff + h * DK + ch * 8);
    }
    CP_COMMIT();

    CP_WAIT(1);
    __syncthreads();
    uint32_t qh[2][2][4], ql[2][2][4];           // [m-tile][ks]
    #pragma unroll
    for (int m = 0; m < 2; m++) {
        #pragma unroll
        for (int ks = 0; ks < 2; ks++) {
            const int arow = warp * 32 + m * 16 + rl + (tl & 1) * 8;
            const int ach  = ks * 2 + (tl >> 1);
            const uint32_t ad = sQb + (uint32_t)(arow * 64
                              + ((ach ^ (arow & 3)) << 4));
            ldsm4(qh[m][ks], ad);
            ldsm4(ql[m][ks], ad + 8192);
        }
    }

    float o[2][4][4] = {};
    float lsum[2][2] = {};
    const float scale = 0.17677669529663687f;    // 1/sqrt(32)

    for (int t = 0; t < 16; t++) {
        const int buf = t & 1;
        if (t + 1 < 16) {
            const int nb = buf ^ 1;
            #pragma unroll
            for (int s = 0; s < 4; s++) {
                const int c   = tid + s * 128;
                const int arr = c >> 8;
                const int r   = (c & 255) >> 2, ch = c & 3;
                const uint32_t off = (uint32_t)(r * 64 + ((ch ^ (r & 3)) << 4));
                const uint32_t dst = arr ? (sVb[nb] + off) : (sKb[nb] + off);
                const int coff = arr ? voff : koff;
                cp16(dst, QKVh + (long)(b * SEG + (t + 1) * 64 + r) * NQKV
                          + coff + h * DK + ch * 8);
            }
            CP_COMMIT();
            CP_WAIT(1);
        } else {
            CP_WAIT(0);
        }
        __syncthreads();

        #pragma unroll
        for (int nb16 = 0; nb16 < 4; nb16++) {
            // --- scores: 16 MMAs per 2 K-fragment loads ---
            float s2[2][2][4] = {};
            #pragma unroll
            for (int ks = 0; ks < 2; ks++) {
                const int krow = nb16 * 16 + rl + (tl >> 1) * 8;
                const int kch  = ks * 2 + (tl & 1);
                const uint32_t ka = sKb[buf] + (uint32_t)(krow * 64
                                  + ((kch ^ (krow & 3)) << 4));
                uint32_t kh[4];
                ldsm4(kh, ka);
                #pragma unroll
                for (int m = 0; m < 2; m++) {
                    mma_bf16(s2[m][0], qh[m][ks], &kh[0]);
                    mma_bf16(s2[m][0], ql[m][ks], &kh[0]);
                    mma_bf16(s2[m][1], qh[m][ks], &kh[2]);
                    mma_bf16(s2[m][1], ql[m][ks], &kh[2]);
                }
            }
            // --- softmax + P pack ---
            uint32_t pf[2][4];
            #pragma unroll
            for (int m = 0; m < 2; m++) {
                float p00 = __expf(s2[m][0][0] * scale), p01 = __expf(s2[m][0][1] * scale);
                float p02 = __expf(s2[m][0][2] * scale), p03 = __expf(s2[m][0][3] * scale);
                float p10 = __expf(s2[m][1][0] * scale), p11 = __expf(s2[m][1][1] * scale);
                float p12 = __expf(s2[m][1][2] * scale), p13 = __expf(s2[m][1][3] * scale);
                lsum[m][0] += p00 + p01 + p10 + p11;
                lsum[m][1] += p02 + p03 + p12 + p13;
                __nv_bfloat162 t2;
                t2 = __floats2bfloat162_rn(p00, p01); pf[m][0] = *(uint32_t*)&t2;
                t2 = __floats2bfloat162_rn(p02, p03); pf[m][1] = *(uint32_t*)&t2;
                t2 = __floats2bfloat162_rn(p10, p11); pf[m][2] = *(uint32_t*)&t2;
                t2 = __floats2bfloat162_rn(p12, p13); pf[m][3] = *(uint32_t*)&t2;
            }
            // --- PV: 8 MMAs per 2 V-fragment loads ---
            #pragma unroll
            for (int db = 0; db < 2; db++) {
                const int vrow = nb16 * 16 + rl + (tl & 1) * 8;
                const int vch  = db * 2 + (tl >> 1);
                const uint32_t va = sVb[buf] + (uint32_t)(vrow * 64
                                  + ((vch ^ (vrow & 3)) << 4));
                uint32_t vf[4];
                ldsm4t(vf, va);
                #pragma unroll
                for (int m = 0; m < 2; m++) {
                    mma_bf16(o[m][db * 2],     pf[m], &vf[0]);
                    mma_bf16(o[m][db * 2 + 1], pf[m], &vf[2]);
                }
            }
        }
        __syncthreads();
    }

    // --- normalize + store bf16 (hi only) ---
    #pragma unroll
    for (int m = 0; m < 2; m++) {
        float l0 = lsum[m][0], l1 = lsum[m][1];
        l0 += __shfl_xor_sync(0xffffffffu, l0, 1);
        l0 += __shfl_xor_sync(0xffffffffu, l0, 2);
        l1 += __shfl_xor_sync(0xffffffffu, l1, 1);
        l1 += __shfl_xor_sync(0xffffffffu, l1, 2);
        const float inv0 = 1.0f / l0;
        const float inv1 = 1.0f / l1;

        const int rloc = q0 + warp * 32 + m * 16 + (lane >> 2);
        const long row0g = (long)(b * 2 * SEG + out_off + rloc) * Dd + h * DK;
        const long row1g = row0g + 8L * Dd;
        #pragma unroll
        for (int db = 0; db < 4; db++) {
            const int col = db * 8 + (lane & 3) * 2;
            *(__nv_bfloat162*)(OutHi + row0g + col)
                = __floats2bfloat162_rn(o[m][db][0] * inv0, o[m][db][1] * inv0);
            *(__nv_bfloat162*)(OutHi + row1g + col)
                = __floats2bfloat162_rn(o[m][db][2] * inv1, o[m][db][3] * inv1);
        }
    }
}

// ---------------------------------------------------------------------------
// LayerNorm (256-wide rows): warp per row; optional fp32 / bf16-hi outputs.
// ---------------------------------------------------------------------------
__global__ void __launch_bounds__(256)
ln_kernel(const float* __restrict__ X, const float* __restrict__ g,
          const float* __restrict__ beta, float* __restrict__ Y,
          bf16* __restrict__ YHi)
{
    const int row  = blockIdx.x * 8 + (threadIdx.x >> 5);
    const int lane = threadIdx.x & 31;
    const int c0   = lane * 8;
    const float* xr = X + (long)row * Dd + c0;

    float v[8];
    {
        float4 p0 = *(const float4*)xr;
        float4 p1 = *(const float4*)(xr + 4);
        v[0]=p0.x; v[1]=p0.y; v[2]=p0.z; v[3]=p0.w;
        v[4]=p1.x; v[5]=p1.y; v[6]=p1.z; v[7]=p1.w;
    }
    float s = 0.0f;
    #pragma unroll
    for (int i = 0; i < 8; i++) s += v[i];
    #pragma unroll
    for (int o = 16; o; o >>= 1) s += __shfl_xor_sync(0xffffffffu, s, o);
    const float mu = s * (1.0f / 256.0f);

    float ss = 0.0f;
    #pragma unroll
    for (int i = 0; i < 8; i++) { const float d = v[i] - mu; ss += d * d; }
    #pragma unroll
    for (int o = 16; o; o >>= 1) ss += __shfl_xor_sync(0xffffffffu, ss, o);
    const float inv = rsqrtf(ss * (1.0f / 256.0f) + 1e-5f);

    float4 g0 = *(const float4*)(g + c0),    g1 = *(const float4*)(g + c0 + 4);
    float4 e0 = *(const float4*)(beta + c0), e1 = *(const float4*)(beta + c0 + 4);
    float y[8];
    y[0] = (v[0]-mu)*inv*g0.x + e0.x; y[1] = (v[1]-mu)*inv*g0.y + e0.y;
    y[2] = (v[2]-mu)*inv*g0.z + e0.z; y[3] = (v[3]-mu)*inv*g0.w + e0.w;
    y[4] = (v[4]-mu)*inv*g1.x + e1.x; y[5] = (v[5]-mu)*inv*g1.y + e1.y;
    y[6] = (v[6]-mu)*inv*g1.z + e1.z; y[7] = (v[7]-mu)*inv*g1.w + e1.w;

    const long ob = (long)row * Dd + c0;
    if (Y) {
        *(float4*)(Y + ob)     = make_float4(y[0], y[1], y[2], y[3]);
        *(float4*)(Y + ob + 4) = make_float4(y[4], y[5], y[6], y[7]);
    }
    if (YHi) {
        #pragma unroll
        for (int p = 0; p < 4; p++)
            *(__nv_bfloat162*)(YHi + ob + 2*p)
                = __floats2bfloat162_rn(y[2*p], y[2*p+1]);
    }
}

// ---------------------------------------------------------------------------
// Launch
// ---------------------------------------------------------------------------
extern "C" void kernel_launch(void* const* d_in, const int* in_sizes, int n_in,
                              void* d_out, int out_size)
{
    const float* x   = (const float*)d_in[0];
    const float* Wq  = (const float*)d_in[1];
    const float* bq  = (const float*)d_in[2];
    const float* Wk  = (const float*)d_in[3];
    const float* bk  = (const float*)d_in[4];
    const float* Wv  = (const float*)d_in[5];
    const float* bv  = (const float*)d_in[6];
    const float* Wo  = (const float*)d_in[7];
    const float* bo  = (const float*)d_in[8];
    const float* g31 = (const float*)d_in[9];
    const float* b31 = (const float*)d_in[10];
    const float* W1  = (const float*)d_in[11];
    const float* b1  = (const float*)d_in[12];
    const float* W2  = (const float*)d_in[13];
    const float* b2  = (const float*)d_in[14];
    const float* g41 = (const float*)d_in[15];
    const float* b41 = (const float*)d_in[16];
    float* out = (float*)d_out;

    float *pZ, *pH1, *pZ2, *pbqkv;
    bf16 *xHi, *xLo, *QKVHi, *QKVLo, *AttHi, *H1Hi, *THi;
    bf16 *WqkvT, *WoT, *W1T, *W2T;

    cudaGetSymbolAddress((void**)&pZ,  g_Z);
    cudaGetSymbolAddress((void**)&pH1, g_H1);
    cudaGetSymbolAddress((void**)&pZ2, g_Z2);
    cudaGetSymbolAddress((void**)&pbqkv, g_bqkv);
    cudaGetSymbolAddress((void**)&xHi,   g_xHi);   cudaGetSymbolAddress((void**)&xLo,   g_xLo);
    cudaGetSymbolAddress((void**)&QKVHi, g_QKVHi); cudaGetSymbolAddress((void**)&QKVLo, g_QKVLo);
    cudaGetSymbolAddress((void**)&AttHi, g_AttHi);
    cudaGetSymbolAddress((void**)&H1Hi,  g_H1Hi);
    cudaGetSymbolAddress((void**)&THi,   g_THi);
    cudaGetSymbolAddress((void**)&WqkvT, g_WqkvT);
    cudaGetSymbolAddress((void**)&WoT, g_WoT);
    cudaGetSymbolAddress((void**)&W1T, g_W1T);
    cudaGetSymbolAddress((void**)&W2T, g_W2T);

    // weight prep + x split
    transpose_all<<<768, dim3(32, 8)>>>(Wq, Wk, Wv, Wo, W1, W2, bq, bk, bv,
                                        WqkvT, WoT, W1T, W2T, pbqkv);
    split_kernel<<<(NROWS_FULL * Dd) / 1024, 256>>>(x, xHi, xLo);

    // fused QKV projection (N=768, per-column segment gather)
    gemm_bf16<<<dim3(NROWS_HALF / 128, NQKV / 128), 256, 49152>>>(
        xHi, xLo, WqkvT, pbqkv, nullptr, nullptr, QKVHi, QKVLo,
        NQKV, Dd, 1, 0);

    // two-stage cross-segment attention (128q x 64k tiles)
    attn_tc<<<dim3(SEG / 128, Bb * Hh, 2), 128>>>(QKVHi, QKVLo, AttHi);

    // output projection + residual(x), LN1 (single-MMA A = bf16(Att))
    gemm_bf16<<<dim3(NROWS_FULL / 128, Dd / 128), 256, 32768>>>(
        AttHi, nullptr, WoT, bo, x, pZ, nullptr, nullptr, Dd, Dd, 0, 0);
    ln_kernel<<<NROWS_FULL / 8, 256>>>(pZ, g31, b31, pH1, H1Hi);

    // MLP (single-MMA bf16)
    gemm_bf16<<<dim3(NROWS_FULL / 128, DFF / 128), 256, 32768>>>(
        H1Hi, nullptr, W1T, b1, nullptr, nullptr, THi, nullptr, DFF, Dd, 0, 1);
    gemm_bf16<<<dim3(NROWS_FULL / 128, Dd / 128), 256, 32768>>>(
        THi, nullptr, W2T, b2, pH1, pZ2, nullptr, nullptr, Dd, DFF, 0, 0);
    ln_kernel<<<NROWS_FULL / 8, 256>>>(pZ2, g41, b41, out, nullptr);
}

// round 9
// speedup vs baseline: 1.5478x; 1.5478x over previous
#include <cuda_runtime.h>
#include <cuda_bf16.h>
#include <math.h>
#include <stdint.h>

// ---------------------------------------------------------------------------
// TwoStageAttentionLayerCrossSegments  (B=16, TS_D=2, SEG=1024, D=256, H=8,
// DK=32, D_FF=1024)
// GEMMs + attention on mma.sync bf16. x/QKV split hi/lo (2-MMA);
// Att/MLP single-MMA bf16. QKV fused (N=768). Attention 64q x 64k tiles.
// ---------------------------------------------------------------------------

typedef __nv_bfloat16 bf16;

#define Bb   16
#define SEG  1024
#define Dd   256
#define Hh   8
#define DK   32
#define DFF  1024
#define NROWS_HALF (Bb*SEG)        // 16384
#define NROWS_FULL (Bb*2*SEG)      // 32768
#define NQKV 768

// fp32 scratch
__device__ float g_Z [NROWS_FULL * Dd];
__device__ float g_H1[NROWS_FULL * Dd];
__device__ float g_Z2[NROWS_FULL * Dd];

// bf16 activations
__device__ bf16 g_xHi  [NROWS_FULL * Dd],   g_xLo  [NROWS_FULL * Dd];
__device__ bf16 g_QKVHi[NROWS_HALF * NQKV], g_QKVLo[NROWS_HALF * NQKV];
__device__ bf16 g_AttHi[NROWS_FULL * Dd];
__device__ bf16 g_H1Hi [NROWS_FULL * Dd];
__device__ bf16 g_THi  [NROWS_FULL * DFF];

// transposed weights ([N,K] K-major), bf16
__device__ bf16 g_WqkvT[NQKV * Dd];
__device__ bf16 g_WoT[Dd * Dd];
__device__ bf16 g_W1T[DFF * Dd];
__device__ bf16 g_W2T[Dd * DFF];
__device__ float g_bqkv[NQKV];

// ---------------------------------------------------------------------------
// helpers
// ---------------------------------------------------------------------------
__device__ __forceinline__ uint32_t smem_u32(const void* p) {
    uint32_t a;
    asm("{ .reg .u64 t; cvta.to.shared.u64 t, %1; cvt.u32.u64 %0, t; }"
        : "=r"(a) : "l"(p));
    return a;
}

__device__ __forceinline__ void splitf(float v, bf16& h, bf16& l) {
    h = __float2bfloat16(v);
    l = __float2bfloat16(v - __bfloat162float(h));
}

__device__ __forceinline__ void cp16(uint32_t s, const void* g) {
    asm volatile("cp.async.cg.shared.global [%0], [%1], 16;" :: "r"(s), "l"(g));
}
#define CP_COMMIT() asm volatile("cp.async.commit_group;" ::: "memory")
#define CP_WAIT(n)  asm volatile("cp.async.wait_group %0;" :: "n"(n) : "memory")

__device__ __forceinline__ void ldsm4(uint32_t* r, uint32_t addr) {
    asm volatile("ldmatrix.sync.aligned.m8n8.x4.shared.b16 {%0,%1,%2,%3}, [%4];"
        : "=r"(r[0]), "=r"(r[1]), "=r"(r[2]), "=r"(r[3]) : "r"(addr));
}
__device__ __forceinline__ void ldsm4t(uint32_t* r, uint32_t addr) {
    asm volatile("ldmatrix.sync.aligned.m8n8.x4.trans.shared.b16 {%0,%1,%2,%3}, [%4];"
        : "=r"(r[0]), "=r"(r[1]), "=r"(r[2]), "=r"(r[3]) : "r"(addr));
}

__device__ __forceinline__ void mma_bf16(float* d, const uint32_t* a, const uint32_t* b) {
    asm volatile(
        "mma.sync.aligned.m16n8k16.row.col.f32.bf16.bf16.f32 "
        "{%0,%1,%2,%3}, {%4,%5,%6,%7}, {%8,%9}, {%0,%1,%2,%3};"
        : "+f"(d[0]), "+f"(d[1]), "+f"(d[2]), "+f"(d[3])
        : "r"(a[0]), "r"(a[1]), "r"(a[2]), "r"(a[3]), "r"(b[0]), "r"(b[1]));
}

// ---------------------------------------------------------------------------
// fp32 -> bf16 hi/lo split
// ---------------------------------------------------------------------------
__global__ void __launch_bounds__(256)
split_kernel(const float* __restrict__ X,
             bf16* __restrict__ Hi, bf16* __restrict__ Lo)
{
    const long i = ((long)blockIdx.x * 256 + threadIdx.x) * 4;
    float4 v = *(const float4*)(X + i);
    __nv_bfloat162 h0, h1, l0, l1;
    splitf(v.x, h0.x, l0.x); splitf(v.y, h0.y, l0.y);
    splitf(v.z, h1.x, l1.x); splitf(v.w, h1.y, l1.y);
    *(__nv_bfloat162*)(Hi + i)     = h0;
    *(__nv_bfloat162*)(Hi + i + 2) = h1;
    *(__nv_bfloat162*)(Lo + i)     = l0;
    *(__nv_bfloat162*)(Lo + i + 2) = l1;
}

// ---------------------------------------------------------------------------
// All weight transposes (bf16) + QKV bias concat, ONE launch.
// ---------------------------------------------------------------------------
__global__ void __launch_bounds__(256)
transpose_all(const float* __restrict__ Wq, const float* __restrict__ Wk,
              const float* __restrict__ Wv, const float* __restrict__ Wo,
              const float* __restrict__ W1, const float* __restrict__ W2,
              const float* __restrict__ bq, const float* __restrict__ bk,
              const float* __restrict__ bv,
              bf16* __restrict__ dWqkv, bf16* __restrict__ dWo,
              bf16* __restrict__ dW1, bf16* __restrict__ dW2,
              float* __restrict__ dbqkv)
{
    __shared__ float t[32][33];
    const int bid = blockIdx.x;
    const int tix = threadIdx.y * 32 + threadIdx.x;
    if (bid == 0 && tix < 256) {
        dbqkv[tix]       = bq[tix];
        dbqkv[tix + 256] = bk[tix];
        dbqkv[tix + 512] = bv[tix];
    }
    const float* S; bf16* D; int R, Cc, loc;
    if      (bid < 64)  { S = Wq; D = dWqkv;             R = Dd;  Cc = Dd;  loc = bid; }
    else if (bid < 128) { S = Wk; D = dWqkv + 256 * Dd;  R = Dd;  Cc = Dd;  loc = bid - 64; }
    else if (bid < 192) { S = Wv; D = dWqkv + 512 * Dd;  R = Dd;  Cc = Dd;  loc = bid - 128; }
    else if (bid < 256) { S = Wo; D = dWo;               R = Dd;  Cc = Dd;  loc = bid - 192; }
    else if (bid < 512) { S = W1; D = dW1;               R = Dd;  Cc = DFF; loc = bid - 256; }
    else                { S = W2; D = dW2;               R = DFF; Cc = Dd;  loc = bid - 512; }
    const int nbx = Cc / 32;
    const int c0 = (loc % nbx) * 32, r0 = (loc / nbx) * 32;
    #pragma unroll
    for (int i = threadIdx.y; i < 32; i += 8)
        t[i][threadIdx.x] = S[(long)(r0 + i) * Cc + c0 + threadIdx.x];
    __syncthreads();
    #pragma unroll
    for (int i = threadIdx.y; i < 32; i += 8)
        D[(long)(c0 + i) * R + r0 + threadIdx.x]
            = __float2bfloat16(t[threadIdx.x][i]);
}

// ---------------------------------------------------------------------------
// bf16 GEMM (mma.sync m16n8k16): C = (Ahi[+Alo]) @ bf16(W)^T.
// 128x128 tile, BK=32, 8 warps, double-buffered cp.async.
// ---------------------------------------------------------------------------
__global__ void __launch_bounds__(256, 2)
gemm_bf16(const bf16* __restrict__ Ahi, const bf16* __restrict__ Alo,
          const bf16* __restrict__ Bhi,
          const float* __restrict__ bias, const float* __restrict__ res,
          float* __restrict__ Cf,
          bf16* __restrict__ Chi, bf16* __restrict__ Clo,
          int Ntot, int K, int gather, int do_gelu)
{
    extern __shared__ char smem[];
    const uint32_t sb = smem_u32(smem);
    const int tid  = threadIdx.x;
    const int lane = tid & 31, wid = tid >> 5;
    const int wm = wid & 3, wn = wid >> 2;
    const int row0 = blockIdx.x * 128, col0 = blockIdx.y * 128;
    const int hasLo = (Alo != nullptr);
    const uint32_t Boff = hasLo ? 16384u : 8192u;
    const uint32_t ST   = hasLo ? 24576u : 16384u;

    uint32_t dstOff[2];
    long aIdx[2], bIdx[2];
    #pragma unroll
    for (int s = 0; s < 2; s++) {
        const int c  = tid + s * 256;
        const int r  = c >> 2, ch = c & 3;
        dstOff[s] = (uint32_t)(r * 64 + ((ch ^ (r & 3)) << 4));
        const int gA = row0 + r;
        long ar = gA;
        if (gather) {
            const int seg = (col0 >= 256) ? 1024 : 0;
            ar = (long)(gA >> 10) * 2048 + seg + (gA & 1023);
        }
        aIdx[s] = ar * (long)K + ch * 8;
        bIdx[s] = (long)(col0 + r) * K + ch * 8;
    }

    #pragma unroll
    for (int s = 0; s < 2; s++) {
        cp16(sb + 0    + dstOff[s], Ahi + aIdx[s]);
        if (hasLo) cp16(sb + 8192 + dstOff[s], Alo + aIdx[s]);
        cp16(sb + Boff + dstOff[s], Bhi + bIdx[s]);
    }
    CP_COMMIT();

    float acc[2][8][4] = {};
    const int CCH = K >> 5;
    const int rl = lane & 7, tl = lane >> 3;

    for (int c = 0; c < CCH; c++) {
        const uint32_t base = sb + (uint32_t)(c & 1) * ST;
        if (c + 1 < CCH) {
            const uint32_t nb = sb + (uint32_t)((c + 1) & 1) * ST;
            const long k0 = (long)(c + 1) * 32;
            #pragma unroll
            for (int s = 0; s < 2; s++) {
                cp16(nb + 0    + dstOff[s], Ahi + aIdx[s] + k0);
                if (hasLo) cp16(nb + 8192 + dstOff[s], Alo + aIdx[s] + k0);
                cp16(nb + Boff + dstOff[s], Bhi + bIdx[s] + k0);
            }
            CP_COMMIT();
            CP_WAIT(1);
        } else {
            CP_WAIT(0);
        }
        __syncthreads();

        #pragma unroll
        for (int ks = 0; ks < 2; ks++) {
            uint32_t aH[2][4], aL[2][4], bH[4][4];
            #pragma unroll
            for (int i = 0; i < 2; i++) {
                const int arow = wm * 32 + i * 16 + rl + (tl & 1) * 8;
                const int ach  = ks * 2 + (tl >> 1);
                const uint32_t ad = base + (uint32_t)(arow * 64
                                  + ((ach ^ (arow & 3)) << 4));
                ldsm4(aH[i], ad);
                if (hasLo) ldsm4(aL[i], ad + 8192);
            }
            #pragma unroll
            for (int j = 0; j < 4; j++) {
                const int brow = wn * 64 + j * 16 + rl + (tl >> 1) * 8;
                const int bch  = ks * 2 + (tl & 1);
                const uint32_t bd = base + Boff + (uint32_t)(brow * 64
                                  + ((bch ^ (brow & 3)) << 4));
                ldsm4(bH[j], bd);
            }
            #pragma unroll
            for (int i = 0; i < 2; i++) {
                #pragma unroll
                for (int j = 0; j < 4; j++) {
                    mma_bf16(acc[i][2*j],   aH[i], &bH[j][0]);
                    mma_bf16(acc[i][2*j+1], aH[i], &bH[j][2]);
                    if (hasLo) {
                        mma_bf16(acc[i][2*j],   aL[i], &bH[j][0]);
                        mma_bf16(acc[i][2*j+1], aL[i], &bH[j][2]);
                    }
                }
            }
        }
        __syncthreads();
    }

    #pragma unroll
    for (int i = 0; i < 2; i++) {
        const int r_top = row0 + wm * 32 + i * 16 + (lane >> 2);
        #pragma unroll
        for (int j = 0; j < 8; j++) {
            const int col = col0 + wn * 64 + j * 8 + (lane & 3) * 2;
            const float b0 = bias[col], b1 = bias[col + 1];
            float v00 = acc[i][j][0] + b0, v01 = acc[i][j][1] + b1;
            float v10 = acc[i][j][2] + b0, v11 = acc[i][j][3] + b1;
            if (do_gelu) {
                v00 = 0.5f * v00 * (1.0f + erff(v00 * 0.70710678118654752f));
                v01 = 0.5f * v01 * (1.0f + erff(v01 * 0.70710678118654752f));
                v10 = 0.5f * v10 * (1.0f + erff(v10 * 0.70710678118654752f));
                v11 = 0.5f * v11 * (1.0f + erff(v11 * 0.70710678118654752f));
            }
            const long o0 = (long)r_top * Ntot + col;
            const long o1 = (long)(r_top + 8) * Ntot + col;
            if (res) {
                v00 += res[o0]; v01 += res[o0 + 1];
                v10 += res[o1]; v11 += res[o1 + 1];
            }
            if (Cf) {
                *(float2*)(Cf + o0) = make_float2(v00, v01);
                *(float2*)(Cf + o1) = make_float2(v10, v11);
            }
            if (Chi) {
                if (Clo) {
                    __nv_bfloat162 h, l;
                    splitf(v00, h.x, l.x); splitf(v01, h.y, l.y);
                    *(__nv_bfloat162*)(Chi + o0) = h;
                    *(__nv_bfloat162*)(Clo + o0) = l;
                    splitf(v10, h.x, l.x); splitf(v11, h.y, l.y);
                    *(__nv_bfloat162*)(Chi + o1) = h;
                    *(__nv_bfloat162*)(Clo + o1) = l;
                } else {
                    *(__nv_bfloat162*)(Chi + o0) = __floats2bfloat162_rn(v00, v01);
                    *(__nv_bfloat162*)(Chi + o1) = __floats2bfloat162_rn(v10, v11);
                }
            }
        }
    }
}

// ---------------------------------------------------------------------------
// Tensor-core flash attention (R7 shape: 64 queries/block, 16 rows/warp).
// Scores 2-MMA (Q hi/lo, K bf16); softmax fp32 (no max shift); PV bf16.
// Output: Att bf16 (hi only).
// ---------------------------------------------------------------------------
__global__ void __launch_bounds__(128)
attn_tc(const bf16* __restrict__ QKVh, const bf16* __restrict__ QKVl,
        bf16* __restrict__ OutHi)
{
    __shared__ bf16 sQ[2 * 2048];        // hi | lo  (8 KB)
    __shared__ bf16 sK[2][2048];         // hi only  (8 KB)
    __shared__ bf16 sV[2][2048];         //          (8 KB)

    const int stage = blockIdx.z;
    const int qoff = stage ? 256 : 0;
    const int koff = stage ? 0 : 256;
    const int voff = stage ? 0 : 512;
    const int out_off = stage ? SEG : 0;

    const int bh = blockIdx.y;
    const int b  = bh >> 3;
    const int h  = bh & 7;
    const int q0 = blockIdx.x * 64;

    const int tid  = threadIdx.x;
    const int lane = tid & 31, warp = tid >> 5;
    const int rl = lane & 7, tl = lane >> 3;

    const uint32_t sQb = smem_u32(sQ);
    const uint32_t sKb[2] = { smem_u32(sK[0]), smem_u32(sK[1]) };
    const uint32_t sVb[2] = { smem_u32(sV[0]), smem_u32(sV[1]) };

    // --- load Q (hi|lo): 512 chunks ---
    #pragma unroll
    for (int s = 0; s < 4; s++) {
        const int c   = tid + s * 128;
        const int arr = c >> 8;
        const int r   = (c & 255) >> 2, ch = c & 3;
        const uint32_t dst = sQb + (uint32_t)(arr * 4096 + r * 64
                           + ((ch ^ (r & 3)) << 4));
        const bf16* src = (arr ? QKVl : QKVh)
                        + (long)(b * SEG + q0 + r) * NQKV + qoff + h * DK + ch * 8;
        cp16(dst, src);
    }
    CP_COMMIT();

    // --- prefetch key tile 0 (K + V) ---
    #pragma unroll
    for (int s = 0; s < 4; s++) {
        const int c   = tid + s * 128;
        const int arr = c >> 8;                 // 0 K, 1 V
        const int r   = (c & 255) >> 2, ch = c & 3;
        const uint32_t off = (uint32_t)(r * 64 + ((ch ^ (r & 3)) << 4));
        const uint32_t dst = arr ? (sVb[0] + off) : (sKb[0] + off);
        const int coff = arr ? voff : koff;
        cp16(dst, QKVh + (long)(b * SEG + r) * NQKV + coff + h * DK + ch * 8);
    }
    CP_COMMIT();

    CP_WAIT(1);
    __syncthreads();
    uint32_t qh[2][4], ql[2][4];
    #pragma unroll
    for (int ks = 0; ks < 2; ks++) {
        const int arow = warp * 16 + rl + (tl & 1) * 8;
        const int ach  = ks * 2 + (tl >> 1);
        const uint32_t ad = sQb + (uint32_t)(arow * 64 + ((ach ^ (arow & 3)) << 4));
        ldsm4(qh[ks], ad);
        ldsm4(ql[ks], ad + 4096);
    }

    float o[4][4] = {};
    float lsum0 = 0.0f, lsum1 = 0.0f;
    const float scale = 0.17677669529663687f;   // 1/sqrt(32)

    for (int t = 0; t < 16; t++) {
        const int buf = t & 1;
        if (t + 1 < 16) {
            const int nb = buf ^ 1;
            #pragma unroll
            for (int s = 0; s < 4; s++) {
                const int c   = tid + s * 128;
                const int arr = c >> 8;
                const int r   = (c & 255) >> 2, ch = c & 3;
                const uint32_t off = (uint32_t)(r * 64 + ((ch ^ (r & 3)) << 4));
                const uint32_t dst = arr ? (sVb[nb] + off) : (sKb[nb] + off);
                const int coff = arr ? voff : koff;
                cp16(dst, QKVh + (long)(b * SEG + (t + 1) * 64 + r) * NQKV
                          + coff + h * DK + ch * 8);
            }
            CP_COMMIT();
            CP_WAIT(1);
        } else {
            CP_WAIT(0);
        }
        __syncthreads();

        #pragma unroll
        for (int nb16 = 0; nb16 < 4; nb16++) {
            float s2[2][4] = {};
            #pragma unroll
            for (int ks = 0; ks < 2; ks++) {
                const int krow = nb16 * 16 + rl + (tl >> 1) * 8;
                const int kch  = ks * 2 + (tl & 1);
                const uint32_t ka = sKb[buf] + (uint32_t)(krow * 64
                                  + ((kch ^ (krow & 3)) << 4));
                uint32_t kh[4];
                ldsm4(kh, ka);
                mma_bf16(s2[0], qh[ks], &kh[0]);
                mma_bf16(s2[0], ql[ks], &kh[0]);
                mma_bf16(s2[1], qh[ks], &kh[2]);
                mma_bf16(s2[1], ql[ks], &kh[2]);
            }
            float p00 = __expf(s2[0][0] * scale), p01 = __expf(s2[0][1] * scale);
            float p02 = __expf(s2[0][2] * scale), p03 = __expf(s2[0][3] * scale);
            float p10 = __expf(s2[1][0] * scale), p11 = __expf(s2[1][1] * scale);
            float p12 = __expf(s2[1][2] * scale), p13 = __expf(s2[1][3] * scale);
            lsum0 += p00 + p01 + p10 + p11;
            lsum1 += p02 + p03 + p12 + p13;
            uint32_t pf[4];
            __nv_bfloat162 t2;
            t2 = __floats2bfloat162_rn(p00, p01); pf[0] = *(uint32_t*)&t2;
            t2 = __floats2bfloat162_rn(p02, p03); pf[1] = *(uint32_t*)&t2;
            t2 = __floats2bfloat162_rn(p10, p11); pf[2] = *(uint32_t*)&t2;
            t2 = __floats2bfloat162_rn(p12, p13); pf[3] = *(uint32_t*)&t2;
            #pragma unroll
            for (int db = 0; db < 2; db++) {
                const int vrow = nb16 * 16 + rl + (tl & 1) * 8;
                const int vch  = db * 2 + (tl >> 1);
                const uint32_t va = sVb[buf] + (uint32_t)(vrow * 64
                                  + ((vch ^ (vrow & 3)) << 4));
                uint32_t vf[4];
                ldsm4t(vf, va);
                mma_bf16(o[db * 2],     pf, &vf[0]);
                mma_bf16(o[db * 2 + 1], pf, &vf[2]);
            }
        }
        __syncthreads();
    }

    lsum0 += __shfl_xor_sync(0xffffffffu, lsum0, 1);
    lsum0 += __shfl_xor_sync(0xffffffffu, lsum0, 2);
    lsum1 += __shfl_xor_sync(0xffffffffu, lsum1, 1);
    lsum1 += __shfl_xor_sync(0xffffffffu, lsum1, 2);
    const float inv0 = 1.0f / lsum0;
    const float inv1 = 1.0f / lsum1;

    const int rloc = q0 + warp * 16 + (lane >> 2);
    const long row0g = (long)(b * 2 * SEG + out_off + rloc) * Dd + h * DK;
    const long row1g = row0g + 8L * Dd;
    #pragma unroll
    for (int db = 0; db < 4; db++) {
        const int col = db * 8 + (lane & 3) * 2;
        *(__nv_bfloat162*)(OutHi + row0g + col)
            = __floats2bfloat162_rn(o[db][0] * inv0, o[db][1] * inv0);
        *(__nv_bfloat162*)(OutHi + row1g + col)
            = __floats2bfloat162_rn(o[db][2] * inv1, o[db][3] * inv1);
    }
}

// ---------------------------------------------------------------------------
// LayerNorm (256-wide rows): warp per row; optional fp32 / bf16-hi outputs.
// ---------------------------------------------------------------------------
__global__ void __launch_bounds__(256)
ln_kernel(const float* __restrict__ X, const float* __restrict__ g,
          const float* __restrict__ beta, float* __restrict__ Y,
          bf16* __restrict__ YHi)
{
    const int row  = blockIdx.x * 8 + (threadIdx.x >> 5);
    const int lane = threadIdx.x & 31;
    const int c0   = lane * 8;
    const float* xr = X + (long)row * Dd + c0;

    float v[8];
    {
        float4 p0 = *(const float4*)xr;
        float4 p1 = *(const float4*)(xr + 4);
        v[0]=p0.x; v[1]=p0.y; v[2]=p0.z; v[3]=p0.w;
        v[4]=p1.x; v[5]=p1.y; v[6]=p1.z; v[7]=p1.w;
    }
    float s = 0.0f;
    #pragma unroll
    for (int i = 0; i < 8; i++) s += v[i];
    #pragma unroll
    for (int o = 16; o; o >>= 1) s += __shfl_xor_sync(0xffffffffu, s, o);
    const float mu = s * (1.0f / 256.0f);

    float ss = 0.0f;
    #pragma unroll
    for (int i = 0; i < 8; i++) { const float d = v[i] - mu; ss += d * d; }
    #pragma unroll
    for (int o = 16; o; o >>= 1) ss += __shfl_xor_sync(0xffffffffu, ss, o);
    const float inv = rsqrtf(ss * (1.0f / 256.0f) + 1e-5f);

    float4 g0 = *(const float4*)(g + c0),    g1 = *(const float4*)(g + c0 + 4);
    float4 e0 = *(const float4*)(beta + c0), e1 = *(const float4*)(beta + c0 + 4);
    float y[8];
    y[0] = (v[0]-mu)*inv*g0.x + e0.x; y[1] = (v[1]-mu)*inv*g0.y + e0.y;
    y[2] = (v[2]-mu)*inv*g0.z + e0.z; y[3] = (v[3]-mu)*inv*g0.w + e0.w;
    y[4] = (v[4]-mu)*inv*g1.x + e1.x; y[5] = (v[5]-mu)*inv*g1.y + e1.y;
    y[6] = (v[6]-mu)*inv*g1.z + e1.z; y[7] = (v[7]-mu)*inv*g1.w + e1.w;

    const long ob = (long)row * Dd + c0;
    if (Y) {
        *(float4*)(Y + ob)     = make_float4(y[0], y[1], y[2], y[3]);
        *(float4*)(Y + ob + 4) = make_float4(y[4], y[5], y[6], y[7]);
    }
    if (YHi) {
        #pragma unroll
        for (int p = 0; p < 4; p++)
            *(__nv_bfloat162*)(YHi + ob + 2*p)
                = __floats2bfloat162_rn(y[2*p], y[2*p+1]);
    }
}

// ---------------------------------------------------------------------------
// Launch
// ---------------------------------------------------------------------------
extern "C" void kernel_launch(void* const* d_in, const int* in_sizes, int n_in,
                              void* d_out, int out_size)
{
    const float* x   = (const float*)d_in[0];
    const float* Wq  = (const float*)d_in[1];
    const float* bq  = (const float*)d_in[2];
    const float* Wk  = (const float*)d_in[3];
    const float* bk  = (const float*)d_in[4];
    const float* Wv  = (const float*)d_in[5];
    const float* bv  = (const float*)d_in[6];
    const float* Wo  = (const float*)d_in[7];
    const float* bo  = (const float*)d_in[8];
    const float* g31 = (const float*)d_in[9];
    const float* b31 = (const float*)d_in[10];
    const float* W1  = (const float*)d_in[11];
    const float* b1  = (const float*)d_in[12];
    const float* W2  = (const float*)d_in[13];
    const float* b2  = (const float*)d_in[14];
    const float* g41 = (const float*)d_in[15];
    const float* b41 = (const float*)d_in[16];
    float* out = (float*)d_out;

    float *pZ, *pH1, *pZ2, *pbqkv;
    bf16 *xHi, *xLo, *QKVHi, *QKVLo, *AttHi, *H1Hi, *THi;
    bf16 *WqkvT, *WoT, *W1T, *W2T;

    cudaGetSymbolAddress((void**)&pZ,  g_Z);
    cudaGetSymbolAddress((void**)&pH1, g_H1);
    cudaGetSymbolAddress((void**)&pZ2, g_Z2);
    cudaGetSymbolAddress((void**)&pbqkv, g_bqkv);
    cudaGetSymbolAddress((void**)&xHi,   g_xHi);   cudaGetSymbolAddress((void**)&xLo,   g_xLo);
    cudaGetSymbolAddress((void**)&QKVHi, g_QKVHi); cudaGetSymbolAddress((void**)&QKVLo, g_QKVLo);
    cudaGetSymbolAddress((void**)&AttHi, g_AttHi);
    cudaGetSymbolAddress((void**)&H1Hi,  g_H1Hi);
    cudaGetSymbolAddress((void**)&THi,   g_THi);
    cudaGetSymbolAddress((void**)&WqkvT, g_WqkvT);
    cudaGetSymbolAddress((void**)&WoT, g_WoT);
    cudaGetSymbolAddress((void**)&W1T, g_W1T);
    cudaGetSymbolAddress((void**)&W2T, g_W2T);

    // weight prep + x split
    transpose_all<<<768, dim3(32, 8)>>>(Wq, Wk, Wv, Wo, W1, W2, bq, bk, bv,
                                        WqkvT, WoT, W1T, W2T, pbqkv);
    split_kernel<<<(NROWS_FULL * Dd) / 1024, 256>>>(x, xHi, xLo);

    // fused QKV projection (N=768, per-column segment gather)
    gemm_bf16<<<dim3(NROWS_HALF / 128, NQKV / 128), 256, 49152>>>(
        xHi, xLo, WqkvT, pbqkv, nullptr, nullptr, QKVHi, QKVLo,
        NQKV, Dd, 1, 0);

    // two-stage cross-segment attention (64q x 64k tiles)
    attn_tc<<<dim3(SEG / 64, Bb * Hh, 2), 128>>>(QKVHi, QKVLo, AttHi);

    // output projection + residual(x), LN1 (single-MMA A = bf16(Att))
    gemm_bf16<<<dim3(NROWS_FULL / 128, Dd / 128), 256, 32768>>>(
        AttHi, nullptr, WoT, bo, x, pZ, nullptr, nullptr, Dd, Dd, 0, 0);
    ln_kernel<<<NROWS_FULL / 8, 256>>>(pZ, g31, b31, pH1, H1Hi);

    // MLP (single-MMA bf16)
    gemm_bf16<<<dim3(NROWS_FULL / 128, DFF / 128), 256, 32768>>>(
        H1Hi, nullptr, W1T, b1, nullptr, nullptr, THi, nullptr, DFF, Dd, 0, 1);
    gemm_bf16<<<dim3(NROWS_FULL / 128, Dd / 128), 256, 32768>>>(
        THi, nullptr, W2T, b2, pH1, pZ2, nullptr, nullptr, Dd, DFF, 0, 0);
    ln_kernel<<<NROWS_FULL / 8, 256>>>(pZ2, g41, b41, out, nullptr);
}

// round 11
// speedup vs baseline: 1.6536x; 1.0684x over previous
#include <cuda_runtime.h>
#include <cuda_bf16.h>
#include <math.h>
#include <stdint.h>

// ---------------------------------------------------------------------------
// TwoStageAttentionLayerCrossSegments  (B=16, TS_D=2, SEG=1024, D=256, H=8,
// DK=32, D_FF=1024)
// GEMMs + attention on mma.sync bf16. x split hi/lo (2-MMA) for QKV GEMM;
// everything downstream single-MMA bf16. 3-stage cp.async GEMM pipeline
// (wait -> sync -> mma -> prefetch; one barrier per K-chunk).
// ---------------------------------------------------------------------------

typedef __nv_bfloat16 bf16;

#define Bb   16
#define SEG  1024
#define Dd   256
#define Hh   8
#define DK   32
#define DFF  1024
#define NROWS_HALF (Bb*SEG)        // 16384
#define NROWS_FULL (Bb*2*SEG)      // 32768
#define NQKV 768

// fp32 scratch
__device__ float g_Z [NROWS_FULL * Dd];
__device__ float g_H1[NROWS_FULL * Dd];
__device__ float g_Z2[NROWS_FULL * Dd];

// bf16 activations
__device__ bf16 g_xHi  [NROWS_FULL * Dd],   g_xLo  [NROWS_FULL * Dd];
__device__ bf16 g_QKVHi[NROWS_HALF * NQKV];
__device__ bf16 g_AttHi[NROWS_FULL * Dd];
__device__ bf16 g_H1Hi [NROWS_FULL * Dd];
__device__ bf16 g_THi  [NROWS_FULL * DFF];

// transposed weights ([N,K] K-major), bf16
__device__ bf16 g_WqkvT[NQKV * Dd];
__device__ bf16 g_WoT[Dd * Dd];
__device__ bf16 g_W1T[DFF * Dd];
__device__ bf16 g_W2T[Dd * DFF];
__device__ float g_bqkv[NQKV];

// ---------------------------------------------------------------------------
// helpers
// ---------------------------------------------------------------------------
__device__ __forceinline__ uint32_t smem_u32(const void* p) {
    uint32_t a;
    asm("{ .reg .u64 t; cvta.to.shared.u64 t, %1; cvt.u32.u64 %0, t; }"
        : "=r"(a) : "l"(p));
    return a;
}

__device__ __forceinline__ void splitf(float v, bf16& h, bf16& l) {
    h = __float2bfloat16(v);
    l = __float2bfloat16(v - __bfloat162float(h));
}

__device__ __forceinline__ void cp16(uint32_t s, const void* g) {
    asm volatile("cp.async.cg.shared.global [%0], [%1], 16;" :: "r"(s), "l"(g));
}
#define CP_COMMIT() asm volatile("cp.async.commit_group;" ::: "memory")
#define CP_WAIT(n)  asm volatile("cp.async.wait_group %0;" :: "n"(n) : "memory")

__device__ __forceinline__ void ldsm4(uint32_t* r, uint32_t addr) {
    asm volatile("ldmatrix.sync.aligned.m8n8.x4.shared.b16 {%0,%1,%2,%3}, [%4];"
        : "=r"(r[0]), "=r"(r[1]), "=r"(r[2]), "=r"(r[3]) : "r"(addr));
}
__device__ __forceinline__ void ldsm4t(uint32_t* r, uint32_t addr) {
    asm volatile("ldmatrix.sync.aligned.m8n8.x4.trans.shared.b16 {%0,%1,%2,%3}, [%4];"
        : "=r"(r[0]), "=r"(r[1]), "=r"(r[2]), "=r"(r[3]) : "r"(addr));
}

__device__ __forceinline__ void mma_bf16(float* d, const uint32_t* a, const uint32_t* b) {
    asm volatile(
        "mma.sync.aligned.m16n8k16.row.col.f32.bf16.bf16.f32 "
        "{%0,%1,%2,%3}, {%4,%5,%6,%7}, {%8,%9}, {%0,%1,%2,%3};"
        : "+f"(d[0]), "+f"(d[1]), "+f"(d[2]), "+f"(d[3])
        : "r"(a[0]), "r"(a[1]), "r"(a[2]), "r"(a[3]), "r"(b[0]), "r"(b[1]));
}

// ---------------------------------------------------------------------------
// fp32 -> bf16 hi/lo split
// ---------------------------------------------------------------------------
__global__ void __launch_bounds__(256)
split_kernel(const float* __restrict__ X,
             bf16* __restrict__ Hi, bf16* __restrict__ Lo)
{
    const long i = ((long)blockIdx.x * 256 + threadIdx.x) * 4;
    float4 v = *(const float4*)(X + i);
    __nv_bfloat162 h0, h1, l0, l1;
    splitf(v.x, h0.x, l0.x); splitf(v.y, h0.y, l0.y);
    splitf(v.z, h1.x, l1.x); splitf(v.w, h1.y, l1.y);
    *(__nv_bfloat162*)(Hi + i)     = h0;
    *(__nv_bfloat162*)(Hi + i + 2) = h1;
    *(__nv_bfloat162*)(Lo + i)     = l0;
    *(__nv_bfloat162*)(Lo + i + 2) = l1;
}

// ---------------------------------------------------------------------------
// All weight transposes (bf16) + QKV bias concat, ONE launch.
// ---------------------------------------------------------------------------
__global__ void __launch_bounds__(256)
transpose_all(const float* __restrict__ Wq, const float* __restrict__ Wk,
              const float* __restrict__ Wv, const float* __restrict__ Wo,
              const float* __restrict__ W1, const float* __restrict__ W2,
              const float* __restrict__ bq, const float* __restrict__ bk,
              const float* __restrict__ bv,
              bf16* __restrict__ dWqkv, bf16* __restrict__ dWo,
              bf16* __restrict__ dW1, bf16* __restrict__ dW2,
              float* __restrict__ dbqkv)
{
    __shared__ float t[32][33];
    const int bid = blockIdx.x;
    const int tix = threadIdx.y * 32 + threadIdx.x;
    if (bid == 0 && tix < 256) {
        dbqkv[tix]       = bq[tix];
        dbqkv[tix + 256] = bk[tix];
        dbqkv[tix + 512] = bv[tix];
    }
    const float* S; bf16* D; int R, Cc, loc;
    if      (bid < 64)  { S = Wq; D = dWqkv;             R = Dd;  Cc = Dd;  loc = bid; }
    else if (bid < 128) { S = Wk; D = dWqkv + 256 * Dd;  R = Dd;  Cc = Dd;  loc = bid - 64; }
    else if (bid < 192) { S = Wv; D = dWqkv + 512 * Dd;  R = Dd;  Cc = Dd;  loc = bid - 128; }
    else if (bid < 256) { S = Wo; D = dWo;               R = Dd;  Cc = Dd;  loc = bid - 192; }
    else if (bid < 512) { S = W1; D = dW1;               R = Dd;  Cc = DFF; loc = bid - 256; }
    else                { S = W2; D = dW2;               R = DFF; Cc = Dd;  loc = bid - 512; }
    const int nbx = Cc / 32;
    const int c0 = (loc % nbx) * 32, r0 = (loc / nbx) * 32;
    #pragma unroll
    for (int i = threadIdx.y; i < 32; i += 8)
        t[i][threadIdx.x] = S[(long)(r0 + i) * Cc + c0 + threadIdx.x];
    __syncthreads();
    #pragma unroll
    for (int i = threadIdx.y; i < 32; i += 8)
        D[(long)(c0 + i) * R + r0 + threadIdx.x]
            = __float2bfloat16(t[threadIdx.x][i]);
}

// ---------------------------------------------------------------------------
// bf16 GEMM (mma.sync m16n8k16): C = (Ahi[+Alo]) @ bf16(W)^T.
// 128x128 tile, BK=32, 8 warps, 3-stage cp.async pipeline.
// Iteration order: wait(own g(c)) -> syncthreads -> ldsm/MMA -> prefetch c+2.
// ---------------------------------------------------------------------------
__global__ void __launch_bounds__(256, 2)
gemm_bf16(const bf16* __restrict__ Ahi, const bf16* __restrict__ Alo,
          const bf16* __restrict__ Bhi,
          const float* __restrict__ bias, const float* __restrict__ res,
          float* __restrict__ Cf,
          bf16* __restrict__ Chi, bf16* __restrict__ Clo,
          int Ntot, int K, int gather, int do_gelu)
{
    extern __shared__ char smem[];
    const uint32_t sb = smem_u32(smem);
    const int tid  = threadIdx.x;
    const int lane = tid & 31, wid = tid >> 5;
    const int wm = wid & 3, wn = wid >> 2;
    const int row0 = blockIdx.x * 128, col0 = blockIdx.y * 128;
    const int hasLo = (Alo != nullptr);
    const uint32_t Boff = hasLo ? 16384u : 8192u;
    const uint32_t ST   = hasLo ? 24576u : 16384u;

    uint32_t dstOff[2];
    long aIdx[2], bIdx[2];
    #pragma unroll
    for (int s = 0; s < 2; s++) {
        const int c  = tid + s * 256;
        const int r  = c >> 2, ch = c & 3;
        dstOff[s] = (uint32_t)(r * 64 + ((ch ^ (r & 3)) << 4));
        const int gA = row0 + r;
        long ar = gA;
        if (gather) {
            const int seg = (col0 >= 256) ? 1024 : 0;
            ar = (long)(gA >> 10) * 2048 + seg + (gA & 1023);
        }
        aIdx[s] = ar * (long)K + ch * 8;
        bIdx[s] = (long)(col0 + r) * K + ch * 8;
    }

    const int CCH = K >> 5;

    // prologue: prefetch chunks 0 and 1 into stages 0 and 1
    #pragma unroll
    for (int pc = 0; pc < 2; pc++) {
        const uint32_t st = sb + (uint32_t)pc * ST;
        const long k0 = (long)pc * 32;
        #pragma unroll
        for (int s = 0; s < 2; s++) {
            cp16(st + 0    + dstOff[s], Ahi + aIdx[s] + k0);
            if (hasLo) cp16(st + 8192 + dstOff[s], Alo + aIdx[s] + k0);
            cp16(st + Boff + dstOff[s], Bhi + bIdx[s] + k0);
        }
        CP_COMMIT();
    }

    float acc[2][8][4] = {};
    const int rl = lane & 7, tl = lane >> 3;

    int stg = 0;            // stage holding chunk c
    int pstg = 2;           // stage for chunk c+2
    for (int c = 0; c < CCH; c++) {
        // RAW: own group g(c) complete, then barrier so ALL threads' g(c)
        // writes are visible before anyone reads chunk c.
        if (c + 1 < CCH) { CP_WAIT(1); } else { CP_WAIT(0); }
        __syncthreads();

        const uint32_t base = sb + (uint32_t)stg * ST;
        #pragma unroll
        for (int ks = 0; ks < 2; ks++) {
            uint32_t aH[2][4], aL[2][4], bH[4][4];
            #pragma unroll
            for (int i = 0; i < 2; i++) {
                const int arow = wm * 32 + i * 16 + rl + (tl & 1) * 8;
                const int ach  = ks * 2 + (tl >> 1);
                const uint32_t ad = base + (uint32_t)(arow * 64
                                  + ((ach ^ (arow & 3)) << 4));
                ldsm4(aH[i], ad);
                if (hasLo) ldsm4(aL[i], ad + 8192);
            }
            #pragma unroll
            for (int j = 0; j < 4; j++) {
                const int brow = wn * 64 + j * 16 + rl + (tl >> 1) * 8;
                const int bch  = ks * 2 + (tl & 1);
                const uint32_t bd = base + Boff + (uint32_t)(brow * 64
                                  + ((bch ^ (brow & 3)) << 4));
                ldsm4(bH[j], bd);
            }
            #pragma unroll
            for (int i = 0; i < 2; i++) {
                #pragma unroll
                for (int j = 0; j < 4; j++) {
                    mma_bf16(acc[i][2*j],   aH[i], &bH[j][0]);
                    mma_bf16(acc[i][2*j+1], aH[i], &bH[j][2]);
                    if (hasLo) {
                        mma_bf16(acc[i][2*j],   aL[i], &bH[j][0]);
                        mma_bf16(acc[i][2*j+1], aL[i], &bH[j][2]);
                    }
                }
            }
        }

        // WAR-safe prefetch: stage pstg == (c-1)%3; all its readers retired
        // before the barrier above (their reads were in iteration c-1).
        if (c + 2 < CCH) {
            const uint32_t st = sb + (uint32_t)pstg * ST;
            const long k0 = (long)(c + 2) * 32;
            #pragma unroll
            for (int s = 0; s < 2; s++) {
                cp16(st + 0    + dstOff[s], Ahi + aIdx[s] + k0);
                if (hasLo) cp16(st + 8192 + dstOff[s], Alo + aIdx[s] + k0);
                cp16(st + Boff + dstOff[s], Bhi + bIdx[s] + k0);
            }
            CP_COMMIT();
        }
        stg  = (stg  == 2) ? 0 : stg  + 1;
        pstg = (pstg == 2) ? 0 : pstg + 1;
    }

    #pragma unroll
    for (int i = 0; i < 2; i++) {
        const int r_top = row0 + wm * 32 + i * 16 + (lane >> 2);
        #pragma unroll
        for (int j = 0; j < 8; j++) {
            const int col = col0 + wn * 64 + j * 8 + (lane & 3) * 2;
            const float b0 = bias[col], b1 = bias[col + 1];
            float v00 = acc[i][j][0] + b0, v01 = acc[i][j][1] + b1;
            float v10 = acc[i][j][2] + b0, v11 = acc[i][j][3] + b1;
            if (do_gelu) {
                v00 = 0.5f * v00 * (1.0f + erff(v00 * 0.70710678118654752f));
                v01 = 0.5f * v01 * (1.0f + erff(v01 * 0.70710678118654752f));
                v10 = 0.5f * v10 * (1.0f + erff(v10 * 0.70710678118654752f));
                v11 = 0.5f * v11 * (1.0f + erff(v11 * 0.70710678118654752f));
            }
            const long o0 = (long)r_top * Ntot + col;
            const long o1 = (long)(r_top + 8) * Ntot + col;
            if (res) {
                v00 += res[o0]; v01 += res[o0 + 1];
                v10 += res[o1]; v11 += res[o1 + 1];
            }
            if (Cf) {
                *(float2*)(Cf + o0) = make_float2(v00, v01);
                *(float2*)(Cf + o1) = make_float2(v10, v11);
            }
            if (Chi) {
                if (Clo) {
                    __nv_bfloat162 h, l;
                    splitf(v00, h.x, l.x); splitf(v01, h.y, l.y);
                    *(__nv_bfloat162*)(Chi + o0) = h;
                    *(__nv_bfloat162*)(Clo + o0) = l;
                    splitf(v10, h.x, l.x); splitf(v11, h.y, l.y);
                    *(__nv_bfloat162*)(Chi + o1) = h;
                    *(__nv_bfloat162*)(Clo + o1) = l;
                } else {
                    *(__nv_bfloat162*)(Chi + o0) = __floats2bfloat162_rn(v00, v01);
                    *(__nv_bfloat162*)(Chi + o1) = __floats2bfloat162_rn(v10, v11);
                }
            }
        }
    }
}

// ---------------------------------------------------------------------------
// Tensor-core flash attention (64 queries/block, 16 rows/warp).
// Scores single-MMA: bf16(q) x bf16(k). Softmax fp32 (no max shift). PV bf16.
// Output: Att bf16 (hi only).
// ---------------------------------------------------------------------------
__global__ void __launch_bounds__(128)
attn_tc(const bf16* __restrict__ QKVh, bf16* __restrict__ OutHi)
{
    __shared__ bf16 sQ[2048];            // 64 rows hi  (4 KB)
    __shared__ bf16 sK[2][2048];         //             (8 KB)
    __shared__ bf16 sV[2][2048];         //             (8 KB)

    const int stage = blockIdx.z;
    const int qoff = stage ? 256 : 0;
    const int koff = stage ? 0 : 256;
    const int voff = stage ? 0 : 512;
    const int out_off = stage ? SEG : 0;

    const int bh = blockIdx.y;
    const int b  = bh >> 3;
    const int h  = bh & 7;
    const int q0 = blockIdx.x * 64;

    const int tid  = threadIdx.x;
    const int lane = tid & 31, warp = tid >> 5;
    const int rl = lane & 7, tl = lane >> 3;

    const uint32_t sQb = smem_u32(sQ);
    const uint32_t sKb[2] = { smem_u32(sK[0]), smem_u32(sK[1]) };
    const uint32_t sVb[2] = { smem_u32(sV[0]), smem_u32(sV[1]) };

    // --- load Q (hi): 256 chunks ---
    #pragma unroll
    for (int s = 0; s < 2; s++) {
        const int c = tid + s * 128;
        const int r = c >> 2, ch = c & 3;
        const uint32_t dst = sQb + (uint32_t)(r * 64 + ((ch ^ (r & 3)) << 4));
        cp16(dst, QKVh + (long)(b * SEG + q0 + r) * NQKV + qoff + h * DK + ch * 8);
    }
    CP_COMMIT();

    // --- prefetch key tile 0 (K + V) ---
    #pragma unroll
    for (int s = 0; s < 4; s++) {
        const int c   = tid + s * 128;
        const int arr = c >> 8;                 // 0 K, 1 V
        const int r   = (c & 255) >> 2, ch = c & 3;
        const uint32_t off = (uint32_t)(r * 64 + ((ch ^ (r & 3)) << 4));
        const uint32_t dst = arr ? (sVb[0] + off) : (sKb[0] + off);
        const int coff = arr ? voff : koff;
        cp16(dst, QKVh + (long)(b * SEG + r) * NQKV + coff + h * DK + ch * 8);
    }
    CP_COMMIT();

    CP_WAIT(1);
    __syncthreads();
    uint32_t qh[2][4];
    #pragma unroll
    for (int ks = 0; ks < 2; ks++) {
        const int arow = warp * 16 + rl + (tl & 1) * 8;
        const int ach  = ks * 2 + (tl >> 1);
        const uint32_t ad = sQb + (uint32_t)(arow * 64 + ((ach ^ (arow & 3)) << 4));
        ldsm4(qh[ks], ad);
    }

    float o[4][4] = {};
    float lsum0 = 0.0f, lsum1 = 0.0f;
    const float scale = 0.17677669529663687f;   // 1/sqrt(32)

    for (int t = 0; t < 16; t++) {
        const int buf = t & 1;
        if (t + 1 < 16) {
            const int nb = buf ^ 1;
            #pragma unroll
            for (int s = 0; s < 4; s++) {
                const int c   = tid + s * 128;
                const int arr = c >> 8;
                const int r   = (c & 255) >> 2, ch = c & 3;
                const uint32_t off = (uint32_t)(r * 64 + ((ch ^ (r & 3)) << 4));
                const uint32_t dst = arr ? (sVb[nb] + off) : (sKb[nb] + off);
                const int coff = arr ? voff : koff;
                cp16(dst, QKVh + (long)(b * SEG + (t + 1) * 64 + r) * NQKV
                          + coff + h * DK + ch * 8);
            }
            CP_COMMIT();
            CP_WAIT(1);
        } else {
            CP_WAIT(0);
        }
        __syncthreads();

        #pragma unroll
        for (int nb16 = 0; nb16 < 4; nb16++) {
            float s2[2][4] = {};
            #pragma unroll
            for (int ks = 0; ks < 2; ks++) {
                const int krow = nb16 * 16 + rl + (tl >> 1) * 8;
                const int kch  = ks * 2 + (tl & 1);
                const uint32_t ka = sKb[buf] + (uint32_t)(krow * 64
                                  + ((kch ^ (krow & 3)) << 4));
                uint32_t kh[4];
                ldsm4(kh, ka);
                mma_bf16(s2[0], qh[ks], &kh[0]);
                mma_bf16(s2[1], qh[ks], &kh[2]);
            }
            float p00 = __expf(s2[0][0] * scale), p01 = __expf(s2[0][1] * scale);
            float p02 = __expf(s2[0][2] * scale), p03 = __expf(s2[0][3] * scale);
            float p10 = __expf(s2[1][0] * scale), p11 = __expf(s2[1][1] * scale);
            float p12 = __expf(s2[1][2] * scale), p13 = __expf(s2[1][3] * scale);
            lsum0 += p00 + p01 + p10 + p11;
            lsum1 += p02 + p03 + p12 + p13;
            uint32_t pf[4];
            __nv_bfloat162 t2;
            t2 = __floats2bfloat162_rn(p00, p01); pf[0] = *(uint32_t*)&t2;
            t2 = __floats2bfloat162_rn(p02, p03); pf[1] = *(uint32_t*)&t2;
            t2 = __floats2bfloat162_rn(p10, p11); pf[2] = *(uint32_t*)&t2;
            t2 = __floats2bfloat162_rn(p12, p13); pf[3] = *(uint32_t*)&t2;
            #pragma unroll
            for (int db = 0; db < 2; db++) {
                const int vrow = nb16 * 16 + rl + (tl & 1) * 8;
                const int vch  = db * 2 + (tl >> 1);
                const uint32_t va = sVb[buf] + (uint32_t)(vrow * 64
                                  + ((vch ^ (vrow & 3)) << 4));
                uint32_t vf[4];
                ldsm4t(vf, va);
                mma_bf16(o[db * 2],     pf, &vf[0]);
                mma_bf16(o[db * 2 + 1], pf, &vf[2]);
            }
        }
        __syncthreads();
    }

    lsum0 += __shfl_xor_sync(0xffffffffu, lsum0, 1);
    lsum0 += __shfl_xor_sync(0xffffffffu, lsum0, 2);
    lsum1 += __shfl_xor_sync(0xffffffffu, lsum1, 1);
    lsum1 += __shfl_xor_sync(0xffffffffu, lsum1, 2);
    const float inv0 = 1.0f / lsum0;
    const float inv1 = 1.0f / lsum1;

    const int rloc = q0 + warp * 16 + (lane >> 2);
    const long row0g = (long)(b * 2 * SEG + out_off + rloc) * Dd + h * DK;
    const long row1g = row0g + 8L * Dd;
    #pragma unroll
    for (int db = 0; db < 4; db++) {
        const int col = db * 8 + (lane & 3) * 2;
        *(__nv_bfloat162*)(OutHi + row0g + col)
            = __floats2bfloat162_rn(o[db][0] * inv0, o[db][1] * inv0);
        *(__nv_bfloat162*)(OutHi + row1g + col)
            = __floats2bfloat162_rn(o[db][2] * inv1, o[db][3] * inv1);
    }
}

// ---------------------------------------------------------------------------
// LayerNorm (256-wide rows): warp per row; optional fp32 / bf16-hi outputs.
// ---------------------------------------------------------------------------
__global__ void __launch_bounds__(256)
ln_kernel(const float* __restrict__ X, const float* __restrict__ g,
          const float* __restrict__ beta, float* __restrict__ Y,
          bf16* __restrict__ YHi)
{
    const int row  = blockIdx.x * 8 + (threadIdx.x >> 5);
    const int lane = threadIdx.x & 31;
    const int c0   = lane * 8;
    const float* xr = X + (long)row * Dd + c0;

    float v[8];
    {
        float4 p0 = *(const float4*)xr;
        float4 p1 = *(const float4*)(xr + 4);
        v[0]=p0.x; v[1]=p0.y; v[2]=p0.z; v[3]=p0.w;
        v[4]=p1.x; v[5]=p1.y; v[6]=p1.z; v[7]=p1.w;
    }
    float s = 0.0f;
    #pragma unroll
    for (int i = 0; i < 8; i++) s += v[i];
    #pragma unroll
    for (int o = 16; o; o >>= 1) s += __shfl_xor_sync(0xffffffffu, s, o);
    const float mu = s * (1.0f / 256.0f);

    float ss = 0.0f;
    #pragma unroll
    for (int i = 0; i < 8; i++) { const float d = v[i] - mu; ss += d * d; }
    #pragma unroll
    for (int o = 16; o; o >>= 1) ss += __shfl_xor_sync(0xffffffffu, ss, o);
    const float inv = rsqrtf(ss * (1.0f / 256.0f) + 1e-5f);

    float4 g0 = *(const float4*)(g + c0),    g1 = *(const float4*)(g + c0 + 4);
    float4 e0 = *(const float4*)(beta + c0), e1 = *(const float4*)(beta + c0 + 4);
    float y[8];
    y[0] = (v[0]-mu)*inv*g0.x + e0.x; y[1] = (v[1]-mu)*inv*g0.y + e0.y;
    y[2] = (v[2]-mu)*inv*g0.z + e0.z; y[3] = (v[3]-mu)*inv*g0.w + e0.w;
    y[4] = (v[4]-mu)*inv*g1.x + e1.x; y[5] = (v[5]-mu)*inv*g1.y + e1.y;
    y[6] = (v[6]-mu)*inv*g1.z + e1.z; y[7] = (v[7]-mu)*inv*g1.w + e1.w;

    const long ob = (long)row * Dd + c0;
    if (Y) {
        *(float4*)(Y + ob)     = make_float4(y[0], y[1], y[2], y[3]);
        *(float4*)(Y + ob + 4) = make_float4(y[4], y[5], y[6], y[7]);
    }
    if (YHi) {
        #pragma unroll
        for (int p = 0; p < 4; p++)
            *(__nv_bfloat162*)(YHi + ob + 2*p)
                = __floats2bfloat162_rn(y[2*p], y[2*p+1]);
    }
}

// ---------------------------------------------------------------------------
// Launch
// ---------------------------------------------------------------------------
extern "C" void kernel_launch(void* const* d_in, const int* in_sizes, int n_in,
                              void* d_out, int out_size)
{
    const float* x   = (const float*)d_in[0];
    const float* Wq  = (const float*)d_in[1];
    const float* bq  = (const float*)d_in[2];
    const float* Wk  = (const float*)d_in[3];
    const float* bk  = (const float*)d_in[4];
    const float* Wv  = (const float*)d_in[5];
    const float* bv  = (const float*)d_in[6];
    const float* Wo  = (const float*)d_in[7];
    const float* bo  = (const float*)d_in[8];
    const float* g31 = (const float*)d_in[9];
    const float* b31 = (const float*)d_in[10];
    const float* W1  = (const float*)d_in[11];
    const float* b1  = (const float*)d_in[12];
    const float* W2  = (const float*)d_in[13];
    const float* b2  = (const float*)d_in[14];
    const float* g41 = (const float*)d_in[15];
    const float* b41 = (const float*)d_in[16];
    float* out = (float*)d_out;

    float *pZ, *pH1, *pZ2, *pbqkv;
    bf16 *xHi, *xLo, *QKVHi, *AttHi, *H1Hi, *THi;
    bf16 *WqkvT, *WoT, *W1T, *W2T;

    cudaGetSymbolAddress((void**)&pZ,  g_Z);
    cudaGetSymbolAddress((void**)&pH1, g_H1);
    cudaGetSymbolAddress((void**)&pZ2, g_Z2);
    cudaGetSymbolAddress((void**)&pbqkv, g_bqkv);
    cudaGetSymbolAddress((void**)&xHi,   g_xHi);   cudaGetSymbolAddress((void**)&xLo, g_xLo);
    cudaGetSymbolAddress((void**)&QKVHi, g_QKVHi);
    cudaGetSymbolAddress((void**)&AttHi, g_AttHi);
    cudaGetSymbolAddress((void**)&H1Hi,  g_H1Hi);
    cudaGetSymbolAddress((void**)&THi,   g_THi);
    cudaGetSymbolAddress((void**)&WqkvT, g_WqkvT);
    cudaGetSymbolAddress((void**)&WoT, g_WoT);
    cudaGetSymbolAddress((void**)&W1T, g_W1T);
    cudaGetSymbolAddress((void**)&W2T, g_W2T);

    static bool attr_set = false;
    if (!attr_set) {
        cudaFuncSetAttribute(gemm_bf16,
            cudaFuncAttributeMaxDynamicSharedMemorySize, 73728);
        attr_set = true;
    }

    // weight prep + x split
    transpose_all<<<768, dim3(32, 8)>>>(Wq, Wk, Wv, Wo, W1, W2, bq, bk, bv,
                                        WqkvT, WoT, W1T, W2T, pbqkv);
    split_kernel<<<(NROWS_FULL * Dd) / 1024, 256>>>(x, xHi, xLo);

    // fused QKV projection (N=768, per-column segment gather; 2-MMA; hi out)
    gemm_bf16<<<dim3(NROWS_HALF / 128, NQKV / 128), 256, 73728>>>(
        xHi, xLo, WqkvT, pbqkv, nullptr, nullptr, QKVHi, nullptr,
        NQKV, Dd, 1, 0);

    // two-stage cross-segment attention (hi-only scores)
    attn_tc<<<dim3(SEG / 64, Bb * Hh, 2), 128>>>(QKVHi, AttHi);

    // output projection + residual(x), LN1
    gemm_bf16<<<dim3(NROWS_FULL / 128, Dd / 128), 256, 49152>>>(
        AttHi, nullptr, WoT, bo, x, pZ, nullptr, nullptr, Dd, Dd, 0, 0);
    ln_kernel<<<NROWS_FULL / 8, 256>>>(pZ, g31, b31, pH1, H1Hi);

    // MLP (single-MMA bf16)
    gemm_bf16<<<dim3(NROWS_FULL / 128, DFF / 128), 256, 49152>>>(
        H1Hi, nullptr, W1T, b1, nullptr, nullptr, THi, nullptr, DFF, Dd, 0, 1);
    gemm_bf16<<<dim3(NROWS_FULL / 128, Dd / 128), 256, 49152>>>(
        THi, nullptr, W2T, b2, pH1, pZ2, nullptr, nullptr, Dd, DFF, 0, 0);
    ln_kernel<<<NROWS_FULL / 8, 256>>>(pZ2, g41, b41, out, nullptr);
}

// round 12
// speedup vs baseline: 1.7224x; 1.0416x over previous
#include <cuda_runtime.h>
#include <cuda_bf16.h>
#include <math.h>
#include <stdint.h>

// ---------------------------------------------------------------------------
// TwoStageAttentionLayerCrossSegments  (B=16, TS_D=2, SEG=1024, D=256, H=8,
// DK=32, D_FF=1024)
// GEMMs + attention on mma.sync bf16. x split hi/lo (2-MMA) for QKV GEMM;
// everything downstream single-MMA bf16. 3-stage cp.async GEMM pipeline.
// Attention: 128 q/block, 4 warps x 2 m-tiles (K/V fragment reuse).
// ---------------------------------------------------------------------------

typedef __nv_bfloat16 bf16;

#define Bb   16
#define SEG  1024
#define Dd   256
#define Hh   8
#define DK   32
#define DFF  1024
#define NROWS_HALF (Bb*SEG)        // 16384
#define NROWS_FULL (Bb*2*SEG)      // 32768
#define NQKV 768

// fp32 scratch
__device__ float g_Z [NROWS_FULL * Dd];
__device__ float g_H1[NROWS_FULL * Dd];
__device__ float g_Z2[NROWS_FULL * Dd];

// bf16 activations
__device__ bf16 g_xHi  [NROWS_FULL * Dd],   g_xLo  [NROWS_FULL * Dd];
__device__ bf16 g_QKVHi[NROWS_HALF * NQKV];
__device__ bf16 g_AttHi[NROWS_FULL * Dd];
__device__ bf16 g_H1Hi [NROWS_FULL * Dd];
__device__ bf16 g_THi  [NROWS_FULL * DFF];

// transposed weights ([N,K] K-major), bf16
__device__ bf16 g_WqkvT[NQKV * Dd];
__device__ bf16 g_WoT[Dd * Dd];
__device__ bf16 g_W1T[DFF * Dd];
__device__ bf16 g_W2T[Dd * DFF];
__device__ float g_bqkv[NQKV];

// ---------------------------------------------------------------------------
// helpers
// ---------------------------------------------------------------------------
__device__ __forceinline__ uint32_t smem_u32(const void* p) {
    uint32_t a;
    asm("{ .reg .u64 t; cvta.to.shared.u64 t, %1; cvt.u32.u64 %0, t; }"
        : "=r"(a) : "l"(p));
    return a;
}

__device__ __forceinline__ void splitf(float v, bf16& h, bf16& l) {
    h = __float2bfloat16(v);
    l = __float2bfloat16(v - __bfloat162float(h));
}

__device__ __forceinline__ void cp16(uint32_t s, const void* g) {
    asm volatile("cp.async.cg.shared.global [%0], [%1], 16;" :: "r"(s), "l"(g));
}
#define CP_COMMIT() asm volatile("cp.async.commit_group;" ::: "memory")
#define CP_WAIT(n)  asm volatile("cp.async.wait_group %0;" :: "n"(n) : "memory")

__device__ __forceinline__ void ldsm4(uint32_t* r, uint32_t addr) {
    asm volatile("ldmatrix.sync.aligned.m8n8.x4.shared.b16 {%0,%1,%2,%3}, [%4];"
        : "=r"(r[0]), "=r"(r[1]), "=r"(r[2]), "=r"(r[3]) : "r"(addr));
}
__device__ __forceinline__ void ldsm4t(uint32_t* r, uint32_t addr) {
    asm volatile("ldmatrix.sync.aligned.m8n8.x4.trans.shared.b16 {%0,%1,%2,%3}, [%4];"
        : "=r"(r[0]), "=r"(r[1]), "=r"(r[2]), "=r"(r[3]) : "r"(addr));
}

__device__ __forceinline__ void mma_bf16(float* d, const uint32_t* a, const uint32_t* b) {
    asm volatile(
        "mma.sync.aligned.m16n8k16.row.col.f32.bf16.bf16.f32 "
        "{%0,%1,%2,%3}, {%4,%5,%6,%7}, {%8,%9}, {%0,%1,%2,%3};"
        : "+f"(d[0]), "+f"(d[1]), "+f"(d[2]), "+f"(d[3])
        : "r"(a[0]), "r"(a[1]), "r"(a[2]), "r"(a[3]), "r"(b[0]), "r"(b[1]));
}

// ---------------------------------------------------------------------------
// fp32 -> bf16 hi/lo split
// ---------------------------------------------------------------------------
__global__ void __launch_bounds__(256)
split_kernel(const float* __restrict__ X,
             bf16* __restrict__ Hi, bf16* __restrict__ Lo)
{
    const long i = ((long)blockIdx.x * 256 + threadIdx.x) * 4;
    float4 v = *(const float4*)(X + i);
    __nv_bfloat162 h0, h1, l0, l1;
    splitf(v.x, h0.x, l0.x); splitf(v.y, h0.y, l0.y);
    splitf(v.z, h1.x, l1.x); splitf(v.w, h1.y, l1.y);
    *(__nv_bfloat162*)(Hi + i)     = h0;
    *(__nv_bfloat162*)(Hi + i + 2) = h1;
    *(__nv_bfloat162*)(Lo + i)     = l0;
    *(__nv_bfloat162*)(Lo + i + 2) = l1;
}

// ---------------------------------------------------------------------------
// All weight transposes (bf16) + QKV bias concat, ONE launch.
// ---------------------------------------------------------------------------
__global__ void __launch_bounds__(256)
transpose_all(const float* __restrict__ Wq, const float* __restrict__ Wk,
              const float* __restrict__ Wv, const float* __restrict__ Wo,
              const float* __restrict__ W1, const float* __restrict__ W2,
              const float* __restrict__ bq, const float* __restrict__ bk,
              const float* __restrict__ bv,
              bf16* __restrict__ dWqkv, bf16* __restrict__ dWo,
              bf16* __restrict__ dW1, bf16* __restrict__ dW2,
              float* __restrict__ dbqkv)
{
    __shared__ float t[32][33];
    const int bid = blockIdx.x;
    const int tix = threadIdx.y * 32 + threadIdx.x;
    if (bid == 0 && tix < 256) {
        dbqkv[tix]       = bq[tix];
        dbqkv[tix + 256] = bk[tix];
        dbqkv[tix + 512] = bv[tix];
    }
    const float* S; bf16* D; int R, Cc, loc;
    if      (bid < 64)  { S = Wq; D = dWqkv;             R = Dd;  Cc = Dd;  loc = bid; }
    else if (bid < 128) { S = Wk; D = dWqkv + 256 * Dd;  R = Dd;  Cc = Dd;  loc = bid - 64; }
    else if (bid < 192) { S = Wv; D = dWqkv + 512 * Dd;  R = Dd;  Cc = Dd;  loc = bid - 128; }
    else if (bid < 256) { S = Wo; D = dWo;               R = Dd;  Cc = Dd;  loc = bid - 192; }
    else if (bid < 512) { S = W1; D = dW1;               R = Dd;  Cc = DFF; loc = bid - 256; }
    else                { S = W2; D = dW2;               R = DFF; Cc = Dd;  loc = bid - 512; }
    const int nbx = Cc / 32;
    const int c0 = (loc % nbx) * 32, r0 = (loc / nbx) * 32;
    #pragma unroll
    for (int i = threadIdx.y; i < 32; i += 8)
        t[i][threadIdx.x] = S[(long)(r0 + i) * Cc + c0 + threadIdx.x];
    __syncthreads();
    #pragma unroll
    for (int i = threadIdx.y; i < 32; i += 8)
        D[(long)(c0 + i) * R + r0 + threadIdx.x]
            = __float2bfloat16(t[threadIdx.x][i]);
}

// ---------------------------------------------------------------------------
// bf16 GEMM (mma.sync m16n8k16): C = (Ahi[+Alo]) @ bf16(W)^T.
// 128x128 tile, BK=32, 8 warps, 3-stage cp.async pipeline.
// Iteration: wait(own g(c)) -> syncthreads -> ldsm/MMA -> prefetch c+2.
// ---------------------------------------------------------------------------
__global__ void __launch_bounds__(256, 2)
gemm_bf16(const bf16* __restrict__ Ahi, const bf16* __restrict__ Alo,
          const bf16* __restrict__ Bhi,
          const float* __restrict__ bias, const float* __restrict__ res,
          float* __restrict__ Cf,
          bf16* __restrict__ Chi, bf16* __restrict__ Clo,
          int Ntot, int K, int gather, int do_gelu)
{
    extern __shared__ char smem[];
    const uint32_t sb = smem_u32(smem);
    const int tid  = threadIdx.x;
    const int lane = tid & 31, wid = tid >> 5;
    const int wm = wid & 3, wn = wid >> 2;
    const int row0 = blockIdx.x * 128, col0 = blockIdx.y * 128;
    const int hasLo = (Alo != nullptr);
    const uint32_t Boff = hasLo ? 16384u : 8192u;
    const uint32_t ST   = hasLo ? 24576u : 16384u;

    uint32_t dstOff[2];
    long aIdx[2], bIdx[2];
    #pragma unroll
    for (int s = 0; s < 2; s++) {
        const int c  = tid + s * 256;
        const int r  = c >> 2, ch = c & 3;
        dstOff[s] = (uint32_t)(r * 64 + ((ch ^ (r & 3)) << 4));
        const int gA = row0 + r;
        long ar = gA;
        if (gather) {
            const int seg = (col0 >= 256) ? 1024 : 0;
            ar = (long)(gA >> 10) * 2048 + seg + (gA & 1023);
        }
        aIdx[s] = ar * (long)K + ch * 8;
        bIdx[s] = (long)(col0 + r) * K + ch * 8;
    }

    const int CCH = K >> 5;

    // prologue: prefetch chunks 0 and 1 into stages 0 and 1
    #pragma unroll
    for (int pc = 0; pc < 2; pc++) {
        const uint32_t st = sb + (uint32_t)pc * ST;
        const long k0 = (long)pc * 32;
        #pragma unroll
        for (int s = 0; s < 2; s++) {
            cp16(st + 0    + dstOff[s], Ahi + aIdx[s] + k0);
            if (hasLo) cp16(st + 8192 + dstOff[s], Alo + aIdx[s] + k0);
            cp16(st + Boff + dstOff[s], Bhi + bIdx[s] + k0);
        }
        CP_COMMIT();
    }

    float acc[2][8][4] = {};
    const int rl = lane & 7, tl = lane >> 3;

    int stg = 0;            // stage holding chunk c
    int pstg = 2;           // stage for chunk c+2
    for (int c = 0; c < CCH; c++) {
        if (c + 1 < CCH) { CP_WAIT(1); } else { CP_WAIT(0); }
        __syncthreads();

        const uint32_t base = sb + (uint32_t)stg * ST;
        #pragma unroll
        for (int ks = 0; ks < 2; ks++) {
            uint32_t aH[2][4], aL[2][4], bH[4][4];
            #pragma unroll
            for (int i = 0; i < 2; i++) {
                const int arow = wm * 32 + i * 16 + rl + (tl & 1) * 8;
                const int ach  = ks * 2 + (tl >> 1);
                const uint32_t ad = base + (uint32_t)(arow * 64
                                  + ((ach ^ (arow & 3)) << 4));
                ldsm4(aH[i], ad);
                if (hasLo) ldsm4(aL[i], ad + 8192);
            }
            #pragma unroll
            for (int j = 0; j < 4; j++) {
                const int brow = wn * 64 + j * 16 + rl + (tl >> 1) * 8;
                const int bch  = ks * 2 + (tl & 1);
                const uint32_t bd = base + Boff + (uint32_t)(brow * 64
                                  + ((bch ^ (brow & 3)) << 4));
                ldsm4(bH[j], bd);
            }
            #pragma unroll
            for (int i = 0; i < 2; i++) {
                #pragma unroll
                for (int j = 0; j < 4; j++) {
                    mma_bf16(acc[i][2*j],   aH[i], &bH[j][0]);
                    mma_bf16(acc[i][2*j+1], aH[i], &bH[j][2]);
                    if (hasLo) {
                        mma_bf16(acc[i][2*j],   aL[i], &bH[j][0]);
                        mma_bf16(acc[i][2*j+1], aL[i], &bH[j][2]);
                    }
                }
            }
        }

        if (c + 2 < CCH) {
            const uint32_t st = sb + (uint32_t)pstg * ST;
            const long k0 = (long)(c + 2) * 32;
            #pragma unroll
            for (int s = 0; s < 2; s++) {
                cp16(st + 0    + dstOff[s], Ahi + aIdx[s] + k0);
                if (hasLo) cp16(st + 8192 + dstOff[s], Alo + aIdx[s] + k0);
                cp16(st + Boff + dstOff[s], Bhi + bIdx[s] + k0);
            }
            CP_COMMIT();
        }
        stg  = (stg  == 2) ? 0 : stg  + 1;
        pstg = (pstg == 2) ? 0 : pstg + 1;
    }

    #pragma unroll
    for (int i = 0; i < 2; i++) {
        const int r_top = row0 + wm * 32 + i * 16 + (lane >> 2);
        #pragma unroll
        for (int j = 0; j < 8; j++) {
            const int col = col0 + wn * 64 + j * 8 + (lane & 3) * 2;
            const float b0 = bias[col], b1 = bias[col + 1];
            float v00 = acc[i][j][0] + b0, v01 = acc[i][j][1] + b1;
            float v10 = acc[i][j][2] + b0, v11 = acc[i][j][3] + b1;
            if (do_gelu) {
                v00 = 0.5f * v00 * (1.0f + erff(v00 * 0.70710678118654752f));
                v01 = 0.5f * v01 * (1.0f + erff(v01 * 0.70710678118654752f));
                v10 = 0.5f * v10 * (1.0f + erff(v10 * 0.70710678118654752f));
                v11 = 0.5f * v11 * (1.0f + erff(v11 * 0.70710678118654752f));
            }
            const long o0 = (long)r_top * Ntot + col;
            const long o1 = (long)(r_top + 8) * Ntot + col;
            if (res) {
                v00 += res[o0]; v01 += res[o0 + 1];
                v10 += res[o1]; v11 += res[o1 + 1];
            }
            if (Cf) {
                *(float2*)(Cf + o0) = make_float2(v00, v01);
                *(float2*)(Cf + o1) = make_float2(v10, v11);
            }
            if (Chi) {
                if (Clo) {
                    __nv_bfloat162 h, l;
                    splitf(v00, h.x, l.x); splitf(v01, h.y, l.y);
                    *(__nv_bfloat162*)(Chi + o0) = h;
                    *(__nv_bfloat162*)(Clo + o0) = l;
                    splitf(v10, h.x, l.x); splitf(v11, h.y, l.y);
                    *(__nv_bfloat162*)(Chi + o1) = h;
                    *(__nv_bfloat162*)(Clo + o1) = l;
                } else {
                    *(__nv_bfloat162*)(Chi + o0) = __floats2bfloat162_rn(v00, v01);
                    *(__nv_bfloat162*)(Chi + o1) = __floats2bfloat162_rn(v10, v11);
                }
            }
        }
    }
}

// ---------------------------------------------------------------------------
// Tensor-core flash attention: 128 queries/block, 4 warps x 2 m-tiles of 16
// rows. Each K/V fragment load feeds both m-tiles (LDSM per MMA halved).
// Scores single-MMA bf16. Softmax fp32 (no max shift). PV bf16. Out bf16 hi.
// ---------------------------------------------------------------------------
__global__ void __launch_bounds__(128, 4)
attn_tc(const bf16* __restrict__ QKVh, bf16* __restrict__ OutHi)
{
    __shared__ bf16 sQ[4096];            // 128 rows hi (8 KB)
    __shared__ bf16 sK[2][2048];         //             (8 KB)
    __shared__ bf16 sV[2][2048];         //             (8 KB)

    const int stage = blockIdx.z;
    const int qoff = stage ? 256 : 0;
    const int koff = stage ? 0 : 256;
    const int voff = stage ? 0 : 512;
    const int out_off = stage ? SEG : 0;

    const int bh = blockIdx.y;
    const int b  = bh >> 3;
    const int h  = bh & 7;
    const int q0 = blockIdx.x * 128;

    const int tid  = threadIdx.x;
    const int lane = tid & 31, warp = tid >> 5;
    const int rl = lane & 7, tl = lane >> 3;

    const uint32_t sQb = smem_u32(sQ);
    const uint32_t sKb[2] = { smem_u32(sK[0]), smem_u32(sK[1]) };
    const uint32_t sVb[2] = { smem_u32(sV[0]), smem_u32(sV[1]) };

    // --- load Q (hi): 512 chunks, 4 per thread ---
    #pragma unroll
    for (int s = 0; s < 4; s++) {
        const int c = tid + s * 128;
        const int r = c >> 2, ch = c & 3;
        const uint32_t dst = sQb + (uint32_t)(r * 64 + ((ch ^ (r & 3)) << 4));
        cp16(dst, QKVh + (long)(b * SEG + q0 + r) * NQKV + qoff + h * DK + ch * 8);
    }
    CP_COMMIT();

    // --- prefetch key tile 0 (K + V) ---
    #pragma unroll
    for (int s = 0; s < 4; s++) {
        const int c   = tid + s * 128;
        const int arr = c >> 8;                 // 0 K, 1 V
        const int r   = (c & 255) >> 2, ch = c & 3;
        const uint32_t off = (uint32_t)(r * 64 + ((ch ^ (r & 3)) << 4));
        const uint32_t dst = arr ? (sVb[0] + off) : (sKb[0] + off);
        const int coff = arr ? voff : koff;
        cp16(dst, QKVh + (long)(b * SEG + r) * NQKV + coff + h * DK + ch * 8);
    }
    CP_COMMIT();

    CP_WAIT(1);
    __syncthreads();
    uint32_t qh[2][2][4];                      // [m][ks]
    #pragma unroll
    for (int m = 0; m < 2; m++) {
        #pragma unroll
        for (int ks = 0; ks < 2; ks++) {
            const int arow = warp * 32 + m * 16 + rl + (tl & 1) * 8;
            const int ach  = ks * 2 + (tl >> 1);
            const uint32_t ad = sQb + (uint32_t)(arow * 64
                              + ((ach ^ (arow & 3)) << 4));
            ldsm4(qh[m][ks], ad);
        }
    }

    float o[2][4][4] = {};
    float lsum[2][2] = {};
    const float scale = 0.17677669529663687f;   // 1/sqrt(32)

    for (int t = 0; t < 16; t++) {
        const int buf = t & 1;
        if (t + 1 < 16) {
            const int nb = buf ^ 1;
            #pragma unroll
            for (int s = 0; s < 4; s++) {
                const int c   = tid + s * 128;
                const int arr = c >> 8;
                const int r   = (c & 255) >> 2, ch = c & 3;
                const uint32_t off = (uint32_t)(r * 64 + ((ch ^ (r & 3)) << 4));
                const uint32_t dst = arr ? (sVb[nb] + off) : (sKb[nb] + off);
                const int coff = arr ? voff : koff;
                cp16(dst, QKVh + (long)(b * SEG + (t + 1) * 64 + r) * NQKV
                          + coff + h * DK + ch * 8);
            }
            CP_COMMIT();
            CP_WAIT(1);
        } else {
            CP_WAIT(0);
        }
        __syncthreads();

        #pragma unroll
        for (int nb16 = 0; nb16 < 4; nb16++) {
            // --- scores: 2 K-fragment loads feed 8 MMAs (both m-tiles) ---
            float s2[2][2][4] = {};
            #pragma unroll
            for (int ks = 0; ks < 2; ks++) {
                const int krow = nb16 * 16 + rl + (tl >> 1) * 8;
                const int kch  = ks * 2 + (tl & 1);
                const uint32_t ka = sKb[buf] + (uint32_t)(krow * 64
                                  + ((kch ^ (krow & 3)) << 4));
                uint32_t kh[4];
                ldsm4(kh, ka);
                #pragma unroll
                for (int m = 0; m < 2; m++) {
                    mma_bf16(s2[m][0], qh[m][ks], &kh[0]);
                    mma_bf16(s2[m][1], qh[m][ks], &kh[2]);
                }
            }
            // --- softmax + P pack ---
            uint32_t pf[2][4];
            #pragma unroll
            for (int m = 0; m < 2; m++) {
                float p00 = __expf(s2[m][0][0] * scale), p01 = __expf(s2[m][0][1] * scale);
                float p02 = __expf(s2[m][0][2] * scale), p03 = __expf(s2[m][0][3] * scale);
                float p10 = __expf(s2[m][1][0] * scale), p11 = __expf(s2[m][1][1] * scale);
                float p12 = __expf(s2[m][1][2] * scale), p13 = __expf(s2[m][1][3] * scale);
                lsum[m][0] += p00 + p01 + p10 + p11;
                lsum[m][1] += p02 + p03 + p12 + p13;
                __nv_bfloat162 t2;
                t2 = __floats2bfloat162_rn(p00, p01); pf[m][0] = *(uint32_t*)&t2;
                t2 = __floats2bfloat162_rn(p02, p03); pf[m][1] = *(uint32_t*)&t2;
                t2 = __floats2bfloat162_rn(p10, p11); pf[m][2] = *(uint32_t*)&t2;
                t2 = __floats2bfloat162_rn(p12, p13); pf[m][3] = *(uint32_t*)&t2;
            }
            // --- PV: 2 V-fragment loads feed 8 MMAs ---
            #pragma unroll
            for (int db = 0; db < 2; db++) {
                const int vrow = nb16 * 16 + rl + (tl & 1) * 8;
                const int vch  = db * 2 + (tl >> 1);
                const uint32_t va = sVb[buf] + (uint32_t)(vrow * 64
                                  + ((vch ^ (vrow & 3)) << 4));
                uint32_t vf[4];
                ldsm4t(vf, va);
                #pragma unroll
                for (int m = 0; m < 2; m++) {
                    mma_bf16(o[m][db * 2],     pf[m], &vf[0]);
                    mma_bf16(o[m][db * 2 + 1], pf[m], &vf[2]);
                }
            }
        }
        __syncthreads();
    }

    // --- normalize + store bf16 (hi only) ---
    #pragma unroll
    for (int m = 0; m < 2; m++) {
        float l0 = lsum[m][0], l1 = lsum[m][1];
        l0 += __shfl_xor_sync(0xffffffffu, l0, 1);
        l0 += __shfl_xor_sync(0xffffffffu, l0, 2);
        l1 += __shfl_xor_sync(0xffffffffu, l1, 1);
        l1 += __shfl_xor_sync(0xffffffffu, l1, 2);
        const float inv0 = 1.0f / l0;
        const float inv1 = 1.0f / l1;

        const int rloc = q0 + warp * 32 + m * 16 + (lane >> 2);
        const long row0g = (long)(b * 2 * SEG + out_off + rloc) * Dd + h * DK;
        const long row1g = row0g + 8L * Dd;
        #pragma unroll
        for (int db = 0; db < 4; db++) {
            const int col = db * 8 + (lane & 3) * 2;
            *(__nv_bfloat162*)(OutHi + row0g + col)
                = __floats2bfloat162_rn(o[m][db][0] * inv0, o[m][db][1] * inv0);
            *(__nv_bfloat162*)(OutHi + row1g + col)
                = __floats2bfloat162_rn(o[m][db][2] * inv1, o[m][db][3] * inv1);
        }
    }
}

// ---------------------------------------------------------------------------
// LayerNorm (256-wide rows): warp per row; optional fp32 / bf16-hi outputs.
// ---------------------------------------------------------------------------
__global__ void __launch_bounds__(256)
ln_kernel(const float* __restrict__ X, const float* __restrict__ g,
          const float* __restrict__ beta, float* __restrict__ Y,
          bf16* __restrict__ YHi)
{
    const int row  = blockIdx.x * 8 + (threadIdx.x >> 5);
    const int lane = threadIdx.x & 31;
    const int c0   = lane * 8;
    const float* xr = X + (long)row * Dd + c0;

    float v[8];
    {
        float4 p0 = *(const float4*)xr;
        float4 p1 = *(const float4*)(xr + 4);
        v[0]=p0.x; v[1]=p0.y; v[2]=p0.z; v[3]=p0.w;
        v[4]=p1.x; v[5]=p1.y; v[6]=p1.z; v[7]=p1.w;
    }
    float s = 0.0f;
    #pragma unroll
    for (int i = 0; i < 8; i++) s += v[i];
    #pragma unroll
    for (int o = 16; o; o >>= 1) s += __shfl_xor_sync(0xffffffffu, s, o);
    const float mu = s * (1.0f / 256.0f);

    float ss = 0.0f;
    #pragma unroll
    for (int i = 0; i < 8; i++) { const float d = v[i] - mu; ss += d * d; }
    #pragma unroll
    for (int o = 16; o; o >>= 1) ss += __shfl_xor_sync(0xffffffffu, ss, o);
    const float inv = rsqrtf(ss * (1.0f / 256.0f) + 1e-5f);

    float4 g0 = *(const float4*)(g + c0),    g1 = *(const float4*)(g + c0 + 4);
    float4 e0 = *(const float4*)(beta + c0), e1 = *(const float4*)(beta + c0 + 4);
    float y[8];
    y[0] = (v[0]-mu)*inv*g0.x + e0.x; y[1] = (v[1]-mu)*inv*g0.y + e0.y;
    y[2] = (v[2]-mu)*inv*g0.z + e0.z; y[3] = (v[3]-mu)*inv*g0.w + e0.w;
    y[4] = (v[4]-mu)*inv*g1.x + e1.x; y[5] = (v[5]-mu)*inv*g1.y + e1.y;
    y[6] = (v[6]-mu)*inv*g1.z + e1.z; y[7] = (v[7]-mu)*inv*g1.w + e1.w;

    const long ob = (long)row * Dd + c0;
    if (Y) {
        *(float4*)(Y + ob)     = make_float4(y[0], y[1], y[2], y[3]);
        *(float4*)(Y + ob + 4) = make_float4(y[4], y[5], y[6], y[7]);
    }
    if (YHi) {
        #pragma unroll
        for (int p = 0; p < 4; p++)
            *(__nv_bfloat162*)(YHi + ob + 2*p)
                = __floats2bfloat162_rn(y[2*p], y[2*p+1]);
    }
}

// ---------------------------------------------------------------------------
// Launch
// ---------------------------------------------------------------------------
extern "C" void kernel_launch(void* const* d_in, const int* in_sizes, int n_in,
                              void* d_out, int out_size)
{
    const float* x   = (const float*)d_in[0];
    const float* Wq  = (const float*)d_in[1];
    const float* bq  = (const float*)d_in[2];
    const float* Wk  = (const float*)d_in[3];
    const float* bk  = (const float*)d_in[4];
    const float* Wv  = (const float*)d_in[5];
    const float* bv  = (const float*)d_in[6];
    const float* Wo  = (const float*)d_in[7];
    const float* bo  = (const float*)d_in[8];
    const float* g31 = (const float*)d_in[9];
    const float* b31 = (const float*)d_in[10];
    const float* W1  = (const float*)d_in[11];
    const float* b1  = (const float*)d_in[12];
    const float* W2  = (const float*)d_in[13];
    const float* b2  = (const float*)d_in[14];
    const float* g41 = (const float*)d_in[15];
    const float* b41 = (const float*)d_in[16];
    float* out = (float*)d_out;

    float *pZ, *pH1, *pZ2, *pbqkv;
    bf16 *xHi, *xLo, *QKVHi, *AttHi, *H1Hi, *THi;
    bf16 *WqkvT, *WoT, *W1T, *W2T;

    cudaGetSymbolAddress((void**)&pZ,  g_Z);
    cudaGetSymbolAddress((void**)&pH1, g_H1);
    cudaGetSymbolAddress((void**)&pZ2, g_Z2);
    cudaGetSymbolAddress((void**)&pbqkv, g_bqkv);
    cudaGetSymbolAddress((void**)&xHi,   g_xHi);   cudaGetSymbolAddress((void**)&xLo, g_xLo);
    cudaGetSymbolAddress((void**)&QKVHi, g_QKVHi);
    cudaGetSymbolAddress((void**)&AttHi, g_AttHi);
    cudaGetSymbolAddress((void**)&H1Hi,  g_H1Hi);
    cudaGetSymbolAddress((void**)&THi,   g_THi);
    cudaGetSymbolAddress((void**)&WqkvT, g_WqkvT);
    cudaGetSymbolAddress((void**)&WoT, g_WoT);
    cudaGetSymbolAddress((void**)&W1T, g_W1T);
    cudaGetSymbolAddress((void**)&W2T, g_W2T);

    static bool attr_set = false;
    if (!attr_set) {
        cudaFuncSetAttribute(gemm_bf16,
            cudaFuncAttributeMaxDynamicSharedMemorySize, 73728);
        attr_set = true;
    }

    // weight prep + x split
    transpose_all<<<768, dim3(32, 8)>>>(Wq, Wk, Wv, Wo, W1, W2, bq, bk, bv,
                                        WqkvT, WoT, W1T, W2T, pbqkv);
    split_kernel<<<(NROWS_FULL * Dd) / 1024, 256>>>(x, xHi, xLo);

    // fused QKV projection (N=768, per-column segment gather; 2-MMA; hi out)
    gemm_bf16<<<dim3(NROWS_HALF / 128, NQKV / 128), 256, 73728>>>(
        xHi, xLo, WqkvT, pbqkv, nullptr, nullptr, QKVHi, nullptr,
        NQKV, Dd, 1, 0);

    // two-stage cross-segment attention (128q x 64k tiles, fragment reuse)
    attn_tc<<<dim3(SEG / 128, Bb * Hh, 2), 128>>>(QKVHi, AttHi);

    // output projection + residual(x), LN1
    gemm_bf16<<<dim3(NROWS_FULL / 128, Dd / 128), 256, 49152>>>(
        AttHi, nullptr, WoT, bo, x, pZ, nullptr, nullptr, Dd, Dd, 0, 0);
    ln_kernel<<<NROWS_FULL / 8, 256>>>(pZ, g31, b31, pH1, H1Hi);

    // MLP (single-MMA bf16)
    gemm_bf16<<<dim3(NROWS_FULL / 128, DFF / 128), 256, 49152>>>(
        H1Hi, nullptr, W1T, b1, nullptr, nullptr, THi, nullptr, DFF, Dd, 0, 1);
    gemm_bf16<<<dim3(NROWS_FULL / 128, Dd / 128), 256, 49152>>>(
        THi, nullptr, W2T, b2, pH1, pZ2, nullptr, nullptr, Dd, DFF, 0, 0);
    ln_kernel<<<NROWS_FULL / 8, 256>>>(pZ2, g41, b41, out, nullptr);
}

// round 13
// speedup vs baseline: 2.1482x; 1.2472x over previous
#include <cuda_runtime.h>
#include <cuda_bf16.h>
#include <math.h>
#include <stdint.h>

// ---------------------------------------------------------------------------
// TwoStageAttentionLayerCrossSegments  (B=16, TS_D=2, SEG=1024, D=256, H=8,
// DK=32, D_FF=1024)
// All GEMMs single-MMA bf16 (mma.sync m16n8k16), BK=64, 3-stage cp.async.
// Attention: 128 q/block, 4 warps x 2 m-tiles (K/V fragment reuse).
// ---------------------------------------------------------------------------

typedef __nv_bfloat16 bf16;

#define Bb   16
#define SEG  1024
#define Dd   256
#define Hh   8
#define DK   32
#define DFF  1024
#define NROWS_HALF (Bb*SEG)        // 16384
#define NROWS_FULL (Bb*2*SEG)      // 32768
#define NQKV 768

// fp32 scratch
__device__ float g_Z [NROWS_FULL * Dd];
__device__ float g_H1[NROWS_FULL * Dd];
__device__ float g_Z2[NROWS_FULL * Dd];

// bf16 activations
__device__ bf16 g_xHi  [NROWS_FULL * Dd];
__device__ bf16 g_QKVHi[NROWS_HALF * NQKV];
__device__ bf16 g_AttHi[NROWS_FULL * Dd];
__device__ bf16 g_H1Hi [NROWS_FULL * Dd];
__device__ bf16 g_THi  [NROWS_FULL * DFF];

// transposed weights ([N,K] K-major), bf16
__device__ bf16 g_WqkvT[NQKV * Dd];
__device__ bf16 g_WoT[Dd * Dd];
__device__ bf16 g_W1T[DFF * Dd];
__device__ bf16 g_W2T[Dd * DFF];
__device__ float g_bqkv[NQKV];

// ---------------------------------------------------------------------------
// helpers
// ---------------------------------------------------------------------------
__device__ __forceinline__ uint32_t smem_u32(const void* p) {
    uint32_t a;
    asm("{ .reg .u64 t; cvta.to.shared.u64 t, %1; cvt.u32.u64 %0, t; }"
        : "=r"(a) : "l"(p));
    return a;
}

__device__ __forceinline__ void cp16(uint32_t s, const void* g) {
    asm volatile("cp.async.cg.shared.global [%0], [%1], 16;" :: "r"(s), "l"(g));
}
#define CP_COMMIT() asm volatile("cp.async.commit_group;" ::: "memory")
#define CP_WAIT(n)  asm volatile("cp.async.wait_group %0;" :: "n"(n) : "memory")

__device__ __forceinline__ void ldsm4(uint32_t* r, uint32_t addr) {
    asm volatile("ldmatrix.sync.aligned.m8n8.x4.shared.b16 {%0,%1,%2,%3}, [%4];"
        : "=r"(r[0]), "=r"(r[1]), "=r"(r[2]), "=r"(r[3]) : "r"(addr));
}
__device__ __forceinline__ void ldsm4t(uint32_t* r, uint32_t addr) {
    asm volatile("ldmatrix.sync.aligned.m8n8.x4.trans.shared.b16 {%0,%1,%2,%3}, [%4];"
        : "=r"(r[0]), "=r"(r[1]), "=r"(r[2]), "=r"(r[3]) : "r"(addr));
}

__device__ __forceinline__ void mma_bf16(float* d, const uint32_t* a, const uint32_t* b) {
    asm volatile(
        "mma.sync.aligned.m16n8k16.row.col.f32.bf16.bf16.f32 "
        "{%0,%1,%2,%3}, {%4,%5,%6,%7}, {%8,%9}, {%0,%1,%2,%3};"
        : "+f"(d[0]), "+f"(d[1]), "+f"(d[2]), "+f"(d[3])
        : "r"(a[0]), "r"(a[1]), "r"(a[2]), "r"(a[3]), "r"(b[0]), "r"(b[1]));
}

// ---------------------------------------------------------------------------
// fp32 -> bf16 convert (hi only)
// ---------------------------------------------------------------------------
__global__ void __launch_bounds__(256)
cvt_kernel(const float* __restrict__ X, bf16* __restrict__ Hi)
{
    const long i = ((long)blockIdx.x * 256 + threadIdx.x) * 4;
    float4 v = *(const float4*)(X + i);
    *(__nv_bfloat162*)(Hi + i)     = __floats2bfloat162_rn(v.x, v.y);
    *(__nv_bfloat162*)(Hi + i + 2) = __floats2bfloat162_rn(v.z, v.w);
}

// ---------------------------------------------------------------------------
// All weight transposes (bf16) + QKV bias concat, ONE launch.
// ---------------------------------------------------------------------------
__global__ void __launch_bounds__(256)
transpose_all(const float* __restrict__ Wq, const float* __restrict__ Wk,
              const float* __restrict__ Wv, const float* __restrict__ Wo,
              const float* __restrict__ W1, const float* __restrict__ W2,
              const float* __restrict__ bq, const float* __restrict__ bk,
              const float* __restrict__ bv,
              bf16* __restrict__ dWqkv, bf16* __restrict__ dWo,
              bf16* __restrict__ dW1, bf16* __restrict__ dW2,
              float* __restrict__ dbqkv)
{
    __shared__ float t[32][33];
    const int bid = blockIdx.x;
    const int tix = threadIdx.y * 32 + threadIdx.x;
    if (bid == 0 && tix < 256) {
        dbqkv[tix]       = bq[tix];
        dbqkv[tix + 256] = bk[tix];
        dbqkv[tix + 512] = bv[tix];
    }
    const float* S; bf16* D; int R, Cc, loc;
    if      (bid < 64)  { S = Wq; D = dWqkv;             R = Dd;  Cc = Dd;  loc = bid; }
    else if (bid < 128) { S = Wk; D = dWqkv + 256 * Dd;  R = Dd;  Cc = Dd;  loc = bid - 64; }
    else if (bid < 192) { S = Wv; D = dWqkv + 512 * Dd;  R = Dd;  Cc = Dd;  loc = bid - 128; }
    else if (bid < 256) { S = Wo; D = dWo;               R = Dd;  Cc = Dd;  loc = bid - 192; }
    else if (bid < 512) { S = W1; D = dW1;               R = Dd;  Cc = DFF; loc = bid - 256; }
    else                { S = W2; D = dW2;               R = DFF; Cc = Dd;  loc = bid - 512; }
    const int nbx = Cc / 32;
    const int c0 = (loc % nbx) * 32, r0 = (loc / nbx) * 32;
    #pragma unroll
    for (int i = threadIdx.y; i < 32; i += 8)
        t[i][threadIdx.x] = S[(long)(r0 + i) * Cc + c0 + threadIdx.x];
    __syncthreads();
    #pragma unroll
    for (int i = threadIdx.y; i < 32; i += 8)
        D[(long)(c0 + i) * R + r0 + threadIdx.x]
            = __float2bfloat16(t[threadIdx.x][i]);
}

// ---------------------------------------------------------------------------
// bf16 GEMM (mma.sync m16n8k16): C = bf16(A) @ bf16(W)^T.
// 128x128 tile, BK=64, 8 warps, 3-stage cp.async pipeline (1 sync/chunk).
// Stage: A 16KB @0, B 16KB @16384; 3 stages x 32KB = 96KB.
// Row = 128B = 8 chunks; swizzle ch ^= (row & 7).
// ---------------------------------------------------------------------------
__global__ void __launch_bounds__(256, 2)
gemm_bf16(const bf16* __restrict__ A, const bf16* __restrict__ B,
          const float* __restrict__ bias, const float* __restrict__ res,
          float* __restrict__ Cf, bf16* __restrict__ Chi,
          int Ntot, int K, int gather, int do_gelu)
{
    extern __shared__ char smem[];
    const uint32_t sb = smem_u32(smem);
    const int tid  = threadIdx.x;
    const int lane = tid & 31, wid = tid >> 5;
    const int wm = wid & 3, wn = wid >> 2;
    const int row0 = blockIdx.x * 128, col0 = blockIdx.y * 128;
    const uint32_t ST = 32768u;

    // loader: per operand, 1024 chunks / 256 threads = 4 slots
    uint32_t dstOff[4];
    long aIdx[4], bIdx[4];
    #pragma unroll
    for (int s = 0; s < 4; s++) {
        const int c  = tid + s * 256;
        const int r  = c >> 3, ch = c & 7;
        dstOff[s] = (uint32_t)(r * 128 + ((ch ^ (r & 7)) << 4));
        const int gA = row0 + r;
        long ar = gA;
        if (gather) {
            const int seg = (col0 >= 256) ? 1024 : 0;
            ar = (long)(gA >> 10) * 2048 + seg + (gA & 1023);
        }
        aIdx[s] = ar * (long)K + ch * 8;
        bIdx[s] = (long)(col0 + r) * K + ch * 8;
    }

    const int CCH = K >> 6;

    // prologue: prefetch chunks 0,1 into stages 0,1
    #pragma unroll
    for (int pc = 0; pc < 2; pc++) {
        const uint32_t st = sb + (uint32_t)pc * ST;
        const long k0 = (long)pc * 64;
        #pragma unroll
        for (int s = 0; s < 4; s++) {
            cp16(st + 0      + dstOff[s], A + aIdx[s] + k0);
            cp16(st + 16384u + dstOff[s], B + bIdx[s] + k0);
        }
        CP_COMMIT();
    }

    float acc[2][8][4] = {};
    const int rl = lane & 7, tl = lane >> 3;

    int stg = 0, pstg = 2;
    for (int c = 0; c < CCH; c++) {
        if (c + 1 < CCH) { CP_WAIT(1); } else { CP_WAIT(0); }
        __syncthreads();

        const uint32_t base = sb + (uint32_t)stg * ST;
        #pragma unroll
        for (int ks = 0; ks < 4; ks++) {
            uint32_t aH[2][4], bH[4][4];
            #pragma unroll
            for (int i = 0; i < 2; i++) {
                const int arow = wm * 32 + i * 16 + rl + (tl & 1) * 8;
                const int ach  = ks * 2 + (tl >> 1);
                const uint32_t ad = base + (uint32_t)(arow * 128
                                  + ((ach ^ (arow & 7)) << 4));
                ldsm4(aH[i], ad);
            }
            #pragma unroll
            for (int j = 0; j < 4; j++) {
                const int brow = wn * 64 + j * 16 + rl + (tl >> 1) * 8;
                const int bch  = ks * 2 + (tl & 1);
                const uint32_t bd = base + 16384u + (uint32_t)(brow * 128
                                  + ((bch ^ (brow & 7)) << 4));
                ldsm4(bH[j], bd);
            }
            #pragma unroll
            for (int i = 0; i < 2; i++) {
                #pragma unroll
                for (int j = 0; j < 4; j++) {
                    mma_bf16(acc[i][2*j],   aH[i], &bH[j][0]);
                    mma_bf16(acc[i][2*j+1], aH[i], &bH[j][2]);
                }
            }
        }

        if (c + 2 < CCH) {
            const uint32_t st = sb + (uint32_t)pstg * ST;
            const long k0 = (long)(c + 2) * 64;
            #pragma unroll
            for (int s = 0; s < 4; s++) {
                cp16(st + 0      + dstOff[s], A + aIdx[s] + k0);
                cp16(st + 16384u + dstOff[s], B + bIdx[s] + k0);
            }
            CP_COMMIT();
        }
        stg  = (stg  == 2) ? 0 : stg  + 1;
        pstg = (pstg == 2) ? 0 : pstg + 1;
    }

    #pragma unroll
    for (int i = 0; i < 2; i++) {
        const int r_top = row0 + wm * 32 + i * 16 + (lane >> 2);
        #pragma unroll
        for (int j = 0; j < 8; j++) {
            const int col = col0 + wn * 64 + j * 8 + (lane & 3) * 2;
            const float b0 = bias[col], b1 = bias[col + 1];
            float v00 = acc[i][j][0] + b0, v01 = acc[i][j][1] + b1;
            float v10 = acc[i][j][2] + b0, v11 = acc[i][j][3] + b1;
            if (do_gelu) {
                v00 = 0.5f * v00 * (1.0f + erff(v00 * 0.70710678118654752f));
                v01 = 0.5f * v01 * (1.0f + erff(v01 * 0.70710678118654752f));
                v10 = 0.5f * v10 * (1.0f + erff(v10 * 0.70710678118654752f));
                v11 = 0.5f * v11 * (1.0f + erff(v11 * 0.70710678118654752f));
            }
            const long o0 = (long)r_top * Ntot + col;
            const long o1 = (long)(r_top + 8) * Ntot + col;
            if (res) {
                v00 += res[o0]; v01 += res[o0 + 1];
                v10 += res[o1]; v11 += res[o1 + 1];
            }
            if (Cf) {
                *(float2*)(Cf + o0) = make_float2(v00, v01);
                *(float2*)(Cf + o1) = make_float2(v10, v11);
            }
            if (Chi) {
                *(__nv_bfloat162*)(Chi + o0) = __floats2bfloat162_rn(v00, v01);
                *(__nv_bfloat162*)(Chi + o1) = __floats2bfloat162_rn(v10, v11);
            }
        }
    }
}

// ---------------------------------------------------------------------------
// Tensor-core flash attention: 128 queries/block, 4 warps x 2 m-tiles of 16
// rows. Each K/V fragment load feeds both m-tiles.
// Scores single-MMA bf16. Softmax fp32 (no max shift). PV bf16. Out bf16 hi.
// ---------------------------------------------------------------------------
__global__ void __launch_bounds__(128, 4)
attn_tc(const bf16* __restrict__ QKVh, bf16* __restrict__ OutHi)
{
    __shared__ bf16 sQ[4096];            // 128 rows hi (8 KB)
    __shared__ bf16 sK[2][2048];         //             (8 KB)
    __shared__ bf16 sV[2][2048];         //             (8 KB)

    const int stage = blockIdx.z;
    const int qoff = stage ? 256 : 0;
    const int koff = stage ? 0 : 256;
    const int voff = stage ? 0 : 512;
    const int out_off = stage ? SEG : 0;

    const int bh = blockIdx.y;
    const int b  = bh >> 3;
    const int h  = bh & 7;
    const int q0 = blockIdx.x * 128;

    const int tid  = threadIdx.x;
    const int lane = tid & 31, warp = tid >> 5;
    const int rl = lane & 7, tl = lane >> 3;

    const uint32_t sQb = smem_u32(sQ);
    const uint32_t sKb[2] = { smem_u32(sK[0]), smem_u32(sK[1]) };
    const uint32_t sVb[2] = { smem_u32(sV[0]), smem_u32(sV[1]) };

    // --- load Q (hi): 512 chunks, 4 per thread ---
    #pragma unroll
    for (int s = 0; s < 4; s++) {
        const int c = tid + s * 128;
        const int r = c >> 2, ch = c & 3;
        const uint32_t dst = sQb + (uint32_t)(r * 64 + ((ch ^ (r & 3)) << 4));
        cp16(dst, QKVh + (long)(b * SEG + q0 + r) * NQKV + qoff + h * DK + ch * 8);
    }
    CP_COMMIT();

    // --- prefetch key tile 0 (K + V) ---
    #pragma unroll
    for (int s = 0; s < 4; s++) {
        const int c   = tid + s * 128;
        const int arr = c >> 8;                 // 0 K, 1 V
        const int r   = (c & 255) >> 2, ch = c & 3;
        const uint32_t off = (uint32_t)(r * 64 + ((ch ^ (r & 3)) << 4));
        const uint32_t dst = arr ? (sVb[0] + off) : (sKb[0] + off);
        const int coff = arr ? voff : koff;
        cp16(dst, QKVh + (long)(b * SEG + r) * NQKV + coff + h * DK + ch * 8);
    }
    CP_COMMIT();

    CP_WAIT(1);
    __syncthreads();
    uint32_t qh[2][2][4];                      // [m][ks]
    #pragma unroll
    for (int m = 0; m < 2; m++) {
        #pragma unroll
        for (int ks = 0; ks < 2; ks++) {
            const int arow = warp * 32 + m * 16 + rl + (tl & 1) * 8;
            const int ach  = ks * 2 + (tl >> 1);
            const uint32_t ad = sQb + (uint32_t)(arow * 64
                              + ((ach ^ (arow & 3)) << 4));
            ldsm4(qh[m][ks], ad);
        }
    }

    float o[2][4][4] = {};
    float lsum[2][2] = {};
    const float scale = 0.17677669529663687f;   // 1/sqrt(32)

    for (int t = 0; t < 16; t++) {
        const int buf = t & 1;
        if (t + 1 < 16) {
            const int nb = buf ^ 1;
            #pragma unroll
            for (int s = 0; s < 4; s++) {
                const int c   = tid + s * 128;
                const int arr = c >> 8;
                const int r   = (c & 255) >> 2, ch = c & 3;
                const uint32_t off = (uint32_t)(r * 64 + ((ch ^ (r & 3)) << 4));
                const uint32_t dst = arr ? (sVb[nb] + off) : (sKb[nb] + off);
                const int coff = arr ? voff : koff;
                cp16(dst, QKVh + (long)(b * SEG + (t + 1) * 64 + r) * NQKV
                          + coff + h * DK + ch * 8);
            }
            CP_COMMIT();
            CP_WAIT(1);
        } else {
            CP_WAIT(0);
        }
        __syncthreads();

        #pragma unroll
        for (int nb16 = 0; nb16 < 4; nb16++) {
            float s2[2][2][4] = {};
            #pragma unroll
            for (int ks = 0; ks < 2; ks++) {
                const int krow = nb16 * 16 + rl + (tl >> 1) * 8;
                const int kch  = ks * 2 + (tl & 1);
                const uint32_t ka = sKb[buf] + (uint32_t)(krow * 64
                                  + ((kch ^ (krow & 3)) << 4));
                uint32_t kh[4];
                ldsm4(kh, ka);
                #pragma unroll
                for (int m = 0; m < 2; m++) {
                    mma_bf16(s2[m][0], qh[m][ks], &kh[0]);
                    mma_bf16(s2[m][1], qh[m][ks], &kh[2]);
                }
            }
            uint32_t pf[2][4];
            #pragma unroll
            for (int m = 0; m < 2; m++) {
                float p00 = __expf(s2[m][0][0] * scale), p01 = __expf(s2[m][0][1] * scale);
                float p02 = __expf(s2[m][0][2] * scale), p03 = __expf(s2[m][0][3] * scale);
                float p10 = __expf(s2[m][1][0] * scale), p11 = __expf(s2[m][1][1] * scale);
                float p12 = __expf(s2[m][1][2] * scale), p13 = __expf(s2[m][1][3] * scale);
                lsum[m][0] += p00 + p01 + p10 + p11;
                lsum[m][1] += p02 + p03 + p12 + p13;
                __nv_bfloat162 t2;
                t2 = __floats2bfloat162_rn(p00, p01); pf[m][0] = *(uint32_t*)&t2;
                t2 = __floats2bfloat162_rn(p02, p03); pf[m][1] = *(uint32_t*)&t2;
                t2 = __floats2bfloat162_rn(p10, p11); pf[m][2] = *(uint32_t*)&t2;
                t2 = __floats2bfloat162_rn(p12, p13); pf[m][3] = *(uint32_t*)&t2;
            }
            #pragma unroll
            for (int db = 0; db < 2; db++) {
                const int vrow = nb16 * 16 + rl + (tl & 1) * 8;
                const int vch  = db * 2 + (tl >> 1);
                const uint32_t va = sVb[buf] + (uint32_t)(vrow * 64
                                  + ((vch ^ (vrow & 3)) << 4));
                uint32_t vf[4];
                ldsm4t(vf, va);
                #pragma unroll
                for (int m = 0; m < 2; m++) {
                    mma_bf16(o[m][db * 2],     pf[m], &vf[0]);
                    mma_bf16(o[m][db * 2 + 1], pf[m], &vf[2]);
                }
            }
        }
        __syncthreads();
    }

    #pragma unroll
    for (int m = 0; m < 2; m++) {
        float l0 = lsum[m][0], l1 = lsum[m][1];
        l0 += __shfl_xor_sync(0xffffffffu, l0, 1);
        l0 += __shfl_xor_sync(0xffffffffu, l0, 2);
        l1 += __shfl_xor_sync(0xffffffffu, l1, 1);
        l1 += __shfl_xor_sync(0xffffffffu, l1, 2);
        const float inv0 = 1.0f / l0;
        const float inv1 = 1.0f / l1;

        const int rloc = q0 + warp * 32 + m * 16 + (lane >> 2);
        const long row0g = (long)(b * 2 * SEG + out_off + rloc) * Dd + h * DK;
        const long row1g = row0g + 8L * Dd;
        #pragma unroll
        for (int db = 0; db < 4; db++) {
            const int col = db * 8 + (lane & 3) * 2;
            *(__nv_bfloat162*)(OutHi + row0g + col)
                = __floats2bfloat162_rn(o[m][db][0] * inv0, o[m][db][1] * inv0);
            *(__nv_bfloat162*)(OutHi + row1g + col)
                = __floats2bfloat162_rn(o[m][db][2] * inv1, o[m][db][3] * inv1);
        }
    }
}

// ---------------------------------------------------------------------------
// LayerNorm (256-wide rows): warp per row; optional fp32 / bf16-hi outputs.
// ---------------------------------------------------------------------------
__global__ void __launch_bounds__(256)
ln_kernel(const float* __restrict__ X, const float* __restrict__ g,
          const float* __restrict__ beta, float* __restrict__ Y,
          bf16* __restrict__ YHi)
{
    const int row  = blockIdx.x * 8 + (threadIdx.x >> 5);
    const int lane = threadIdx.x & 31;
    const int c0   = lane * 8;
    const float* xr = X + (long)row * Dd + c0;

    float v[8];
    {
        float4 p0 = *(const float4*)xr;
        float4 p1 = *(const float4*)(xr + 4);
        v[0]=p0.x; v[1]=p0.y; v[2]=p0.z; v[3]=p0.w;
        v[4]=p1.x; v[5]=p1.y; v[6]=p1.z; v[7]=p1.w;
    }
    float s = 0.0f;
    #pragma unroll
    for (int i = 0; i < 8; i++) s += v[i];
    #pragma unroll
    for (int o = 16; o; o >>= 1) s += __shfl_xor_sync(0xffffffffu, s, o);
    const float mu = s * (1.0f / 256.0f);

    float ss = 0.0f;
    #pragma unroll
    for (int i = 0; i < 8; i++) { const float d = v[i] - mu; ss += d * d; }
    #pragma unroll
    for (int o = 16; o; o >>= 1) ss += __shfl_xor_sync(0xffffffffu, ss, o);
    const float inv = rsqrtf(ss * (1.0f / 256.0f) + 1e-5f);

    float4 g0 = *(const float4*)(g + c0),    g1 = *(const float4*)(g + c0 + 4);
    float4 e0 = *(const float4*)(beta + c0), e1 = *(const float4*)(beta + c0 + 4);
    float y[8];
    y[0] = (v[0]-mu)*inv*g0.x + e0.x; y[1] = (v[1]-mu)*inv*g0.y + e0.y;
    y[2] = (v[2]-mu)*inv*g0.z + e0.z; y[3] = (v[3]-mu)*inv*g0.w + e0.w;
    y[4] = (v[4]-mu)*inv*g1.x + e1.x; y[5] = (v[5]-mu)*inv*g1.y + e1.y;
    y[6] = (v[6]-mu)*inv*g1.z + e1.z; y[7] = (v[7]-mu)*inv*g1.w + e1.w;

    const long ob = (long)row * Dd + c0;
    if (Y) {
        *(float4*)(Y + ob)     = make_float4(y[0], y[1], y[2], y[3]);
        *(float4*)(Y + ob + 4) = make_float4(y[4], y[5], y[6], y[7]);
    }
    if (YHi) {
        #pragma unroll
        for (int p = 0; p < 4; p++)
            *(__nv_bfloat162*)(YHi + ob + 2*p)
                = __floats2bfloat162_rn(y[2*p], y[2*p+1]);
    }
}

// ---------------------------------------------------------------------------
// Launch
// ---------------------------------------------------------------------------
extern "C" void kernel_launch(void* const* d_in, const int* in_sizes, int n_in,
                              void* d_out, int out_size)
{
    const float* x   = (const float*)d_in[0];
    const float* Wq  = (const float*)d_in[1];
    const float* bq  = (const float*)d_in[2];
    const float* Wk  = (const float*)d_in[3];
    const float* bk  = (const float*)d_in[4];
    const float* Wv  = (const float*)d_in[5];
    const float* bv  = (const float*)d_in[6];
    const float* Wo  = (const float*)d_in[7];
    const float* bo  = (const float*)d_in[8];
    const float* g31 = (const float*)d_in[9];
    const float* b31 = (const float*)d_in[10];
    const float* W1  = (const float*)d_in[11];
    const float* b1  = (const float*)d_in[12];
    const float* W2  = (const float*)d_in[13];
    const float* b2  = (const float*)d_in[14];
    const float* g41 = (const float*)d_in[15];
    const float* b41 = (const float*)d_in[16];
    float* out = (float*)d_out;

    float *pZ, *pH1, *pZ2, *pbqkv;
    bf16 *xHi, *QKVHi, *AttHi, *H1Hi, *THi;
    bf16 *WqkvT, *WoT, *W1T, *W2T;

    cudaGetSymbolAddress((void**)&pZ,  g_Z);
    cudaGetSymbolAddress((void**)&pH1, g_H1);
    cudaGetSymbolAddress((void**)&pZ2, g_Z2);
    cudaGetSymbolAddress((void**)&pbqkv, g_bqkv);
    cudaGetSymbolAddress((void**)&xHi,   g_xHi);
    cudaGetSymbolAddress((void**)&QKVHi, g_QKVHi);
    cudaGetSymbolAddress((void**)&AttHi, g_AttHi);
    cudaGetSymbolAddress((void**)&H1Hi,  g_H1Hi);
    cudaGetSymbolAddress((void**)&THi,   g_THi);
    cudaGetSymbolAddress((void**)&WqkvT, g_WqkvT);
    cudaGetSymbolAddress((void**)&WoT, g_WoT);
    cudaGetSymbolAddress((void**)&W1T, g_W1T);
    cudaGetSymbolAddress((void**)&W2T, g_W2T);

    static bool attr_set = false;
    if (!attr_set) {
        cudaFuncSetAttribute(gemm_bf16,
            cudaFuncAttributeMaxDynamicSharedMemorySize, 98304);
        attr_set = true;
    }
    const size_t SMEM = 98304;   // 3 stages x 32 KB

    // weight prep + x convert
    transpose_all<<<768, dim3(32, 8)>>>(Wq, Wk, Wv, Wo, W1, W2, bq, bk, bv,
                                        WqkvT, WoT, W1T, W2T, pbqkv);
    cvt_kernel<<<(NROWS_FULL * Dd) / 1024, 256>>>(x, xHi);

    // fused QKV projection (N=768, per-column segment gather)
    gemm_bf16<<<dim3(NROWS_HALF / 128, NQKV / 128), 256, SMEM>>>(
        xHi, WqkvT, pbqkv, nullptr, nullptr, QKVHi, NQKV, Dd, 1, 0);

    // two-stage cross-segment attention (128q x 64k tiles, fragment reuse)
    attn_tc<<<dim3(SEG / 128, Bb * Hh, 2), 128>>>(QKVHi, AttHi);

    // output projection + residual(x), LN1
    gemm_bf16<<<dim3(NROWS_FULL / 128, Dd / 128), 256, SMEM>>>(
        AttHi, WoT, bo, x, pZ, nullptr, Dd, Dd, 0, 0);
    ln_kernel<<<NROWS_FULL / 8, 256>>>(pZ, g31, b31, pH1, H1Hi);

    // MLP
    gemm_bf16<<<dim3(NROWS_FULL / 128, DFF / 128), 256, SMEM>>>(
        H1Hi, W1T, b1, nullptr, nullptr, THi, DFF, Dd, 0, 1);
    gemm_bf16<<<dim3(NROWS_FULL / 128, Dd / 128), 256, SMEM>>>(
        THi, W2T, b2, pH1, pZ2, nullptr, Dd, DFF, 0, 0);
    ln_kernel<<<NROWS_FULL / 8, 256>>>(pZ2, g41, b41, out, nullptr);
}

// round 14
// speedup vs baseline: 2.2600x; 1.0521x over previous
#include <cuda_runtime.h>
#include <cuda_bf16.h>
#include <math.h>
#include <stdint.h>

// ---------------------------------------------------------------------------
// TwoStageAttentionLayerCrossSegments  (B=16, TS_D=2, SEG=1024, D=256, H=8,
// DK=32, D_FF=1024)
// All GEMMs single-MMA bf16, BK=64, 3-stage cp.async.
// Wo and W2 GEMMs fuse bias+residual+LayerNorm in the epilogue.
// Attention: 128 q/block, 4 warps x 2 m-tiles (K/V fragment reuse).
// ---------------------------------------------------------------------------

typedef __nv_bfloat16 bf16;

#define Bb   16
#define SEG  1024
#define Dd   256
#define Hh   8
#define DK   32
#define DFF  1024
#define NROWS_HALF (Bb*SEG)        // 16384
#define NROWS_FULL (Bb*2*SEG)      // 32768
#define NQKV 768

// fp32 scratch
__device__ float g_H1[NROWS_FULL * Dd];

// bf16 activations
__device__ bf16 g_xHi  [NROWS_FULL * Dd];
__device__ bf16 g_QKVHi[NROWS_HALF * NQKV];
__device__ bf16 g_AttHi[NROWS_FULL * Dd];
__device__ bf16 g_H1Hi [NROWS_FULL * Dd];
__device__ bf16 g_THi  [NROWS_FULL * DFF];

// transposed weights ([N,K] K-major), bf16
__device__ bf16 g_WqkvT[NQKV * Dd];
__device__ bf16 g_WoT[Dd * Dd];
__device__ bf16 g_W1T[DFF * Dd];
__device__ bf16 g_W2T[Dd * DFF];
__device__ float g_bqkv[NQKV];

// ---------------------------------------------------------------------------
// helpers
// ---------------------------------------------------------------------------
__device__ __forceinline__ uint32_t smem_u32(const void* p) {
    uint32_t a;
    asm("{ .reg .u64 t; cvta.to.shared.u64 t, %1; cvt.u32.u64 %0, t; }"
        : "=r"(a) : "l"(p));
    return a;
}

__device__ __forceinline__ void cp16(uint32_t s, const void* g) {
    asm volatile("cp.async.cg.shared.global [%0], [%1], 16;" :: "r"(s), "l"(g));
}
#define CP_COMMIT() asm volatile("cp.async.commit_group;" ::: "memory")
#define CP_WAIT(n)  asm volatile("cp.async.wait_group %0;" :: "n"(n) : "memory")

__device__ __forceinline__ void ldsm4(uint32_t* r, uint32_t addr) {
    asm volatile("ldmatrix.sync.aligned.m8n8.x4.shared.b16 {%0,%1,%2,%3}, [%4];"
        : "=r"(r[0]), "=r"(r[1]), "=r"(r[2]), "=r"(r[3]) : "r"(addr));
}
__device__ __forceinline__ void ldsm4t(uint32_t* r, uint32_t addr) {
    asm volatile("ldmatrix.sync.aligned.m8n8.x4.trans.shared.b16 {%0,%1,%2,%3}, [%4];"
        : "=r"(r[0]), "=r"(r[1]), "=r"(r[2]), "=r"(r[3]) : "r"(addr));
}

__device__ __forceinline__ void mma_bf16(float* d, const uint32_t* a, const uint32_t* b) {
    asm volatile(
        "mma.sync.aligned.m16n8k16.row.col.f32.bf16.bf16.f32 "
        "{%0,%1,%2,%3}, {%4,%5,%6,%7}, {%8,%9}, {%0,%1,%2,%3};"
        : "+f"(d[0]), "+f"(d[1]), "+f"(d[2]), "+f"(d[3])
        : "r"(a[0]), "r"(a[1]), "r"(a[2]), "r"(a[3]), "r"(b[0]), "r"(b[1]));
}

// ---------------------------------------------------------------------------
// fp32 -> bf16 convert
// ---------------------------------------------------------------------------
__global__ void __launch_bounds__(256)
cvt_kernel(const float* __restrict__ X, bf16* __restrict__ Hi)
{
    const long i = ((long)blockIdx.x * 256 + threadIdx.x) * 4;
    float4 v = *(const float4*)(X + i);
    *(__nv_bfloat162*)(Hi + i)     = __floats2bfloat162_rn(v.x, v.y);
    *(__nv_bfloat162*)(Hi + i + 2) = __floats2bfloat162_rn(v.z, v.w);
}

// ---------------------------------------------------------------------------
// All weight transposes (bf16) + QKV bias concat, ONE launch.
// ---------------------------------------------------------------------------
__global__ void __launch_bounds__(256)
transpose_all(const float* __restrict__ Wq, const float* __restrict__ Wk,
              const float* __restrict__ Wv, const float* __restrict__ Wo,
              const float* __restrict__ W1, const float* __restrict__ W2,
              const float* __restrict__ bq, const float* __restrict__ bk,
              const float* __restrict__ bv,
              bf16* __restrict__ dWqkv, bf16* __restrict__ dWo,
              bf16* __restrict__ dW1, bf16* __restrict__ dW2,
              float* __restrict__ dbqkv)
{
    __shared__ float t[32][33];
    const int bid = blockIdx.x;
    const int tix = threadIdx.y * 32 + threadIdx.x;
    if (bid == 0 && tix < 256) {
        dbqkv[tix]       = bq[tix];
        dbqkv[tix + 256] = bk[tix];
        dbqkv[tix + 512] = bv[tix];
    }
    const float* S; bf16* D; int R, Cc, loc;
    if      (bid < 64)  { S = Wq; D = dWqkv;             R = Dd;  Cc = Dd;  loc = bid; }
    else if (bid < 128) { S = Wk; D = dWqkv + 256 * Dd;  R = Dd;  Cc = Dd;  loc = bid - 64; }
    else if (bid < 192) { S = Wv; D = dWqkv + 512 * Dd;  R = Dd;  Cc = Dd;  loc = bid - 128; }
    else if (bid < 256) { S = Wo; D = dWo;               R = Dd;  Cc = Dd;  loc = bid - 192; }
    else if (bid < 512) { S = W1; D = dW1;               R = Dd;  Cc = DFF; loc = bid - 256; }
    else                { S = W2; D = dW2;               R = DFF; Cc = Dd;  loc = bid - 512; }
    const int nbx = Cc / 32;
    const int c0 = (loc % nbx) * 32, r0 = (loc / nbx) * 32;
    #pragma unroll
    for (int i = threadIdx.y; i < 32; i += 8)
        t[i][threadIdx.x] = S[(long)(r0 + i) * Cc + c0 + threadIdx.x];
    __syncthreads();
    #pragma unroll
    for (int i = threadIdx.y; i < 32; i += 8)
        D[(long)(c0 + i) * R + r0 + threadIdx.x]
            = __float2bfloat16(t[threadIdx.x][i]);
}

// ---------------------------------------------------------------------------
// bf16 GEMM (mma.sync m16n8k16): C = bf16(A) @ bf16(W)^T.
// 128x128 tile, BK=64, 8 warps, 3-stage cp.async pipeline.
// Used for QKV (gather, bf16 out) and W1 (gelu, bf16 out).
// ---------------------------------------------------------------------------
__global__ void __launch_bounds__(256, 2)
gemm_bf16(const bf16* __restrict__ A, const bf16* __restrict__ B,
          const float* __restrict__ bias,
          bf16* __restrict__ Chi,
          int Ntot, int K, int gather, int do_gelu)
{
    extern __shared__ char smem[];
    const uint32_t sb = smem_u32(smem);
    const int tid  = threadIdx.x;
    const int lane = tid & 31, wid = tid >> 5;
    const int wm = wid & 3, wn = wid >> 2;
    const int row0 = blockIdx.x * 128, col0 = blockIdx.y * 128;
    const uint32_t ST = 32768u;

    uint32_t dstOff[4];
    long aIdx[4], bIdx[4];
    #pragma unroll
    for (int s = 0; s < 4; s++) {
        const int c  = tid + s * 256;
        const int r  = c >> 3, ch = c & 7;
        dstOff[s] = (uint32_t)(r * 128 + ((ch ^ (r & 7)) << 4));
        const int gA = row0 + r;
        long ar = gA;
        if (gather) {
            const int seg = (col0 >= 256) ? 1024 : 0;
            ar = (long)(gA >> 10) * 2048 + seg + (gA & 1023);
        }
        aIdx[s] = ar * (long)K + ch * 8;
        bIdx[s] = (long)(col0 + r) * K + ch * 8;
    }

    const int CCH = K >> 6;

    #pragma unroll
    for (int pc = 0; pc < 2; pc++) {
        const uint32_t st = sb + (uint32_t)pc * ST;
        const long k0 = (long)pc * 64;
        #pragma unroll
        for (int s = 0; s < 4; s++) {
            cp16(st + 0      + dstOff[s], A + aIdx[s] + k0);
            cp16(st + 16384u + dstOff[s], B + bIdx[s] + k0);
        }
        CP_COMMIT();
    }

    float acc[2][8][4] = {};
    const int rl = lane & 7, tl = lane >> 3;

    int stg = 0, pstg = 2;
    for (int c = 0; c < CCH; c++) {
        if (c + 1 < CCH) { CP_WAIT(1); } else { CP_WAIT(0); }
        __syncthreads();

        const uint32_t base = sb + (uint32_t)stg * ST;
        #pragma unroll
        for (int ks = 0; ks < 4; ks++) {
            uint32_t aH[2][4], bH[4][4];
            #pragma unroll
            for (int i = 0; i < 2; i++) {
                const int arow = wm * 32 + i * 16 + rl + (tl & 1) * 8;
                const int ach  = ks * 2 + (tl >> 1);
                const uint32_t ad = base + (uint32_t)(arow * 128
                                  + ((ach ^ (arow & 7)) << 4));
                ldsm4(aH[i], ad);
            }
            #pragma unroll
            for (int j = 0; j < 4; j++) {
                const int brow = wn * 64 + j * 16 + rl + (tl >> 1) * 8;
                const int bch  = ks * 2 + (tl & 1);
                const uint32_t bd = base + 16384u + (uint32_t)(brow * 128
                                  + ((bch ^ (brow & 7)) << 4));
                ldsm4(bH[j], bd);
            }
            #pragma unroll
            for (int i = 0; i < 2; i++) {
                #pragma unroll
                for (int j = 0; j < 4; j++) {
                    mma_bf16(acc[i][2*j],   aH[i], &bH[j][0]);
                    mma_bf16(acc[i][2*j+1], aH[i], &bH[j][2]);
                }
            }
        }

        if (c + 2 < CCH) {
            const uint32_t st = sb + (uint32_t)pstg * ST;
            const long k0 = (long)(c + 2) * 64;
            #pragma unroll
            for (int s = 0; s < 4; s++) {
                cp16(st + 0      + dstOff[s], A + aIdx[s] + k0);
                cp16(st + 16384u + dstOff[s], B + bIdx[s] + k0);
            }
            CP_COMMIT();
        }
        stg  = (stg  == 2) ? 0 : stg  + 1;
        pstg = (pstg == 2) ? 0 : pstg + 1;
    }

    #pragma unroll
    for (int i = 0; i < 2; i++) {
        const int r_top = row0 + wm * 32 + i * 16 + (lane >> 2);
        #pragma unroll
        for (int j = 0; j < 8; j++) {
            const int col = col0 + wn * 64 + j * 8 + (lane & 3) * 2;
            const float b0 = bias[col], b1 = bias[col + 1];
            float v00 = acc[i][j][0] + b0, v01 = acc[i][j][1] + b1;
            float v10 = acc[i][j][2] + b0, v11 = acc[i][j][3] + b1;
            if (do_gelu) {
                v00 = 0.5f * v00 * (1.0f + erff(v00 * 0.70710678118654752f));
                v01 = 0.5f * v01 * (1.0f + erff(v01 * 0.70710678118654752f));
                v10 = 0.5f * v10 * (1.0f + erff(v10 * 0.70710678118654752f));
                v11 = 0.5f * v11 * (1.0f + erff(v11 * 0.70710678118654752f));
            }
            const long o0 = (long)r_top * Ntot + col;
            const long o1 = (long)(r_top + 8) * Ntot + col;
            *(__nv_bfloat162*)(Chi + o0) = __floats2bfloat162_rn(v00, v01);
            *(__nv_bfloat162*)(Chi + o1) = __floats2bfloat162_rn(v10, v11);
        }
    }
}

// ---------------------------------------------------------------------------
// Fused GEMM + bias + residual + LayerNorm.  Tile 128 x 256 (full row),
// 512 threads (16 warps: wm 0..3 x wn 0..3), BK=64, 3-stage pipeline.
// Y = LN(A @ B^T + bias + res; g, beta)  -> Yf fp32 [, YHi bf16].
// smem: 3 stages x 49152 (A 16KB + B 32KB) + LN sums (1KB).
// ---------------------------------------------------------------------------
__global__ void __launch_bounds__(512, 1)
gemm_ln(const bf16* __restrict__ A, const bf16* __restrict__ B,
        const float* __restrict__ bias, const float* __restrict__ res,
        const float* __restrict__ g, const float* __restrict__ beta,
        float* __restrict__ Yf, bf16* __restrict__ YHi, int K)
{
    extern __shared__ char smem[];
    const uint32_t sb = smem_u32(smem);
    float* sSum = (float*)(smem + 147456);
    float* sSq  = (float*)(smem + 147456 + 512);

    const int tid  = threadIdx.x;
    const int lane = tid & 31, wid = tid >> 5;
    const int wm = wid & 3, wn = wid >> 2;
    const int row0 = blockIdx.x * 128;
    const uint32_t ST = 49152u;

    // loaders: A 1024 chunks / 512 thr = 2 slots; B 2048 / 512 = 4 slots
    uint32_t aOff[2]; long aIdx[2];
    #pragma unroll
    for (int s = 0; s < 2; s++) {
        const int c = tid + s * 512;
        const int r = c >> 3, ch = c & 7;
        aOff[s] = (uint32_t)(r * 128 + ((ch ^ (r & 7)) << 4));
        aIdx[s] = (long)(row0 + r) * K + ch * 8;
    }
    uint32_t bOff[4]; long bIdx[4];
    #pragma unroll
    for (int s = 0; s < 4; s++) {
        const int c = tid + s * 512;
        const int r = c >> 3, ch = c & 7;
        bOff[s] = 16384u + (uint32_t)(r * 128 + ((ch ^ (r & 7)) << 4));
        bIdx[s] = (long)r * K + ch * 8;
    }

    const int CCH = K >> 6;

    #pragma unroll
    for (int pc = 0; pc < 2; pc++) {
        const uint32_t st = sb + (uint32_t)pc * ST;
        const long k0 = (long)pc * 64;
        #pragma unroll
        for (int s = 0; s < 2; s++) cp16(st + aOff[s], A + aIdx[s] + k0);
        #pragma unroll
        for (int s = 0; s < 4; s++) cp16(st + bOff[s], B + bIdx[s] + k0);
        CP_COMMIT();
    }

    if (tid < 128) { sSum[tid] = 0.0f; sSq[tid] = 0.0f; }

    float acc[2][8][4] = {};
    const int rl = lane & 7, tl = lane >> 3;

    int stg = 0, pstg = 2;
    for (int c = 0; c < CCH; c++) {
        if (c + 1 < CCH) { CP_WAIT(1); } else { CP_WAIT(0); }
        __syncthreads();

        const uint32_t base = sb + (uint32_t)stg * ST;
        #pragma unroll
        for (int ks = 0; ks < 4; ks++) {
            uint32_t aH[2][4], bH[4][4];
            #pragma unroll
            for (int i = 0; i < 2; i++) {
                const int arow = wm * 32 + i * 16 + rl + (tl & 1) * 8;
                const int ach  = ks * 2 + (tl >> 1);
                const uint32_t ad = base + (uint32_t)(arow * 128
                                  + ((ach ^ (arow & 7)) << 4));
                ldsm4(aH[i], ad);
            }
            #pragma unroll
            for (int j = 0; j < 4; j++) {
                const int brow = wn * 64 + j * 16 + rl + (tl >> 1) * 8;
                const int bch  = ks * 2 + (tl & 1);
                const uint32_t bd = base + 16384u + (uint32_t)(brow * 128
                                  + ((bch ^ (brow & 7)) << 4));
                ldsm4(bH[j], bd);
            }
            #pragma unroll
            for (int i = 0; i < 2; i++) {
                #pragma unroll
                for (int j = 0; j < 4; j++) {
                    mma_bf16(acc[i][2*j],   aH[i], &bH[j][0]);
                    mma_bf16(acc[i][2*j+1], aH[i], &bH[j][2]);
                }
            }
        }

        if (c + 2 < CCH) {
            const uint32_t st = sb + (uint32_t)pstg * ST;
            const long k0 = (long)(c + 2) * 64;
            #pragma unroll
            for (int s = 0; s < 2; s++) cp16(st + aOff[s], A + aIdx[s] + k0);
            #pragma unroll
            for (int s = 0; s < 4; s++) cp16(st + bOff[s], B + bIdx[s] + k0);
            CP_COMMIT();
        }
        stg  = (stg  == 2) ? 0 : stg  + 1;
        pstg = (pstg == 2) ? 0 : pstg + 1;
    }

    // --- epilogue: v = acc + bias + res; accumulate row sums; LN; store ---
    // thread covers rows rA(i), rA(i)+8 (i=0,1) x cols wn*64 + j*8 + (lane&3)*2
    __syncthreads();    // sSum/sSq init visible; mainloop smem reads done

    #pragma unroll
    for (int i = 0; i < 2; i++) {
        const int rloc0 = wm * 32 + i * 16 + (lane >> 2);
        float s0 = 0.0f, q0 = 0.0f, s1 = 0.0f, q1 = 0.0f;
        #pragma unroll
        for (int j = 0; j < 8; j++) {
            const int col = wn * 64 + j * 8 + (lane & 3) * 2;
            const float b0 = bias[col], b1 = bias[col + 1];
            const long o0 = (long)(row0 + rloc0) * Dd + col;
            const long o1 = o0 + 8L * Dd;
            float v00 = acc[i][j][0] + b0 + res[o0];
            float v01 = acc[i][j][1] + b1 + res[o0 + 1];
            float v10 = acc[i][j][2] + b0 + res[o1];
            float v11 = acc[i][j][3] + b1 + res[o1 + 1];
            acc[i][j][0] = v00; acc[i][j][1] = v01;
            acc[i][j][2] = v10; acc[i][j][3] = v11;
            s0 += v00 + v01;          q0 += v00 * v00 + v01 * v01;
            s1 += v10 + v11;          q1 += v10 * v10 + v11 * v11;
        }
        // reduce over lane&3 (4 threads share a row within this warp)
        #pragma unroll
        for (int o = 1; o <= 2; o <<= 1) {
            s0 += __shfl_xor_sync(0xffffffffu, s0, o);
            q0 += __shfl_xor_sync(0xffffffffu, q0, o);
            s1 += __shfl_xor_sync(0xffffffffu, s1, o);
            q1 += __shfl_xor_sync(0xffffffffu, q1, o);
        }
        if ((lane & 3) == 0) {
            atomicAdd(&sSum[rloc0], s0);     atomicAdd(&sSq[rloc0], q0);
            atomicAdd(&sSum[rloc0 + 8], s1); atomicAdd(&sSq[rloc0 + 8], q1);
        }
    }
    __syncthreads();

    #pragma unroll
    for (int i = 0; i < 2; i++) {
        const int rloc0 = wm * 32 + i * 16 + (lane >> 2);
        const float mu0  = sSum[rloc0] * (1.0f / 256.0f);
        const float var0 = sSq[rloc0] * (1.0f / 256.0f) - mu0 * mu0;
        const float in0  = rsqrtf(var0 + 1e-5f);
        const float mu1  = sSum[rloc0 + 8] * (1.0f / 256.0f);
        const float var1 = sSq[rloc0 + 8] * (1.0f / 256.0f) - mu1 * mu1;
        const float in1  = rsqrtf(var1 + 1e-5f);
        #pragma unroll
        for (int j = 0; j < 8; j++) {
            const int col = wn * 64 + j * 8 + (lane & 3) * 2;
            const float g0 = g[col], g1 = g[col + 1];
            const float e0 = beta[col], e1 = beta[col + 1];
            const long o0 = (long)(row0 + rloc0) * Dd + col;
            const long o1 = o0 + 8L * Dd;
            float y00 = (acc[i][j][0] - mu0) * in0 * g0 + e0;
            float y01 = (acc[i][j][1] - mu0) * in0 * g1 + e1;
            float y10 = (acc[i][j][2] - mu1) * in1 * g0 + e0;
            float y11 = (acc[i][j][3] - mu1) * in1 * g1 + e1;
            *(float2*)(Yf + o0) = make_float2(y00, y01);
            *(float2*)(Yf + o1) = make_float2(y10, y11);
            if (YHi) {
                *(__nv_bfloat162*)(YHi + o0) = __floats2bfloat162_rn(y00, y01);
                *(__nv_bfloat162*)(YHi + o1) = __floats2bfloat162_rn(y10, y11);
            }
        }
    }
}

// ---------------------------------------------------------------------------
// Tensor-core flash attention: 128 queries/block, 4 warps x 2 m-tiles of 16
// rows. Each K/V fragment load feeds both m-tiles.
// ---------------------------------------------------------------------------
__global__ void __launch_bounds__(128, 4)
attn_tc(const bf16* __restrict__ QKVh, bf16* __restrict__ OutHi)
{
    __shared__ bf16 sQ[4096];
    __shared__ bf16 sK[2][2048];
    __shared__ bf16 sV[2][2048];

    const int stage = blockIdx.z;
    const int qoff = stage ? 256 : 0;
    const int koff = stage ? 0 : 256;
    const int voff = stage ? 0 : 512;
    const int out_off = stage ? SEG : 0;

    const int bh = blockIdx.y;
    const int b  = bh >> 3;
    const int h  = bh & 7;
    const int q0 = blockIdx.x * 128;

    const int tid  = threadIdx.x;
    const int lane = tid & 31, warp = tid >> 5;
    const int rl = lane & 7, tl = lane >> 3;

    const uint32_t sQb = smem_u32(sQ);
    const uint32_t sKb[2] = { smem_u32(sK[0]), smem_u32(sK[1]) };
    const uint32_t sVb[2] = { smem_u32(sV[0]), smem_u32(sV[1]) };

    #pragma unroll
    for (int s = 0; s < 4; s++) {
        const int c = tid + s * 128;
        const int r = c >> 2, ch = c & 3;
        const uint32_t dst = sQb + (uint32_t)(r * 64 + ((ch ^ (r & 3)) << 4));
        cp16(dst, QKVh + (long)(b * SEG + q0 + r) * NQKV + qoff + h * DK + ch * 8);
    }
    CP_COMMIT();

    #pragma unroll
    for (int s = 0; s < 4; s++) {
        const int c   = tid + s * 128;
        const int arr = c >> 8;
        const int r   = (c & 255) >> 2, ch = c & 3;
        const uint32_t off = (uint32_t)(r * 64 + ((ch ^ (r & 3)) << 4));
        const uint32_t dst = arr ? (sVb[0] + off) : (sKb[0] + off);
        const int coff = arr ? voff : koff;
        cp16(dst, QKVh + (long)(b * SEG + r) * NQKV + coff + h * DK + ch * 8);
    }
    CP_COMMIT();

    CP_WAIT(1);
    __syncthreads();
    uint32_t qh[2][2][4];
    #pragma unroll
    for (int m = 0; m < 2; m++) {
        #pragma unroll
        for (int ks = 0; ks < 2; ks++) {
            const int arow = warp * 32 + m * 16 + rl + (tl & 1) * 8;
            const int ach  = ks * 2 + (tl >> 1);
            const uint32_t ad = sQb + (uint32_t)(arow * 64
                              + ((ach ^ (arow & 3)) << 4));
            ldsm4(qh[m][ks], ad);
        }
    }

    float o[2][4][4] = {};
    float lsum[2][2] = {};
    const float scale = 0.17677669529663687f;

    for (int t = 0; t < 16; t++) {
        const int buf = t & 1;
        if (t + 1 < 16) {
            const int nb = buf ^ 1;
            #pragma unroll
            for (int s = 0; s < 4; s++) {
                const int c   = tid + s * 128;
                const int arr = c >> 8;
                const int r   = (c & 255) >> 2, ch = c & 3;
                const uint32_t off = (uint32_t)(r * 64 + ((ch ^ (r & 3)) << 4));
                const uint32_t dst = arr ? (sVb[nb] + off) : (sKb[nb] + off);
                const int coff = arr ? voff : koff;
                cp16(dst, QKVh + (long)(b * SEG + (t + 1) * 64 + r) * NQKV
                          + coff + h * DK + ch * 8);
            }
            CP_COMMIT();
            CP_WAIT(1);
        } else {
            CP_WAIT(0);
        }
        __syncthreads();

        #pragma unroll
        for (int nb16 = 0; nb16 < 4; nb16++) {
            float s2[2][2][4] = {};
            #pragma unroll
            for (int ks = 0; ks < 2; ks++) {
                const int krow = nb16 * 16 + rl + (tl >> 1) * 8;
                const int kch  = ks * 2 + (tl & 1);
                const uint32_t ka = sKb[buf] + (uint32_t)(krow * 64
                                  + ((kch ^ (krow & 3)) << 4));
                uint32_t kh[4];
                ldsm4(kh, ka);
                #pragma unroll
                for (int m = 0; m < 2; m++) {
                    mma_bf16(s2[m][0], qh[m][ks], &kh[0]);
                    mma_bf16(s2[m][1], qh[m][ks], &kh[2]);
                }
            }
            uint32_t pf[2][4];
            #pragma unroll
            for (int m = 0; m < 2; m++) {
                float p00 = __expf(s2[m][0][0] * scale), p01 = __expf(s2[m][0][1] * scale);
                float p02 = __expf(s2[m][0][2] * scale), p03 = __expf(s2[m][0][3] * scale);
                float p10 = __expf(s2[m][1][0] * scale), p11 = __expf(s2[m][1][1] * scale);
                float p12 = __expf(s2[m][1][2] * scale), p13 = __expf(s2[m][1][3] * scale);
                lsum[m][0] += p00 + p01 + p10 + p11;
                lsum[m][1] += p02 + p03 + p12 + p13;
                __nv_bfloat162 t2;
                t2 = __floats2bfloat162_rn(p00, p01); pf[m][0] = *(uint32_t*)&t2;
                t2 = __floats2bfloat162_rn(p02, p03); pf[m][1] = *(uint32_t*)&t2;
                t2 = __floats2bfloat162_rn(p10, p11); pf[m][2] = *(uint32_t*)&t2;
                t2 = __floats2bfloat162_rn(p12, p13); pf[m][3] = *(uint32_t*)&t2;
            }
            #pragma unroll
            for (int db = 0; db < 2; db++) {
                const int vrow = nb16 * 16 + rl + (tl & 1) * 8;
                const int vch  = db * 2 + (tl >> 1);
                const uint32_t va = sVb[buf] + (uint32_t)(vrow * 64
                                  + ((vch ^ (vrow & 3)) << 4));
                uint32_t vf[4];
                ldsm4t(vf, va);
                #pragma unroll
                for (int m = 0; m < 2; m++) {
                    mma_bf16(o[m][db * 2],     pf[m], &vf[0]);
                    mma_bf16(o[m][db * 2 + 1], pf[m], &vf[2]);
                }
            }
        }
        __syncthreads();
    }

    #pragma unroll
    for (int m = 0; m < 2; m++) {
        float l0 = lsum[m][0], l1 = lsum[m][1];
        l0 += __shfl_xor_sync(0xffffffffu, l0, 1);
        l0 += __shfl_xor_sync(0xffffffffu, l0, 2);
        l1 += __shfl_xor_sync(0xffffffffu, l1, 1);
        l1 += __shfl_xor_sync(0xffffffffu, l1, 2);
        const float inv0 = 1.0f / l0;
        const float inv1 = 1.0f / l1;

        const int rloc = q0 + warp * 32 + m * 16 + (lane >> 2);
        const long row0g = (long)(b * 2 * SEG + out_off + rloc) * Dd + h * DK;
        const long row1g = row0g + 8L * Dd;
        #pragma unroll
        for (int db = 0; db < 4; db++) {
            const int col = db * 8 + (lane & 3) * 2;
            *(__nv_bfloat162*)(OutHi + row0g + col)
                = __floats2bfloat162_rn(o[m][db][0] * inv0, o[m][db][1] * inv0);
            *(__nv_bfloat162*)(OutHi + row1g + col)
                = __floats2bfloat162_rn(o[m][db][2] * inv1, o[m][db][3] * inv1);
        }
    }
}

// ---------------------------------------------------------------------------
// Launch
// ---------------------------------------------------------------------------
extern "C" void kernel_launch(void* const* d_in, const int* in_sizes, int n_in,
                              void* d_out, int out_size)
{
    const float* x   = (const float*)d_in[0];
    const float* Wq  = (const float*)d_in[1];
    const float* bq  = (const float*)d_in[2];
    const float* Wk  = (const float*)d_in[3];
    const float* bk  = (const float*)d_in[4];
    const float* Wv  = (const float*)d_in[5];
    const float* bv  = (const float*)d_in[6];
    const float* Wo  = (const float*)d_in[7];
    const float* bo  = (const float*)d_in[8];
    const float* g31 = (const float*)d_in[9];
    const float* b31 = (const float*)d_in[10];
    const float* W1  = (const float*)d_in[11];
    const float* b1  = (const float*)d_in[12];
    const float* W2  = (const float*)d_in[13];
    const float* b2  = (const float*)d_in[14];
    const float* g41 = (const float*)d_in[15];
    const float* b41 = (const float*)d_in[16];
    float* out = (float*)d_out;

    float *pH1, *pbqkv;
    bf16 *xHi, *QKVHi, *AttHi, *H1Hi, *THi;
    bf16 *WqkvT, *WoT, *W1T, *W2T;

    cudaGetSymbolAddress((void**)&pH1, g_H1);
    cudaGetSymbolAddress((void**)&pbqkv, g_bqkv);
    cudaGetSymbolAddress((void**)&xHi,   g_xHi);
    cudaGetSymbolAddress((void**)&QKVHi, g_QKVHi);
    cudaGetSymbolAddress((void**)&AttHi, g_AttHi);
    cudaGetSymbolAddress((void**)&H1Hi,  g_H1Hi);
    cudaGetSymbolAddress((void**)&THi,   g_THi);
    cudaGetSymbolAddress((void**)&WqkvT, g_WqkvT);
    cudaGetSymbolAddress((void**)&WoT, g_WoT);
    cudaGetSymbolAddress((void**)&W1T, g_W1T);
    cudaGetSymbolAddress((void**)&W2T, g_W2T);

    static bool attr_set = false;
    if (!attr_set) {
        cudaFuncSetAttribute(gemm_bf16,
            cudaFuncAttributeMaxDynamicSharedMemorySize, 98304);
        cudaFuncSetAttribute(gemm_ln,
            cudaFuncAttributeMaxDynamicSharedMemorySize, 148480);
        attr_set = true;
    }

    // weight prep + x convert
    transpose_all<<<768, dim3(32, 8)>>>(Wq, Wk, Wv, Wo, W1, W2, bq, bk, bv,
                                        WqkvT, WoT, W1T, W2T, pbqkv);
    cvt_kernel<<<(NROWS_FULL * Dd) / 1024, 256>>>(x, xHi);

    // fused QKV projection (N=768, per-column segment gather)
    gemm_bf16<<<dim3(NROWS_HALF / 128, NQKV / 128), 256, 98304>>>(
        xHi, WqkvT, pbqkv, QKVHi, NQKV, Dd, 1, 0);

    // two-stage cross-segment attention
    attn_tc<<<dim3(SEG / 128, Bb * Hh, 2), 128>>>(QKVHi, AttHi);

    // output projection + residual(x) + LN1 (fused) -> H1 fp32 + bf16
    gemm_ln<<<NROWS_FULL / 128, 512, 148480>>>(
        AttHi, WoT, bo, x, g31, b31, pH1, H1Hi, Dd);

    // W1 + gelu -> T bf16
    gemm_bf16<<<dim3(NROWS_FULL / 128, DFF / 128), 256, 98304>>>(
        H1Hi, W1T, b1, THi, DFF, Dd, 0, 1);

    // W2 + residual(H1) + LN2 (fused) -> out fp32
    gemm_ln<<<NROWS_FULL / 128, 512, 148480>>>(
        THi, W2T, b2, pH1, g41, b41, out, nullptr, DFF);
}

// round 15
// speedup vs baseline: 2.2615x; 1.0006x over previous
#include <cuda_runtime.h>
#include <cuda_bf16.h>
#include <math.h>
#include <stdint.h>

// ---------------------------------------------------------------------------
// TwoStageAttentionLayerCrossSegments  (B=16, TS_D=2, SEG=1024, D=256, H=8,
// DK=32, D_FF=1024)
// All GEMMs single-MMA bf16, BK=64, 3-stage cp.async.
// Wo and W2 GEMMs fuse bias+residual+LayerNorm in the epilogue.
// Attention: 128 q/block, 4 warps x 2 m-tiles; 3-stage K/V ring, 1 bar/tile.
// ---------------------------------------------------------------------------

typedef __nv_bfloat16 bf16;

#define Bb   16
#define SEG  1024
#define Dd   256
#define Hh   8
#define DK   32
#define DFF  1024
#define NROWS_HALF (Bb*SEG)        // 16384
#define NROWS_FULL (Bb*2*SEG)      // 32768
#define NQKV 768

// fp32 scratch
__device__ float g_H1[NROWS_FULL * Dd];

// bf16 activations
__device__ bf16 g_xHi  [NROWS_FULL * Dd];
__device__ bf16 g_QKVHi[NROWS_HALF * NQKV];
__device__ bf16 g_AttHi[NROWS_FULL * Dd];
__device__ bf16 g_H1Hi [NROWS_FULL * Dd];
__device__ bf16 g_THi  [NROWS_FULL * DFF];

// transposed weights ([N,K] K-major), bf16
__device__ bf16 g_WqkvT[NQKV * Dd];
__device__ bf16 g_WoT[Dd * Dd];
__device__ bf16 g_W1T[DFF * Dd];
__device__ bf16 g_W2T[Dd * DFF];
__device__ float g_bqkv[NQKV];

// ---------------------------------------------------------------------------
// helpers
// ---------------------------------------------------------------------------
__device__ __forceinline__ uint32_t smem_u32(const void* p) {
    uint32_t a;
    asm("{ .reg .u64 t; cvta.to.shared.u64 t, %1; cvt.u32.u64 %0, t; }"
        : "=r"(a) : "l"(p));
    return a;
}

__device__ __forceinline__ void cp16(uint32_t s, const void* g) {
    asm volatile("cp.async.cg.shared.global [%0], [%1], 16;" :: "r"(s), "l"(g));
}
#define CP_COMMIT() asm volatile("cp.async.commit_group;" ::: "memory")
#define CP_WAIT(n)  asm volatile("cp.async.wait_group %0;" :: "n"(n) : "memory")

__device__ __forceinline__ void ldsm4(uint32_t* r, uint32_t addr) {
    asm volatile("ldmatrix.sync.aligned.m8n8.x4.shared.b16 {%0,%1,%2,%3}, [%4];"
        : "=r"(r[0]), "=r"(r[1]), "=r"(r[2]), "=r"(r[3]) : "r"(addr));
}
__device__ __forceinline__ void ldsm4t(uint32_t* r, uint32_t addr) {
    asm volatile("ldmatrix.sync.aligned.m8n8.x4.trans.shared.b16 {%0,%1,%2,%3}, [%4];"
        : "=r"(r[0]), "=r"(r[1]), "=r"(r[2]), "=r"(r[3]) : "r"(addr));
}

__device__ __forceinline__ void mma_bf16(float* d, const uint32_t* a, const uint32_t* b) {
    asm volatile(
        "mma.sync.aligned.m16n8k16.row.col.f32.bf16.bf16.f32 "
        "{%0,%1,%2,%3}, {%4,%5,%6,%7}, {%8,%9}, {%0,%1,%2,%3};"
        : "+f"(d[0]), "+f"(d[1]), "+f"(d[2]), "+f"(d[3])
        : "r"(a[0]), "r"(a[1]), "r"(a[2]), "r"(a[3]), "r"(b[0]), "r"(b[1]));
}

// ---------------------------------------------------------------------------
// fp32 -> bf16 convert
// ---------------------------------------------------------------------------
__global__ void __launch_bounds__(256)
cvt_kernel(const float* __restrict__ X, bf16* __restrict__ Hi)
{
    const long i = ((long)blockIdx.x * 256 + threadIdx.x) * 4;
    float4 v = *(const float4*)(X + i);
    *(__nv_bfloat162*)(Hi + i)     = __floats2bfloat162_rn(v.x, v.y);
    *(__nv_bfloat162*)(Hi + i + 2) = __floats2bfloat162_rn(v.z, v.w);
}

// ---------------------------------------------------------------------------
// All weight transposes (bf16) + QKV bias concat, ONE launch.
// ---------------------------------------------------------------------------
__global__ void __launch_bounds__(256)
transpose_all(const float* __restrict__ Wq, const float* __restrict__ Wk,
              const float* __restrict__ Wv, const float* __restrict__ Wo,
              const float* __restrict__ W1, const float* __restrict__ W2,
              const float* __restrict__ bq, const float* __restrict__ bk,
              const float* __restrict__ bv,
              bf16* __restrict__ dWqkv, bf16* __restrict__ dWo,
              bf16* __restrict__ dW1, bf16* __restrict__ dW2,
              float* __restrict__ dbqkv)
{
    __shared__ float t[32][33];
    const int bid = blockIdx.x;
    const int tix = threadIdx.y * 32 + threadIdx.x;
    if (bid == 0 && tix < 256) {
        dbqkv[tix]       = bq[tix];
        dbqkv[tix + 256] = bk[tix];
        dbqkv[tix + 512] = bv[tix];
    }
    const float* S; bf16* D; int R, Cc, loc;
    if      (bid < 64)  { S = Wq; D = dWqkv;             R = Dd;  Cc = Dd;  loc = bid; }
    else if (bid < 128) { S = Wk; D = dWqkv + 256 * Dd;  R = Dd;  Cc = Dd;  loc = bid - 64; }
    else if (bid < 192) { S = Wv; D = dWqkv + 512 * Dd;  R = Dd;  Cc = Dd;  loc = bid - 128; }
    else if (bid < 256) { S = Wo; D = dWo;               R = Dd;  Cc = Dd;  loc = bid - 192; }
    else if (bid < 512) { S = W1; D = dW1;               R = Dd;  Cc = DFF; loc = bid - 256; }
    else                { S = W2; D = dW2;               R = DFF; Cc = Dd;  loc = bid - 512; }
    const int nbx = Cc / 32;
    const int c0 = (loc % nbx) * 32, r0 = (loc / nbx) * 32;
    #pragma unroll
    for (int i = threadIdx.y; i < 32; i += 8)
        t[i][threadIdx.x] = S[(long)(r0 + i) * Cc + c0 + threadIdx.x];
    __syncthreads();
    #pragma unroll
    for (int i = threadIdx.y; i < 32; i += 8)
        D[(long)(c0 + i) * R + r0 + threadIdx.x]
            = __float2bfloat16(t[threadIdx.x][i]);
}

// ---------------------------------------------------------------------------
// bf16 GEMM (mma.sync m16n8k16): C = bf16(A) @ bf16(W)^T.
// 128x128 tile, BK=64, 8 warps, 3-stage cp.async pipeline.
// ---------------------------------------------------------------------------
__global__ void __launch_bounds__(256, 2)
gemm_bf16(const bf16* __restrict__ A, const bf16* __restrict__ B,
          const float* __restrict__ bias,
          bf16* __restrict__ Chi,
          int Ntot, int K, int gather, int do_gelu)
{
    extern __shared__ char smem[];
    const uint32_t sb = smem_u32(smem);
    const int tid  = threadIdx.x;
    const int lane = tid & 31, wid = tid >> 5;
    const int wm = wid & 3, wn = wid >> 2;
    const int row0 = blockIdx.x * 128, col0 = blockIdx.y * 128;
    const uint32_t ST = 32768u;

    uint32_t dstOff[4];
    long aIdx[4], bIdx[4];
    #pragma unroll
    for (int s = 0; s < 4; s++) {
        const int c  = tid + s * 256;
        const int r  = c >> 3, ch = c & 7;
        dstOff[s] = (uint32_t)(r * 128 + ((ch ^ (r & 7)) << 4));
        const int gA = row0 + r;
        long ar = gA;
        if (gather) {
            const int seg = (col0 >= 256) ? 1024 : 0;
            ar = (long)(gA >> 10) * 2048 + seg + (gA & 1023);
        }
        aIdx[s] = ar * (long)K + ch * 8;
        bIdx[s] = (long)(col0 + r) * K + ch * 8;
    }

    const int CCH = K >> 6;

    #pragma unroll
    for (int pc = 0; pc < 2; pc++) {
        const uint32_t st = sb + (uint32_t)pc * ST;
        const long k0 = (long)pc * 64;
        #pragma unroll
        for (int s = 0; s < 4; s++) {
            cp16(st + 0      + dstOff[s], A + aIdx[s] + k0);
            cp16(st + 16384u + dstOff[s], B + bIdx[s] + k0);
        }
        CP_COMMIT();
    }

    float acc[2][8][4] = {};
    const int rl = lane & 7, tl = lane >> 3;

    int stg = 0, pstg = 2;
    for (int c = 0; c < CCH; c++) {
        if (c + 1 < CCH) { CP_WAIT(1); } else { CP_WAIT(0); }
        __syncthreads();

        const uint32_t base = sb + (uint32_t)stg * ST;
        #pragma unroll
        for (int ks = 0; ks < 4; ks++) {
            uint32_t aH[2][4], bH[4][4];
            #pragma unroll
            for (int i = 0; i < 2; i++) {
                const int arow = wm * 32 + i * 16 + rl + (tl & 1) * 8;
                const int ach  = ks * 2 + (tl >> 1);
                const uint32_t ad = base + (uint32_t)(arow * 128
                                  + ((ach ^ (arow & 7)) << 4));
                ldsm4(aH[i], ad);
            }
            #pragma unroll
            for (int j = 0; j < 4; j++) {
                const int brow = wn * 64 + j * 16 + rl + (tl >> 1) * 8;
                const int bch  = ks * 2 + (tl & 1);
                const uint32_t bd = base + 16384u + (uint32_t)(brow * 128
                                  + ((bch ^ (brow & 7)) << 4));
                ldsm4(bH[j], bd);
            }
            #pragma unroll
            for (int i = 0; i < 2; i++) {
                #pragma unroll
                for (int j = 0; j < 4; j++) {
                    mma_bf16(acc[i][2*j],   aH[i], &bH[j][0]);
                    mma_bf16(acc[i][2*j+1], aH[i], &bH[j][2]);
                }
            }
        }

        if (c + 2 < CCH) {
            const uint32_t st = sb + (uint32_t)pstg * ST;
            const long k0 = (long)(c + 2) * 64;
            #pragma unroll
            for (int s = 0; s < 4; s++) {
                cp16(st + 0      + dstOff[s], A + aIdx[s] + k0);
                cp16(st + 16384u + dstOff[s], B + bIdx[s] + k0);
            }
            CP_COMMIT();
        }
        stg  = (stg  == 2) ? 0 : stg  + 1;
        pstg = (pstg == 2) ? 0 : pstg + 1;
    }

    #pragma unroll
    for (int i = 0; i < 2; i++) {
        const int r_top = row0 + wm * 32 + i * 16 + (lane >> 2);
        #pragma unroll
        for (int j = 0; j < 8; j++) {
            const int col = col0 + wn * 64 + j * 8 + (lane & 3) * 2;
            const float b0 = bias[col], b1 = bias[col + 1];
            float v00 = acc[i][j][0] + b0, v01 = acc[i][j][1] + b1;
            float v10 = acc[i][j][2] + b0, v11 = acc[i][j][3] + b1;
            if (do_gelu) {
                v00 = 0.5f * v00 * (1.0f + erff(v00 * 0.70710678118654752f));
                v01 = 0.5f * v01 * (1.0f + erff(v01 * 0.70710678118654752f));
                v10 = 0.5f * v10 * (1.0f + erff(v10 * 0.70710678118654752f));
                v11 = 0.5f * v11 * (1.0f + erff(v11 * 0.70710678118654752f));
            }
            const long o0 = (long)r_top * Ntot + col;
            const long o1 = (long)(r_top + 8) * Ntot + col;
            *(__nv_bfloat162*)(Chi + o0) = __floats2bfloat162_rn(v00, v01);
            *(__nv_bfloat162*)(Chi + o1) = __floats2bfloat162_rn(v10, v11);
        }
    }
}

// ---------------------------------------------------------------------------
// Fused GEMM + bias + residual + LayerNorm.  Tile 128 x 256 (full row),
// 512 threads (16 warps), BK=64, 3-stage pipeline.
// ---------------------------------------------------------------------------
__global__ void __launch_bounds__(512, 1)
gemm_ln(const bf16* __restrict__ A, const bf16* __restrict__ B,
        const float* __restrict__ bias, const float* __restrict__ res,
        const float* __restrict__ g, const float* __restrict__ beta,
        float* __restrict__ Yf, bf16* __restrict__ YHi, int K)
{
    extern __shared__ char smem[];
    const uint32_t sb = smem_u32(smem);
    float* sSum = (float*)(smem + 147456);
    float* sSq  = (float*)(smem + 147456 + 512);

    const int tid  = threadIdx.x;
    const int lane = tid & 31, wid = tid >> 5;
    const int wm = wid & 3, wn = wid >> 2;
    const int row0 = blockIdx.x * 128;
    const uint32_t ST = 49152u;

    uint32_t aOff[2]; long aIdx[2];
    #pragma unroll
    for (int s = 0; s < 2; s++) {
        const int c = tid + s * 512;
        const int r = c >> 3, ch = c & 7;
        aOff[s] = (uint32_t)(r * 128 + ((ch ^ (r & 7)) << 4));
        aIdx[s] = (long)(row0 + r) * K + ch * 8;
    }
    uint32_t bOff[4]; long bIdx[4];
    #pragma unroll
    for (int s = 0; s < 4; s++) {
        const int c = tid + s * 512;
        const int r = c >> 3, ch = c & 7;
        bOff[s] = 16384u + (uint32_t)(r * 128 + ((ch ^ (r & 7)) << 4));
        bIdx[s] = (long)r * K + ch * 8;
    }

    const int CCH = K >> 6;

    #pragma unroll
    for (int pc = 0; pc < 2; pc++) {
        const uint32_t st = sb + (uint32_t)pc * ST;
        const long k0 = (long)pc * 64;
        #pragma unroll
        for (int s = 0; s < 2; s++) cp16(st + aOff[s], A + aIdx[s] + k0);
        #pragma unroll
        for (int s = 0; s < 4; s++) cp16(st + bOff[s], B + bIdx[s] + k0);
        CP_COMMIT();
    }

    if (tid < 128) { sSum[tid] = 0.0f; sSq[tid] = 0.0f; }

    float acc[2][8][4] = {};
    const int rl = lane & 7, tl = lane >> 3;

    int stg = 0, pstg = 2;
    for (int c = 0; c < CCH; c++) {
        if (c + 1 < CCH) { CP_WAIT(1); } else { CP_WAIT(0); }
        __syncthreads();

        const uint32_t base = sb + (uint32_t)stg * ST;
        #pragma unroll
        for (int ks = 0; ks < 4; ks++) {
            uint32_t aH[2][4], bH[4][4];
            #pragma unroll
            for (int i = 0; i < 2; i++) {
                const int arow = wm * 32 + i * 16 + rl + (tl & 1) * 8;
                const int ach  = ks * 2 + (tl >> 1);
                const uint32_t ad = base + (uint32_t)(arow * 128
                                  + ((ach ^ (arow & 7)) << 4));
                ldsm4(aH[i], ad);
            }
            #pragma unroll
            for (int j = 0; j < 4; j++) {
                const int brow = wn * 64 + j * 16 + rl + (tl >> 1) * 8;
                const int bch  = ks * 2 + (tl & 1);
                const uint32_t bd = base + 16384u + (uint32_t)(brow * 128
                                  + ((bch ^ (brow & 7)) << 4));
                ldsm4(bH[j], bd);
            }
            #pragma unroll
            for (int i = 0; i < 2; i++) {
                #pragma unroll
                for (int j = 0; j < 4; j++) {
                    mma_bf16(acc[i][2*j],   aH[i], &bH[j][0]);
                    mma_bf16(acc[i][2*j+1], aH[i], &bH[j][2]);
                }
            }
        }

        if (c + 2 < CCH) {
            const uint32_t st = sb + (uint32_t)pstg * ST;
            const long k0 = (long)(c + 2) * 64;
            #pragma unroll
            for (int s = 0; s < 2; s++) cp16(st + aOff[s], A + aIdx[s] + k0);
            #pragma unroll
            for (int s = 0; s < 4; s++) cp16(st + bOff[s], B + bIdx[s] + k0);
            CP_COMMIT();
        }
        stg  = (stg  == 2) ? 0 : stg  + 1;
        pstg = (pstg == 2) ? 0 : pstg + 1;
    }

    __syncthreads();

    #pragma unroll
    for (int i = 0; i < 2; i++) {
        const int rloc0 = wm * 32 + i * 16 + (lane >> 2);
        float s0 = 0.0f, q0 = 0.0f, s1 = 0.0f, q1 = 0.0f;
        #pragma unroll
        for (int j = 0; j < 8; j++) {
            const int col = wn * 64 + j * 8 + (lane & 3) * 2;
            const float b0 = bias[col], b1 = bias[col + 1];
            const long o0 = (long)(row0 + rloc0) * Dd + col;
            const long o1 = o0 + 8L * Dd;
            float v00 = acc[i][j][0] + b0 + res[o0];
            float v01 = acc[i][j][1] + b1 + res[o0 + 1];
            float v10 = acc[i][j][2] + b0 + res[o1];
            float v11 = acc[i][j][3] + b1 + res[o1 + 1];
            acc[i][j][0] = v00; acc[i][j][1] = v01;
            acc[i][j][2] = v10; acc[i][j][3] = v11;
            s0 += v00 + v01;          q0 += v00 * v00 + v01 * v01;
            s1 += v10 + v11;          q1 += v10 * v10 + v11 * v11;
        }
        #pragma unroll
        for (int o = 1; o <= 2; o <<= 1) {
            s0 += __shfl_xor_sync(0xffffffffu, s0, o);
            q0 += __shfl_xor_sync(0xffffffffu, q0, o);
            s1 += __shfl_xor_sync(0xffffffffu, s1, o);
            q1 += __shfl_xor_sync(0xffffffffu, q1, o);
        }
        if ((lane & 3) == 0) {
            atomicAdd(&sSum[rloc0], s0);     atomicAdd(&sSq[rloc0], q0);
            atomicAdd(&sSum[rloc0 + 8], s1); atomicAdd(&sSq[rloc0 + 8], q1);
        }
    }
    __syncthreads();

    #pragma unroll
    for (int i = 0; i < 2; i++) {
        const int rloc0 = wm * 32 + i * 16 + (lane >> 2);
        const float mu0  = sSum[rloc0] * (1.0f / 256.0f);
        const float var0 = sSq[rloc0] * (1.0f / 256.0f) - mu0 * mu0;
        const float in0  = rsqrtf(var0 + 1e-5f);
        const float mu1  = sSum[rloc0 + 8] * (1.0f / 256.0f);
        const float var1 = sSq[rloc0 + 8] * (1.0f / 256.0f) - mu1 * mu1;
        const float in1  = rsqrtf(var1 + 1e-5f);
        #pragma unroll
        for (int j = 0; j < 8; j++) {
            const int col = wn * 64 + j * 8 + (lane & 3) * 2;
            const float g0 = g[col], g1 = g[col + 1];
            const float e0 = beta[col], e1 = beta[col + 1];
            const long o0 = (long)(row0 + rloc0) * Dd + col;
            const long o1 = o0 + 8L * Dd;
            float y00 = (acc[i][j][0] - mu0) * in0 * g0 + e0;
            float y01 = (acc[i][j][1] - mu0) * in0 * g1 + e1;
            float y10 = (acc[i][j][2] - mu1) * in1 * g0 + e0;
            float y11 = (acc[i][j][3] - mu1) * in1 * g1 + e1;
            *(float2*)(Yf + o0) = make_float2(y00, y01);
            *(float2*)(Yf + o1) = make_float2(y10, y11);
            if (YHi) {
                *(__nv_bfloat162*)(YHi + o0) = __floats2bfloat162_rn(y00, y01);
                *(__nv_bfloat162*)(YHi + o1) = __floats2bfloat162_rn(y10, y11);
            }
        }
    }
}

// ---------------------------------------------------------------------------
// Tensor-core flash attention: 128 queries/block, 4 warps x 2 m-tiles of 16
// rows; K/V fragment reuse. 3-stage K/V ring, ONE barrier per 64-key tile
// (wait -> sync -> compute -> prefetch t+2).
// ---------------------------------------------------------------------------
__global__ void __launch_bounds__(128, 4)
attn_tc(const bf16* __restrict__ QKVh, bf16* __restrict__ OutHi)
{
    __shared__ bf16 sQ[4096];            // 128 rows hi (8 KB)
    __shared__ bf16 sK[3][2048];         // 3-stage     (12 KB)
    __shared__ bf16 sV[3][2048];         //             (12 KB)

    const int stage = blockIdx.z;
    const int qoff = stage ? 256 : 0;
    const int koff = stage ? 0 : 256;
    const int voff = stage ? 0 : 512;
    const int out_off = stage ? SEG : 0;

    const int bh = blockIdx.y;
    const int b  = bh >> 3;
    const int h  = bh & 7;
    const int q0 = blockIdx.x * 128;

    const int tid  = threadIdx.x;
    const int lane = tid & 31, warp = tid >> 5;
    const int rl = lane & 7, tl = lane >> 3;

    const uint32_t sQb = smem_u32(sQ);
    const uint32_t sKb[3] = { smem_u32(sK[0]), smem_u32(sK[1]), smem_u32(sK[2]) };
    const uint32_t sVb[3] = { smem_u32(sV[0]), smem_u32(sV[1]), smem_u32(sV[2]) };

    // --- load Q (group 0) ---
    #pragma unroll
    for (int s = 0; s < 4; s++) {
        const int c = tid + s * 128;
        const int r = c >> 2, ch = c & 3;
        const uint32_t dst = sQb + (uint32_t)(r * 64 + ((ch ^ (r & 3)) << 4));
        cp16(dst, QKVh + (long)(b * SEG + q0 + r) * NQKV + qoff + h * DK + ch * 8);
    }
    CP_COMMIT();

    // --- prefetch key tiles 0 and 1 (groups 1, 2) ---
    #pragma unroll
    for (int pc = 0; pc < 2; pc++) {
        #pragma unroll
        for (int s = 0; s < 4; s++) {
            const int c   = tid + s * 128;
            const int arr = c >> 8;                 // 0 K, 1 V
            const int r   = (c & 255) >> 2, ch = c & 3;
            const uint32_t off = (uint32_t)(r * 64 + ((ch ^ (r & 3)) << 4));
            const uint32_t dst = arr ? (sVb[pc] + off) : (sKb[pc] + off);
            const int coff = arr ? voff : koff;
            cp16(dst, QKVh + (long)(b * SEG + pc * 64 + r) * NQKV
                      + coff + h * DK + ch * 8);
        }
        CP_COMMIT();
    }

    // Q fragments (Q group done; K/V groups may remain outstanding)
    CP_WAIT(2);
    __syncthreads();
    uint32_t qh[2][2][4];                      // [m][ks]
    #pragma unroll
    for (int m = 0; m < 2; m++) {
        #pragma unroll
        for (int ks = 0; ks < 2; ks++) {
            const int arow = warp * 32 + m * 16 + rl + (tl & 1) * 8;
            const int ach  = ks * 2 + (tl >> 1);
            const uint32_t ad = sQb + (uint32_t)(arow * 64
                              + ((ach ^ (arow & 3)) << 4));
            ldsm4(qh[m][ks], ad);
        }
    }

    float o[2][4][4] = {};
    float lsum[2][2] = {};
    const float scale = 0.17677669529663687f;   // 1/sqrt(32)

    int stg = 0, pstg = 2;
    for (int t = 0; t < 16; t++) {
        // tile t's group complete (allow at most the next tile's group pending)
        if (t + 1 < 16) { CP_WAIT(1); } else { CP_WAIT(0); }
        __syncthreads();

        const uint32_t kb = sKb[stg], vb = sVb[stg];
        #pragma unroll
        for (int nb16 = 0; nb16 < 4; nb16++) {
            float s2[2][2][4] = {};
            #pragma unroll
            for (int ks = 0; ks < 2; ks++) {
                const int krow = nb16 * 16 + rl + (tl >> 1) * 8;
                const int kch  = ks * 2 + (tl & 1);
                const uint32_t ka = kb + (uint32_t)(krow * 64
                                  + ((kch ^ (krow & 3)) << 4));
                uint32_t kh[4];
                ldsm4(kh, ka);
                #pragma unroll
                for (int m = 0; m < 2; m++) {
                    mma_bf16(s2[m][0], qh[m][ks], &kh[0]);
                    mma_bf16(s2[m][1], qh[m][ks], &kh[2]);
                }
            }
            uint32_t pf[2][4];
            #pragma unroll
            for (int m = 0; m < 2; m++) {
                float p00 = __expf(s2[m][0][0] * scale), p01 = __expf(s2[m][0][1] * scale);
                float p02 = __expf(s2[m][0][2] * scale), p03 = __expf(s2[m][0][3] * scale);
                float p10 = __expf(s2[m][1][0] * scale), p11 = __expf(s2[m][1][1] * scale);
                float p12 = __expf(s2[m][1][2] * scale), p13 = __expf(s2[m][1][3] * scale);
                lsum[m][0] += p00 + p01 + p10 + p11;
                lsum[m][1] += p02 + p03 + p12 + p13;
                __nv_bfloat162 t2;
                t2 = __floats2bfloat162_rn(p00, p01); pf[m][0] = *(uint32_t*)&t2;
                t2 = __floats2bfloat162_rn(p02, p03); pf[m][1] = *(uint32_t*)&t2;
                t2 = __floats2bfloat162_rn(p10, p11); pf[m][2] = *(uint32_t*)&t2;
                t2 = __floats2bfloat162_rn(p12, p13); pf[m][3] = *(uint32_t*)&t2;
            }
            #pragma unroll
            for (int db = 0; db < 2; db++) {
                const int vrow = nb16 * 16 + rl + (tl & 1) * 8;
                const int vch  = db * 2 + (tl >> 1);
                const uint32_t va = vb + (uint32_t)(vrow * 64
                                  + ((vch ^ (vrow & 3)) << 4));
                uint32_t vf[4];
                ldsm4t(vf, va);
                #pragma unroll
                for (int m = 0; m < 2; m++) {
                    mma_bf16(o[m][db * 2],     pf[m], &vf[0]);
                    mma_bf16(o[m][db * 2 + 1], pf[m], &vf[2]);
                }
            }
        }

        // prefetch tile t+2 into stage pstg (its readers retired in iter t-1,
        // strictly before this iteration's barrier)
        if (t + 2 < 16) {
            #pragma unroll
            for (int s = 0; s < 4; s++) {
                const int c   = tid + s * 128;
                const int arr = c >> 8;
                const int r   = (c & 255) >> 2, ch = c & 3;
                const uint32_t off = (uint32_t)(r * 64 + ((ch ^ (r & 3)) << 4));
                const uint32_t dst = arr ? (sVb[pstg] + off) : (sKb[pstg] + off);
                const int coff = arr ? voff : koff;
                cp16(dst, QKVh + (long)(b * SEG + (t + 2) * 64 + r) * NQKV
                          + coff + h * DK + ch * 8);
            }
            CP_COMMIT();
        }
        stg  = (stg  == 2) ? 0 : stg  + 1;
        pstg = (pstg == 2) ? 0 : pstg + 1;
    }

    #pragma unroll
    for (int m = 0; m < 2; m++) {
        float l0 = lsum[m][0], l1 = lsum[m][1];
        l0 += __shfl_xor_sync(0xffffffffu, l0, 1);
        l0 += __shfl_xor_sync(0xffffffffu, l0, 2);
        l1 += __shfl_xor_sync(0xffffffffu, l1, 1);
        l1 += __shfl_xor_sync(0xffffffffu, l1, 2);
        const float inv0 = 1.0f / l0;
        const float inv1 = 1.0f / l1;

        const int rloc = q0 + warp * 32 + m * 16 + (lane >> 2);
        const long row0g = (long)(b * 2 * SEG + out_off + rloc) * Dd + h * DK;
        const long row1g = row0g + 8L * Dd;
        #pragma unroll
        for (int db = 0; db < 4; db++) {
            const int col = db * 8 + (lane & 3) * 2;
            *(__nv_bfloat162*)(OutHi + row0g + col)
                = __floats2bfloat162_rn(o[m][db][0] * inv0, o[m][db][1] * inv0);
            *(__nv_bfloat162*)(OutHi + row1g + col)
                = __floats2bfloat162_rn(o[m][db][2] * inv1, o[m][db][3] * inv1);
        }
    }
}

// ---------------------------------------------------------------------------
// Launch
// ---------------------------------------------------------------------------
extern "C" void kernel_launch(void* const* d_in, const int* in_sizes, int n_in,
                              void* d_out, int out_size)
{
    const float* x   = (const float*)d_in[0];
    const float* Wq  = (const float*)d_in[1];
    const float* bq  = (const float*)d_in[2];
    const float* Wk  = (const float*)d_in[3];
    const float* bk  = (const float*)d_in[4];
    const float* Wv  = (const float*)d_in[5];
    const float* bv  = (const float*)d_in[6];
    const float* Wo  = (const float*)d_in[7];
    const float* bo  = (const float*)d_in[8];
    const float* g31 = (const float*)d_in[9];
    const float* b31 = (const float*)d_in[10];
    const float* W1  = (const float*)d_in[11];
    const float* b1  = (const float*)d_in[12];
    const float* W2  = (const float*)d_in[13];
    const float* b2  = (const float*)d_in[14];
    const float* g41 = (const float*)d_in[15];
    const float* b41 = (const float*)d_in[16];
    float* out = (float*)d_out;

    float *pH1, *pbqkv;
    bf16 *xHi, *QKVHi, *AttHi, *H1Hi, *THi;
    bf16 *WqkvT, *WoT, *W1T, *W2T;

    cudaGetSymbolAddress((void**)&pH1, g_H1);
    cudaGetSymbolAddress((void**)&pbqkv, g_bqkv);
    cudaGetSymbolAddress((void**)&xHi,   g_xHi);
    cudaGetSymbolAddress((void**)&QKVHi, g_QKVHi);
    cudaGetSymbolAddress((void**)&AttHi, g_AttHi);
    cudaGetSymbolAddress((void**)&H1Hi,  g_H1Hi);
    cudaGetSymbolAddress((void**)&THi,   g_THi);
    cudaGetSymbolAddress((void**)&WqkvT, g_WqkvT);
    cudaGetSymbolAddress((void**)&WoT, g_WoT);
    cudaGetSymbolAddress((void**)&W1T, g_W1T);
    cudaGetSymbolAddress((void**)&W2T, g_W2T);

    static bool attr_set = false;
    if (!attr_set) {
        cudaFuncSetAttribute(gemm_bf16,
            cudaFuncAttributeMaxDynamicSharedMemorySize, 98304);
        cudaFuncSetAttribute(gemm_ln,
            cudaFuncAttributeMaxDynamicSharedMemorySize, 148480);
        attr_set = true;
    }

    // weight prep + x convert
    transpose_all<<<768, dim3(32, 8)>>>(Wq, Wk, Wv, Wo, W1, W2, bq, bk, bv,
                                        WqkvT, WoT, W1T, W2T, pbqkv);
    cvt_kernel<<<(NROWS_FULL * Dd) / 1024, 256>>>(x, xHi);

    // fused QKV projection (N=768, per-column segment gather)
    gemm_bf16<<<dim3(NROWS_HALF / 128, NQKV / 128), 256, 98304>>>(
        xHi, WqkvT, pbqkv, QKVHi, NQKV, Dd, 1, 0);

    // two-stage cross-segment attention
    attn_tc<<<dim3(SEG / 128, Bb * Hh, 2), 128>>>(QKVHi, AttHi);

    // output projection + residual(x) + LN1 (fused) -> H1 fp32 + bf16
    gemm_ln<<<NROWS_FULL / 128, 512, 148480>>>(
        AttHi, WoT, bo, x, g31, b31, pH1, H1Hi, Dd);

    // W1 + gelu -> T bf16
    gemm_bf16<<<dim3(NROWS_FULL / 128, DFF / 128), 256, 98304>>>(
        H1Hi, W1T, b1, THi, DFF, Dd, 0, 1);

    // W2 + residual(H1) + LN2 (fused) -> out fp32
    gemm_ln<<<NROWS_FULL / 128, 512, 148480>>>(
        THi, W2T, b2, pH1, g41, b41, out, nullptr, DFF);
}

// round 16
// speedup vs baseline: 2.4450x; 1.0811x over previous
#include <cuda_runtime.h>
#include <cuda_bf16.h>
#include <math.h>
#include <stdint.h>

// ---------------------------------------------------------------------------
// TwoStageAttentionLayerCrossSegments  (B=16, TS_D=2, SEG=1024, D=256, H=8,
// DK=32, D_FF=1024)
// All GEMMs single-MMA bf16, BK=64, 3-stage cp.async.
// Wo/W2 GEMMs fuse bias+residual+LayerNorm. Attention: 128 q/block,
// 4 warps x 2 m-tiles, 3-stage K/V ring; K pre-scaled by 1/sqrt(DK)*log2(e)
// so softmax is a bare ex2.
// ---------------------------------------------------------------------------

typedef __nv_bfloat16 bf16;

#define Bb   16
#define SEG  1024
#define Dd   256
#define Hh   8
#define DK   32
#define DFF  1024
#define NROWS_HALF (Bb*SEG)        // 16384
#define NROWS_FULL (Bb*2*SEG)      // 32768
#define NQKV 768
#define KSCALE 0.25503489f         // (1/sqrt(32)) * log2(e)

// fp32 scratch
__device__ float g_H1[NROWS_FULL * Dd];

// bf16 activations
__device__ bf16 g_xHi  [NROWS_FULL * Dd];
__device__ bf16 g_QKVHi[NROWS_HALF * NQKV];
__device__ bf16 g_AttHi[NROWS_FULL * Dd];
__device__ bf16 g_H1Hi [NROWS_FULL * Dd];
__device__ bf16 g_THi  [NROWS_FULL * DFF];

// transposed weights ([N,K] K-major), bf16
__device__ bf16 g_WqkvT[NQKV * Dd];
__device__ bf16 g_WoT[Dd * Dd];
__device__ bf16 g_W1T[DFF * Dd];
__device__ bf16 g_W2T[Dd * DFF];
__device__ float g_bqkv[NQKV];

// ---------------------------------------------------------------------------
// helpers
// ---------------------------------------------------------------------------
__device__ __forceinline__ uint32_t smem_u32(const void* p) {
    uint32_t a;
    asm("{ .reg .u64 t; cvta.to.shared.u64 t, %1; cvt.u32.u64 %0, t; }"
        : "=r"(a) : "l"(p));
    return a;
}

__device__ __forceinline__ float ex2f(float x) {
    float y;
    asm("ex2.approx.ftz.f32 %0, %1;" : "=f"(y) : "f"(x));
    return y;
}

__device__ __forceinline__ void cp16(uint32_t s, const void* g) {
    asm volatile("cp.async.cg.shared.global [%0], [%1], 16;" :: "r"(s), "l"(g));
}
#define CP_COMMIT() asm volatile("cp.async.commit_group;" ::: "memory")
#define CP_WAIT(n)  asm volatile("cp.async.wait_group %0;" :: "n"(n) : "memory")

__device__ __forceinline__ void ldsm4(uint32_t* r, uint32_t addr) {
    asm volatile("ldmatrix.sync.aligned.m8n8.x4.shared.b16 {%0,%1,%2,%3}, [%4];"
        : "=r"(r[0]), "=r"(r[1]), "=r"(r[2]), "=r"(r[3]) : "r"(addr));
}
__device__ __forceinline__ void ldsm4t(uint32_t* r, uint32_t addr) {
    asm volatile("ldmatrix.sync.aligned.m8n8.x4.trans.shared.b16 {%0,%1,%2,%3}, [%4];"
        : "=r"(r[0]), "=r"(r[1]), "=r"(r[2]), "=r"(r[3]) : "r"(addr));
}

__device__ __forceinline__ void mma_bf16(float* d, const uint32_t* a, const uint32_t* b) {
    asm volatile(
        "mma.sync.aligned.m16n8k16.row.col.f32.bf16.bf16.f32 "
        "{%0,%1,%2,%3}, {%4,%5,%6,%7}, {%8,%9}, {%0,%1,%2,%3};"
        : "+f"(d[0]), "+f"(d[1]), "+f"(d[2]), "+f"(d[3])
        : "r"(a[0]), "r"(a[1]), "r"(a[2]), "r"(a[3]), "r"(b[0]), "r"(b[1]));
}

// ---------------------------------------------------------------------------
// fp32 -> bf16 convert
// ---------------------------------------------------------------------------
__global__ void __launch_bounds__(256)
cvt_kernel(const float* __restrict__ X, bf16* __restrict__ Hi)
{
    const long i = ((long)blockIdx.x * 256 + threadIdx.x) * 4;
    float4 v = *(const float4*)(X + i);
    *(__nv_bfloat162*)(Hi + i)     = __floats2bfloat162_rn(v.x, v.y);
    *(__nv_bfloat162*)(Hi + i + 2) = __floats2bfloat162_rn(v.z, v.w);
}

// ---------------------------------------------------------------------------
// All weight transposes (bf16) + QKV bias concat, ONE launch.
// ---------------------------------------------------------------------------
__global__ void __launch_bounds__(256)
transpose_all(const float* __restrict__ Wq, const float* __restrict__ Wk,
              const float* __restrict__ Wv, const float* __restrict__ Wo,
              const float* __restrict__ W1, const float* __restrict__ W2,
              const float* __restrict__ bq, const float* __restrict__ bk,
              const float* __restrict__ bv,
              bf16* __restrict__ dWqkv, bf16* __restrict__ dWo,
              bf16* __restrict__ dW1, bf16* __restrict__ dW2,
              float* __restrict__ dbqkv)
{
    __shared__ float t[32][33];
    const int bid = blockIdx.x;
    const int tix = threadIdx.y * 32 + threadIdx.x;
    if (bid == 0 && tix < 256) {
        dbqkv[tix]       = bq[tix];
        dbqkv[tix + 256] = bk[tix];
        dbqkv[tix + 512] = bv[tix];
    }
    const float* S; bf16* D; int R, Cc, loc;
    if      (bid < 64)  { S = Wq; D = dWqkv;             R = Dd;  Cc = Dd;  loc = bid; }
    else if (bid < 128) { S = Wk; D = dWqkv + 256 * Dd;  R = Dd;  Cc = Dd;  loc = bid - 64; }
    else if (bid < 192) { S = Wv; D = dWqkv + 512 * Dd;  R = Dd;  Cc = Dd;  loc = bid - 128; }
    else if (bid < 256) { S = Wo; D = dWo;               R = Dd;  Cc = Dd;  loc = bid - 192; }
    else if (bid < 512) { S = W1; D = dW1;               R = Dd;  Cc = DFF; loc = bid - 256; }
    else                { S = W2; D = dW2;               R = DFF; Cc = Dd;  loc = bid - 512; }
    const int nbx = Cc / 32;
    const int c0 = (loc % nbx) * 32, r0 = (loc / nbx) * 32;
    #pragma unroll
    for (int i = threadIdx.y; i < 32; i += 8)
        t[i][threadIdx.x] = S[(long)(r0 + i) * Cc + c0 + threadIdx.x];
    __syncthreads();
    #pragma unroll
    for (int i = threadIdx.y; i < 32; i += 8)
        D[(long)(c0 + i) * R + r0 + threadIdx.x]
            = __float2bfloat16(t[threadIdx.x][i]);
}

// ---------------------------------------------------------------------------
// bf16 GEMM (mma.sync m16n8k16): C = bf16(A) @ bf16(W)^T.
// 128x128 tile, BK=64, 8 warps, 3-stage cp.async pipeline.
// gather mode: K-block columns [256,512) get scaled by KSCALE (attention
// score pre-scaling; K is never consumed as V).
// ---------------------------------------------------------------------------
__global__ void __launch_bounds__(256, 2)
gemm_bf16(const bf16* __restrict__ A, const bf16* __restrict__ B,
          const float* __restrict__ bias,
          bf16* __restrict__ Chi,
          int Ntot, int K, int gather, int do_gelu)
{
    extern __shared__ char smem[];
    const uint32_t sb = smem_u32(smem);
    const int tid  = threadIdx.x;
    const int lane = tid & 31, wid = tid >> 5;
    const int wm = wid & 3, wn = wid >> 2;
    const int row0 = blockIdx.x * 128, col0 = blockIdx.y * 128;
    const uint32_t ST = 32768u;
    const float outF = (gather && col0 >= 256 && col0 < 512) ? KSCALE : 1.0f;

    uint32_t dstOff[4];
    long aIdx[4], bIdx[4];
    #pragma unroll
    for (int s = 0; s < 4; s++) {
        const int c  = tid + s * 256;
        const int r  = c >> 3, ch = c & 7;
        dstOff[s] = (uint32_t)(r * 128 + ((ch ^ (r & 7)) << 4));
        const int gA = row0 + r;
        long ar = gA;
        if (gather) {
            const int seg = (col0 >= 256) ? 1024 : 0;
            ar = (long)(gA >> 10) * 2048 + seg + (gA & 1023);
        }
        aIdx[s] = ar * (long)K + ch * 8;
        bIdx[s] = (long)(col0 + r) * K + ch * 8;
    }

    const int CCH = K >> 6;

    #pragma unroll
    for (int pc = 0; pc < 2; pc++) {
        const uint32_t st = sb + (uint32_t)pc * ST;
        const long k0 = (long)pc * 64;
        #pragma unroll
        for (int s = 0; s < 4; s++) {
            cp16(st + 0      + dstOff[s], A + aIdx[s] + k0);
            cp16(st + 16384u + dstOff[s], B + bIdx[s] + k0);
        }
        CP_COMMIT();
    }

    float acc[2][8][4] = {};
    const int rl = lane & 7, tl = lane >> 3;

    int stg = 0, pstg = 2;
    for (int c = 0; c < CCH; c++) {
        if (c + 1 < CCH) { CP_WAIT(1); } else { CP_WAIT(0); }
        __syncthreads();

        const uint32_t base = sb + (uint32_t)stg * ST;
        #pragma unroll
        for (int ks = 0; ks < 4; ks++) {
            uint32_t aH[2][4], bH[4][4];
            #pragma unroll
            for (int i = 0; i < 2; i++) {
                const int arow = wm * 32 + i * 16 + rl + (tl & 1) * 8;
                const int ach  = ks * 2 + (tl >> 1);
                const uint32_t ad = base + (uint32_t)(arow * 128
                                  + ((ach ^ (arow & 7)) << 4));
                ldsm4(aH[i], ad);
            }
            #pragma unroll
            for (int j = 0; j < 4; j++) {
                const int brow = wn * 64 + j * 16 + rl + (tl >> 1) * 8;
                const int bch  = ks * 2 + (tl & 1);
                const uint32_t bd = base + 16384u + (uint32_t)(brow * 128
                                  + ((bch ^ (brow & 7)) << 4));
                ldsm4(bH[j], bd);
            }
            #pragma unroll
            for (int i = 0; i < 2; i++) {
                #pragma unroll
                for (int j = 0; j < 4; j++) {
                    mma_bf16(acc[i][2*j],   aH[i], &bH[j][0]);
                    mma_bf16(acc[i][2*j+1], aH[i], &bH[j][2]);
                }
            }
        }

        if (c + 2 < CCH) {
            const uint32_t st = sb + (uint32_t)pstg * ST;
            const long k0 = (long)(c + 2) * 64;
            #pragma unroll
            for (int s = 0; s < 4; s++) {
                cp16(st + 0      + dstOff[s], A + aIdx[s] + k0);
                cp16(st + 16384u + dstOff[s], B + bIdx[s] + k0);
            }
            CP_COMMIT();
        }
        stg  = (stg  == 2) ? 0 : stg  + 1;
        pstg = (pstg == 2) ? 0 : pstg + 1;
    }

    #pragma unroll
    for (int i = 0; i < 2; i++) {
        const int r_top = row0 + wm * 32 + i * 16 + (lane >> 2);
        #pragma unroll
        for (int j = 0; j < 8; j++) {
            const int col = col0 + wn * 64 + j * 8 + (lane & 3) * 2;
            const float b0 = bias[col], b1 = bias[col + 1];
            float v00 = (acc[i][j][0] + b0) * outF, v01 = (acc[i][j][1] + b1) * outF;
            float v10 = (acc[i][j][2] + b0) * outF, v11 = (acc[i][j][3] + b1) * outF;
            if (do_gelu) {
                v00 = 0.5f * v00 * (1.0f + erff(v00 * 0.70710678118654752f));
                v01 = 0.5f * v01 * (1.0f + erff(v01 * 0.70710678118654752f));
                v10 = 0.5f * v10 * (1.0f + erff(v10 * 0.70710678118654752f));
                v11 = 0.5f * v11 * (1.0f + erff(v11 * 0.70710678118654752f));
            }
            const long o0 = (long)r_top * Ntot + col;
            const long o1 = (long)(r_top + 8) * Ntot + col;
            *(__nv_bfloat162*)(Chi + o0) = __floats2bfloat162_rn(v00, v01);
            *(__nv_bfloat162*)(Chi + o1) = __floats2bfloat162_rn(v10, v11);
        }
    }
}

// ---------------------------------------------------------------------------
// Fused GEMM + bias + residual + LayerNorm.  Tile 128 x 256 (full row),
// 512 threads (16 warps), BK=64, 3-stage pipeline.
// ---------------------------------------------------------------------------
__global__ void __launch_bounds__(512, 1)
gemm_ln(const bf16* __restrict__ A, const bf16* __restrict__ B,
        const float* __restrict__ bias, const float* __restrict__ res,
        const float* __restrict__ g, const float* __restrict__ beta,
        float* __restrict__ Yf, bf16* __restrict__ YHi, int K)
{
    extern __shared__ char smem[];
    const uint32_t sb = smem_u32(smem);
    float* sSum = (float*)(smem + 147456);
    float* sSq  = (float*)(smem + 147456 + 512);

    const int tid  = threadIdx.x;
    const int lane = tid & 31, wid = tid >> 5;
    const int wm = wid & 3, wn = wid >> 2;
    const int row0 = blockIdx.x * 128;
    const uint32_t ST = 49152u;

    uint32_t aOff[2]; long aIdx[2];
    #pragma unroll
    for (int s = 0; s < 2; s++) {
        const int c = tid + s * 512;
        const int r = c >> 3, ch = c & 7;
        aOff[s] = (uint32_t)(r * 128 + ((ch ^ (r & 7)) << 4));
        aIdx[s] = (long)(row0 + r) * K + ch * 8;
    }
    uint32_t bOff[4]; long bIdx[4];
    #pragma unroll
    for (int s = 0; s < 4; s++) {
        const int c = tid + s * 512;
        const int r = c >> 3, ch = c & 7;
        bOff[s] = 16384u + (uint32_t)(r * 128 + ((ch ^ (r & 7)) << 4));
        bIdx[s] = (long)r * K + ch * 8;
    }

    const int CCH = K >> 6;

    #pragma unroll
    for (int pc = 0; pc < 2; pc++) {
        const uint32_t st = sb + (uint32_t)pc * ST;
        const long k0 = (long)pc * 64;
        #pragma unroll
        for (int s = 0; s < 2; s++) cp16(st + aOff[s], A + aIdx[s] + k0);
        #pragma unroll
        for (int s = 0; s < 4; s++) cp16(st + bOff[s], B + bIdx[s] + k0);
        CP_COMMIT();
    }

    if (tid < 128) { sSum[tid] = 0.0f; sSq[tid] = 0.0f; }

    float acc[2][8][4] = {};
    const int rl = lane & 7, tl = lane >> 3;

    int stg = 0, pstg = 2;
    for (int c = 0; c < CCH; c++) {
        if (c + 1 < CCH) { CP_WAIT(1); } else { CP_WAIT(0); }
        __syncthreads();

        const uint32_t base = sb + (uint32_t)stg * ST;
        #pragma unroll
        for (int ks = 0; ks < 4; ks++) {
            uint32_t aH[2][4], bH[4][4];
            #pragma unroll
            for (int i = 0; i < 2; i++) {
                const int arow = wm * 32 + i * 16 + rl + (tl & 1) * 8;
                const int ach  = ks * 2 + (tl >> 1);
                const uint32_t ad = base + (uint32_t)(arow * 128
                                  + ((ach ^ (arow & 7)) << 4));
                ldsm4(aH[i], ad);
            }
            #pragma unroll
            for (int j = 0; j < 4; j++) {
                const int brow = wn * 64 + j * 16 + rl + (tl >> 1) * 8;
                const int bch  = ks * 2 + (tl & 1);
                const uint32_t bd = base + 16384u + (uint32_t)(brow * 128
                                  + ((bch ^ (brow & 7)) << 4));
                ldsm4(bH[j], bd);
            }
            #pragma unroll
            for (int i = 0; i < 2; i++) {
                #pragma unroll
                for (int j = 0; j < 4; j++) {
                    mma_bf16(acc[i][2*j],   aH[i], &bH[j][0]);
                    mma_bf16(acc[i][2*j+1], aH[i], &bH[j][2]);
                }
            }
        }

        if (c + 2 < CCH) {
            const uint32_t st = sb + (uint32_t)pstg * ST;
            const long k0 = (long)(c + 2) * 64;
            #pragma unroll
            for (int s = 0; s < 2; s++) cp16(st + aOff[s], A + aIdx[s] + k0);
            #pragma unroll
            for (int s = 0; s < 4; s++) cp16(st + bOff[s], B + bIdx[s] + k0);
            CP_COMMIT();
        }
        stg  = (stg  == 2) ? 0 : stg  + 1;
        pstg = (pstg == 2) ? 0 : pstg + 1;
    }

    __syncthreads();

    #pragma unroll
    for (int i = 0; i < 2; i++) {
        const int rloc0 = wm * 32 + i * 16 + (lane >> 2);
        float s0 = 0.0f, q0 = 0.0f, s1 = 0.0f, q1 = 0.0f;
        #pragma unroll
        for (int j = 0; j < 8; j++) {
            const int col = wn * 64 + j * 8 + (lane & 3) * 2;
            const float b0 = bias[col], b1 = bias[col + 1];
            const long o0 = (long)(row0 + rloc0) * Dd + col;
            const long o1 = o0 + 8L * Dd;
            float v00 = acc[i][j][0] + b0 + res[o0];
            float v01 = acc[i][j][1] + b1 + res[o0 + 1];
            float v10 = acc[i][j][2] + b0 + res[o1];
            float v11 = acc[i][j][3] + b1 + res[o1 + 1];
            acc[i][j][0] = v00; acc[i][j][1] = v01;
            acc[i][j][2] = v10; acc[i][j][3] = v11;
            s0 += v00 + v01;          q0 += v00 * v00 + v01 * v01;
            s1 += v10 + v11;          q1 += v10 * v10 + v11 * v11;
        }
        #pragma unroll
        for (int o = 1; o <= 2; o <<= 1) {
            s0 += __shfl_xor_sync(0xffffffffu, s0, o);
            q0 += __shfl_xor_sync(0xffffffffu, q0, o);
            s1 += __shfl_xor_sync(0xffffffffu, s1, o);
            q1 += __shfl_xor_sync(0xffffffffu, q1, o);
        }
        if ((lane & 3) == 0) {
            atomicAdd(&sSum[rloc0], s0);     atomicAdd(&sSq[rloc0], q0);
            atomicAdd(&sSum[rloc0 + 8], s1); atomicAdd(&sSq[rloc0 + 8], q1);
        }
    }
    __syncthreads();

    #pragma unroll
    for (int i = 0; i < 2; i++) {
        const int rloc0 = wm * 32 + i * 16 + (lane >> 2);
        const float mu0  = sSum[rloc0] * (1.0f / 256.0f);
        const float var0 = sSq[rloc0] * (1.0f / 256.0f) - mu0 * mu0;
        const float in0  = rsqrtf(var0 + 1e-5f);
        const float mu1  = sSum[rloc0 + 8] * (1.0f / 256.0f);
        const float var1 = sSq[rloc0 + 8] * (1.0f / 256.0f) - mu1 * mu1;
        const float in1  = rsqrtf(var1 + 1e-5f);
        #pragma unroll
        for (int j = 0; j < 8; j++) {
            const int col = wn * 64 + j * 8 + (lane & 3) * 2;
            const float g0 = g[col], g1 = g[col + 1];
            const float e0 = beta[col], e1 = beta[col + 1];
            const long o0 = (long)(row0 + rloc0) * Dd + col;
            const long o1 = o0 + 8L * Dd;
            float y00 = (acc[i][j][0] - mu0) * in0 * g0 + e0;
            float y01 = (acc[i][j][1] - mu0) * in0 * g1 + e1;
            float y10 = (acc[i][j][2] - mu1) * in1 * g0 + e0;
            float y11 = (acc[i][j][3] - mu1) * in1 * g1 + e1;
            *(float2*)(Yf + o0) = make_float2(y00, y01);
            *(float2*)(Yf + o1) = make_float2(y10, y11);
            if (YHi) {
                *(__nv_bfloat162*)(YHi + o0) = __floats2bfloat162_rn(y00, y01);
                *(__nv_bfloat162*)(YHi + o1) = __floats2bfloat162_rn(y10, y11);
            }
        }
    }
}

// ---------------------------------------------------------------------------
// Tensor-core flash attention: 128 queries/block, 4 warps x 2 m-tiles,
// 3-stage K/V ring, one barrier/tile. K pre-scaled -> softmax is bare ex2.
// Running global pointers for prefetch (no per-tile 64-bit muls).
// ---------------------------------------------------------------------------
__global__ void __launch_bounds__(128, 4)
attn_tc(const bf16* __restrict__ QKVh, bf16* __restrict__ OutHi)
{
    __shared__ bf16 sQ[4096];            // 128 rows hi (8 KB)
    __shared__ bf16 sK[3][2048];         // 3-stage     (12 KB)
    __shared__ bf16 sV[3][2048];         //             (12 KB)

    const int stage = blockIdx.z;
    const int qoff = stage ? 256 : 0;
    const int koff = stage ? 0 : 256;
    const int voff = stage ? 0 : 512;
    const int out_off = stage ? SEG : 0;

    const int bh = blockIdx.y;
    const int b  = bh >> 3;
    const int h  = bh & 7;
    const int q0 = blockIdx.x * 128;

    const int tid  = threadIdx.x;
    const int lane = tid & 31, warp = tid >> 5;
    const int rl = lane & 7, tl = lane >> 3;

    const uint32_t sQb = smem_u32(sQ);
    const uint32_t sKb[3] = { smem_u32(sK[0]), smem_u32(sK[1]), smem_u32(sK[2]) };
    const uint32_t sVb[3] = { smem_u32(sV[0]), smem_u32(sV[1]), smem_u32(sV[2]) };

    // --- load Q (group 0) ---
    #pragma unroll
    for (int s = 0; s < 4; s++) {
        const int c = tid + s * 128;
        const int r = c >> 2, ch = c & 3;
        const uint32_t dst = sQb + (uint32_t)(r * 64 + ((ch ^ (r & 3)) << 4));
        cp16(dst, QKVh + (long)(b * SEG + q0 + r) * NQKV + qoff + h * DK + ch * 8);
    }
    CP_COMMIT();

    // per-slot running pointers + smem offsets for K/V tiles
    const bf16* kvPtr[4];
    uint32_t kvOff[4];
    int kvArr[4];
    #pragma unroll
    for (int s = 0; s < 4; s++) {
        const int c   = tid + s * 128;
        const int arr = c >> 8;                 // 0 K, 1 V
        const int r   = (c & 255) >> 2, ch = c & 3;
        kvArr[s] = arr;
        kvOff[s] = (uint32_t)(r * 64 + ((ch ^ (r & 3)) << 4));
        const int coff = arr ? voff : koff;
        kvPtr[s] = QKVh + (long)(b * SEG + r) * NQKV + coff + h * DK + ch * 8;
    }
    const long TILE_STRIDE = 64L * NQKV;

    // --- prefetch key tiles 0 and 1 ---
    #pragma unroll
    for (int pc = 0; pc < 2; pc++) {
        #pragma unroll
        for (int s = 0; s < 4; s++) {
            const uint32_t dst = (kvArr[s] ? sVb[pc] : sKb[pc]) + kvOff[s];
            cp16(dst, kvPtr[s]);
            kvPtr[s] += TILE_STRIDE;
        }
        CP_COMMIT();
    }

    CP_WAIT(2);
    __syncthreads();
    uint32_t qh[2][2][4];                      // [m][ks]
    #pragma unroll
    for (int m = 0; m < 2; m++) {
        #pragma unroll
        for (int ks = 0; ks < 2; ks++) {
            const int arow = warp * 32 + m * 16 + rl + (tl & 1) * 8;
            const int ach  = ks * 2 + (tl >> 1);
            const uint32_t ad = sQb + (uint32_t)(arow * 64
                              + ((ach ^ (arow & 3)) << 4));
            ldsm4(qh[m][ks], ad);
        }
    }

    float o[2][4][4] = {};
    float lsum[2][2] = {};

    int stg = 0, pstg = 2;
    for (int t = 0; t < 16; t++) {
        if (t + 1 < 16) { CP_WAIT(1); } else { CP_WAIT(0); }
        __syncthreads();

        const uint32_t kb = sKb[stg], vb = sVb[stg];
        #pragma unroll
        for (int nb16 = 0; nb16 < 4; nb16++) {
            float s2[2][2][4] = {};
            #pragma unroll
            for (int ks = 0; ks < 2; ks++) {
                const int krow = nb16 * 16 + rl + (tl >> 1) * 8;
                const int kch  = ks * 2 + (tl & 1);
                const uint32_t ka = kb + (uint32_t)(krow * 64
                                  + ((kch ^ (krow & 3)) << 4));
                uint32_t kh[4];
                ldsm4(kh, ka);
                #pragma unroll
                for (int m = 0; m < 2; m++) {
                    mma_bf16(s2[m][0], qh[m][ks], &kh[0]);
                    mma_bf16(s2[m][1], qh[m][ks], &kh[2]);
                }
            }
            uint32_t pf[2][4];
            #pragma unroll
            for (int m = 0; m < 2; m++) {
                // scores already carry scale*log2e (baked into K)
                float p00 = ex2f(s2[m][0][0]), p01 = ex2f(s2[m][0][1]);
                float p02 = ex2f(s2[m][0][2]), p03 = ex2f(s2[m][0][3]);
                float p10 = ex2f(s2[m][1][0]), p11 = ex2f(s2[m][1][1]);
                float p12 = ex2f(s2[m][1][2]), p13 = ex2f(s2[m][1][3]);
                lsum[m][0] += p00 + p01 + p10 + p11;
                lsum[m][1] += p02 + p03 + p12 + p13;
                __nv_bfloat162 t2;
                t2 = __floats2bfloat162_rn(p00, p01); pf[m][0] = *(uint32_t*)&t2;
                t2 = __floats2bfloat162_rn(p02, p03); pf[m][1] = *(uint32_t*)&t2;
                t2 = __floats2bfloat162_rn(p10, p11); pf[m][2] = *(uint32_t*)&t2;
                t2 = __floats2bfloat162_rn(p12, p13); pf[m][3] = *(uint32_t*)&t2;
            }
            #pragma unroll
            for (int db = 0; db < 2; db++) {
                const int vrow = nb16 * 16 + rl + (tl & 1) * 8;
                const int vch  = db * 2 + (tl >> 1);
                const uint32_t va = vb + (uint32_t)(vrow * 64
                                  + ((vch ^ (vrow & 3)) << 4));
                uint32_t vf[4];
                ldsm4t(vf, va);
                #pragma unroll
                for (int m = 0; m < 2; m++) {
                    mma_bf16(o[m][db * 2],     pf[m], &vf[0]);
                    mma_bf16(o[m][db * 2 + 1], pf[m], &vf[2]);
                }
            }
        }

        if (t + 2 < 16) {
            #pragma unroll
            for (int s = 0; s < 4; s++) {
                const uint32_t dst = (kvArr[s] ? sVb[pstg] : sKb[pstg]) + kvOff[s];
                cp16(dst, kvPtr[s]);
                kvPtr[s] += TILE_STRIDE;
            }
            CP_COMMIT();
        }
        stg  = (stg  == 2) ? 0 : stg  + 1;
        pstg = (pstg == 2) ? 0 : pstg + 1;
    }

    #pragma unroll
    for (int m = 0; m < 2; m++) {
        float l0 = lsum[m][0], l1 = lsum[m][1];
        l0 += __shfl_xor_sync(0xffffffffu, l0, 1);
        l0 += __shfl_xor_sync(0xffffffffu, l0, 2);
        l1 += __shfl_xor_sync(0xffffffffu, l1, 1);
        l1 += __shfl_xor_sync(0xffffffffu, l1, 2);
        const float inv0 = 1.0f / l0;
        const float inv1 = 1.0f / l1;

        const int rloc = q0 + warp * 32 + m * 16 + (lane >> 2);
        const long row0g = (long)(b * 2 * SEG + out_off + rloc) * Dd + h * DK;
        const long row1g = row0g + 8L * Dd;
        #pragma unroll
        for (int db = 0; db < 4; db++) {
            const int col = db * 8 + (lane & 3) * 2;
            *(__nv_bfloat162*)(OutHi + row0g + col)
                = __floats2bfloat162_rn(o[m][db][0] * inv0, o[m][db][1] * inv0);
            *(__nv_bfloat162*)(OutHi + row1g + col)
                = __floats2bfloat162_rn(o[m][db][2] * inv1, o[m][db][3] * inv1);
        }
    }
}

// ---------------------------------------------------------------------------
// Launch
// ---------------------------------------------------------------------------
extern "C" void kernel_launch(void* const* d_in, const int* in_sizes, int n_in,
                              void* d_out, int out_size)
{
    const float* x   = (const float*)d_in[0];
    const float* Wq  = (const float*)d_in[1];
    const float* bq  = (const float*)d_in[2];
    const float* Wk  = (const float*)d_in[3];
    const float* bk  = (const float*)d_in[4];
    const float* Wv  = (const float*)d_in[5];
    const float* bv  = (const float*)d_in[6];
    const float* Wo  = (const float*)d_in[7];
    const float* bo  = (const float*)d_in[8];
    const float* g31 = (const float*)d_in[9];
    const float* b31 = (const float*)d_in[10];
    const float* W1  = (const float*)d_in[11];
    const float* b1  = (const float*)d_in[12];
    const float* W2  = (const float*)d_in[13];
    const float* b2  = (const float*)d_in[14];
    const float* g41 = (const float*)d_in[15];
    const float* b41 = (const float*)d_in[16];
    float* out = (float*)d_out;

    float *pH1, *pbqkv;
    bf16 *xHi, *QKVHi, *AttHi, *H1Hi, *THi;
    bf16 *WqkvT, *WoT, *W1T, *W2T;

    cudaGetSymbolAddress((void**)&pH1, g_H1);
    cudaGetSymbolAddress((void**)&pbqkv, g_bqkv);
    cudaGetSymbolAddress((void**)&xHi,   g_xHi);
    cudaGetSymbolAddress((void**)&QKVHi, g_QKVHi);
    cudaGetSymbolAddress((void**)&AttHi, g_AttHi);
    cudaGetSymbolAddress((void**)&H1Hi,  g_H1Hi);
    cudaGetSymbolAddress((void**)&THi,   g_THi);
    cudaGetSymbolAddress((void**)&WqkvT, g_WqkvT);
    cudaGetSymbolAddress((void**)&WoT, g_WoT);
    cudaGetSymbolAddress((void**)&W1T, g_W1T);
    cudaGetSymbolAddress((void**)&W2T, g_W2T);

    static bool attr_set = false;
    if (!attr_set) {
        cudaFuncSetAttribute(gemm_bf16,
            cudaFuncAttributeMaxDynamicSharedMemorySize, 98304);
        cudaFuncSetAttribute(gemm_ln,
            cudaFuncAttributeMaxDynamicSharedMemorySize, 148480);
        attr_set = true;
    }

    // weight prep + x convert
    transpose_all<<<768, dim3(32, 8)>>>(Wq, Wk, Wv, Wo, W1, W2, bq, bk, bv,
                                        WqkvT, WoT, W1T, W2T, pbqkv);
    cvt_kernel<<<(NROWS_FULL * Dd) / 1024, 256>>>(x, xHi);

    // fused QKV projection (K block scaled by KSCALE in epilogue)
    gemm_bf16<<<dim3(NROWS_HALF / 128, NQKV / 128), 256, 98304>>>(
        xHi, WqkvT, pbqkv, QKVHi, NQKV, Dd, 1, 0);

    // two-stage cross-segment attention
    attn_tc<<<dim3(SEG / 128, Bb * Hh, 2), 128>>>(QKVHi, AttHi);

    // output projection + residual(x) + LN1 (fused) -> H1 fp32 + bf16
    gemm_ln<<<NROWS_FULL / 128, 512, 148480>>>(
        AttHi, WoT, bo, x, g31, b31, pH1, H1Hi, Dd);

    // W1 + gelu -> T bf16
    gemm_bf16<<<dim3(NROWS_FULL / 128, DFF / 128), 256, 98304>>>(
        H1Hi, W1T, b1, THi, DFF, Dd, 0, 1);

    // W2 + residual(H1) + LN2 (fused) -> out fp32
    gemm_ln<<<NROWS_FULL / 128, 512, 148480>>>(
        THi, W2T, b2, pH1, g41, b41, out, nullptr, DFF);
}

// round 17
// speedup vs baseline: 2.4476x; 1.0011x over previous
#include <cuda_runtime.h>
#include <cuda_bf16.h>
#include <math.h>
#include <stdint.h>

// ---------------------------------------------------------------------------
// TwoStageAttentionLayerCrossSegments  (B=16, TS_D=2, SEG=1024, D=256, H=8,
// DK=32, D_FF=1024)
// All GEMMs single-MMA bf16, BK=64. Wo/W2 GEMMs fuse bias+residual+LN with
// 64-row tiles (2 CTAs/SM, single wave). Attention: 128 q/block, 4 warps x
// 2 m-tiles, 3-stage K/V ring; K pre-scaled by 1/sqrt(DK)*log2(e) -> bare ex2.
// ---------------------------------------------------------------------------

typedef __nv_bfloat16 bf16;

#define Bb   16
#define SEG  1024
#define Dd   256
#define Hh   8
#define DK   32
#define DFF  1024
#define NROWS_HALF (Bb*SEG)        // 16384
#define NROWS_FULL (Bb*2*SEG)      // 32768
#define NQKV 768
#define KSCALE 0.25503489f         // (1/sqrt(32)) * log2(e)

// fp32 scratch
__device__ float g_H1[NROWS_FULL * Dd];

// bf16 activations
__device__ bf16 g_xHi  [NROWS_FULL * Dd];
__device__ bf16 g_QKVHi[NROWS_HALF * NQKV];
__device__ bf16 g_AttHi[NROWS_FULL * Dd];
__device__ bf16 g_H1Hi [NROWS_FULL * Dd];
__device__ bf16 g_THi  [NROWS_FULL * DFF];

// transposed weights ([N,K] K-major), bf16
__device__ bf16 g_WqkvT[NQKV * Dd];
__device__ bf16 g_WoT[Dd * Dd];
__device__ bf16 g_W1T[DFF * Dd];
__device__ bf16 g_W2T[Dd * DFF];
__device__ float g_bqkv[NQKV];

// ---------------------------------------------------------------------------
// helpers
// ---------------------------------------------------------------------------
__device__ __forceinline__ uint32_t smem_u32(const void* p) {
    uint32_t a;
    asm("{ .reg .u64 t; cvta.to.shared.u64 t, %1; cvt.u32.u64 %0, t; }"
        : "=r"(a) : "l"(p));
    return a;
}

__device__ __forceinline__ float ex2f(float x) {
    float y;
    asm("ex2.approx.ftz.f32 %0, %1;" : "=f"(y) : "f"(x));
    return y;
}

__device__ __forceinline__ void cp16(uint32_t s, const void* g) {
    asm volatile("cp.async.cg.shared.global [%0], [%1], 16;" :: "r"(s), "l"(g));
}
#define CP_COMMIT() asm volatile("cp.async.commit_group;" ::: "memory")
#define CP_WAIT(n)  asm volatile("cp.async.wait_group %0;" :: "n"(n) : "memory")

__device__ __forceinline__ void ldsm4(uint32_t* r, uint32_t addr) {
    asm volatile("ldmatrix.sync.aligned.m8n8.x4.shared.b16 {%0,%1,%2,%3}, [%4];"
        : "=r"(r[0]), "=r"(r[1]), "=r"(r[2]), "=r"(r[3]) : "r"(addr));
}
__device__ __forceinline__ void ldsm4t(uint32_t* r, uint32_t addr) {
    asm volatile("ldmatrix.sync.aligned.m8n8.x4.trans.shared.b16 {%0,%1,%2,%3}, [%4];"
        : "=r"(r[0]), "=r"(r[1]), "=r"(r[2]), "=r"(r[3]) : "r"(addr));
}

__device__ __forceinline__ void mma_bf16(float* d, const uint32_t* a, const uint32_t* b) {
    asm volatile(
        "mma.sync.aligned.m16n8k16.row.col.f32.bf16.bf16.f32 "
        "{%0,%1,%2,%3}, {%4,%5,%6,%7}, {%8,%9}, {%0,%1,%2,%3};"
        : "+f"(d[0]), "+f"(d[1]), "+f"(d[2]), "+f"(d[3])
        : "r"(a[0]), "r"(a[1]), "r"(a[2]), "r"(a[3]), "r"(b[0]), "r"(b[1]));
}

// ---------------------------------------------------------------------------
// fp32 -> bf16 convert
// ---------------------------------------------------------------------------
__global__ void __launch_bounds__(256)
cvt_kernel(const float* __restrict__ X, bf16* __restrict__ Hi)
{
    const long i = ((long)blockIdx.x * 256 + threadIdx.x) * 4;
    float4 v = *(const float4*)(X + i);
    *(__nv_bfloat162*)(Hi + i)     = __floats2bfloat162_rn(v.x, v.y);
    *(__nv_bfloat162*)(Hi + i + 2) = __floats2bfloat162_rn(v.z, v.w);
}

// ---------------------------------------------------------------------------
// All weight transposes (bf16) + QKV bias concat, ONE launch.
// ---------------------------------------------------------------------------
__global__ void __launch_bounds__(256)
transpose_all(const float* __restrict__ Wq, const float* __restrict__ Wk,
              const float* __restrict__ Wv, const float* __restrict__ Wo,
              const float* __restrict__ W1, const float* __restrict__ W2,
              const float* __restrict__ bq, const float* __restrict__ bk,
              const float* __restrict__ bv,
              bf16* __restrict__ dWqkv, bf16* __restrict__ dWo,
              bf16* __restrict__ dW1, bf16* __restrict__ dW2,
              float* __restrict__ dbqkv)
{
    __shared__ float t[32][33];
    const int bid = blockIdx.x;
    const int tix = threadIdx.y * 32 + threadIdx.x;
    if (bid == 0 && tix < 256) {
        dbqkv[tix]       = bq[tix];
        dbqkv[tix + 256] = bk[tix];
        dbqkv[tix + 512] = bv[tix];
    }
    const float* S; bf16* D; int R, Cc, loc;
    if      (bid < 64)  { S = Wq; D = dWqkv;             R = Dd;  Cc = Dd;  loc = bid; }
    else if (bid < 128) { S = Wk; D = dWqkv + 256 * Dd;  R = Dd;  Cc = Dd;  loc = bid - 64; }
    else if (bid < 192) { S = Wv; D = dWqkv + 512 * Dd;  R = Dd;  Cc = Dd;  loc = bid - 128; }
    else if (bid < 256) { S = Wo; D = dWo;               R = Dd;  Cc = Dd;  loc = bid - 192; }
    else if (bid < 512) { S = W1; D = dW1;               R = Dd;  Cc = DFF; loc = bid - 256; }
    else                { S = W2; D = dW2;               R = DFF; Cc = Dd;  loc = bid - 512; }
    const int nbx = Cc / 32;
    const int c0 = (loc % nbx) * 32, r0 = (loc / nbx) * 32;
    #pragma unroll
    for (int i = threadIdx.y; i < 32; i += 8)
        t[i][threadIdx.x] = S[(long)(r0 + i) * Cc + c0 + threadIdx.x];
    __syncthreads();
    #pragma unroll
    for (int i = threadIdx.y; i < 32; i += 8)
        D[(long)(c0 + i) * R + r0 + threadIdx.x]
            = __float2bfloat16(t[threadIdx.x][i]);
}

// ---------------------------------------------------------------------------
// bf16 GEMM (mma.sync m16n8k16): C = bf16(A) @ bf16(W)^T.
// 128x128 tile, BK=64, 8 warps, 3-stage cp.async pipeline.
// gather mode: K-block columns [256,512) scaled by KSCALE.
// ---------------------------------------------------------------------------
__global__ void __launch_bounds__(256, 2)
gemm_bf16(const bf16* __restrict__ A, const bf16* __restrict__ B,
          const float* __restrict__ bias,
          bf16* __restrict__ Chi,
          int Ntot, int K, int gather, int do_gelu)
{
    extern __shared__ char smem[];
    const uint32_t sb = smem_u32(smem);
    const int tid  = threadIdx.x;
    const int lane = tid & 31, wid = tid >> 5;
    const int wm = wid & 3, wn = wid >> 2;
    const int row0 = blockIdx.x * 128, col0 = blockIdx.y * 128;
    const uint32_t ST = 32768u;
    const float outF = (gather && col0 >= 256 && col0 < 512) ? KSCALE : 1.0f;

    uint32_t dstOff[4];
    long aIdx[4], bIdx[4];
    #pragma unroll
    for (int s = 0; s < 4; s++) {
        const int c  = tid + s * 256;
        const int r  = c >> 3, ch = c & 7;
        dstOff[s] = (uint32_t)(r * 128 + ((ch ^ (r & 7)) << 4));
        const int gA = row0 + r;
        long ar = gA;
        if (gather) {
            const int seg = (col0 >= 256) ? 1024 : 0;
            ar = (long)(gA >> 10) * 2048 + seg + (gA & 1023);
        }
        aIdx[s] = ar * (long)K + ch * 8;
        bIdx[s] = (long)(col0 + r) * K + ch * 8;
    }

    const int CCH = K >> 6;

    #pragma unroll
    for (int pc = 0; pc < 2; pc++) {
        const uint32_t st = sb + (uint32_t)pc * ST;
        const long k0 = (long)pc * 64;
        #pragma unroll
        for (int s = 0; s < 4; s++) {
            cp16(st + 0      + dstOff[s], A + aIdx[s] + k0);
            cp16(st + 16384u + dstOff[s], B + bIdx[s] + k0);
        }
        CP_COMMIT();
    }

    float acc[2][8][4] = {};
    const int rl = lane & 7, tl = lane >> 3;

    int stg = 0, pstg = 2;
    for (int c = 0; c < CCH; c++) {
        if (c + 1 < CCH) { CP_WAIT(1); } else { CP_WAIT(0); }
        __syncthreads();

        const uint32_t base = sb + (uint32_t)stg * ST;
        #pragma unroll
        for (int ks = 0; ks < 4; ks++) {
            uint32_t aH[2][4], bH[4][4];
            #pragma unroll
            for (int i = 0; i < 2; i++) {
                const int arow = wm * 32 + i * 16 + rl + (tl & 1) * 8;
                const int ach  = ks * 2 + (tl >> 1);
                const uint32_t ad = base + (uint32_t)(arow * 128
                                  + ((ach ^ (arow & 7)) << 4));
                ldsm4(aH[i], ad);
            }
            #pragma unroll
            for (int j = 0; j < 4; j++) {
                const int brow = wn * 64 + j * 16 + rl + (tl >> 1) * 8;
                const int bch  = ks * 2 + (tl & 1);
                const uint32_t bd = base + 16384u + (uint32_t)(brow * 128
                                  + ((bch ^ (brow & 7)) << 4));
                ldsm4(bH[j], bd);
            }
            #pragma unroll
            for (int i = 0; i < 2; i++) {
                #pragma unroll
                for (int j = 0; j < 4; j++) {
                    mma_bf16(acc[i][2*j],   aH[i], &bH[j][0]);
                    mma_bf16(acc[i][2*j+1], aH[i], &bH[j][2]);
                }
            }
        }

        if (c + 2 < CCH) {
            const uint32_t st = sb + (uint32_t)pstg * ST;
            const long k0 = (long)(c + 2) * 64;
            #pragma unroll
            for (int s = 0; s < 4; s++) {
                cp16(st + 0      + dstOff[s], A + aIdx[s] + k0);
                cp16(st + 16384u + dstOff[s], B + bIdx[s] + k0);
            }
            CP_COMMIT();
        }
        stg  = (stg  == 2) ? 0 : stg  + 1;
        pstg = (pstg == 2) ? 0 : pstg + 1;
    }

    #pragma unroll
    for (int i = 0; i < 2; i++) {
        const int r_top = row0 + wm * 32 + i * 16 + (lane >> 2);
        #pragma unroll
        for (int j = 0; j < 8; j++) {
            const int col = col0 + wn * 64 + j * 8 + (lane & 3) * 2;
            const float b0 = bias[col], b1 = bias[col + 1];
            float v00 = (acc[i][j][0] + b0) * outF, v01 = (acc[i][j][1] + b1) * outF;
            float v10 = (acc[i][j][2] + b0) * outF, v11 = (acc[i][j][3] + b1) * outF;
            if (do_gelu) {
                v00 = 0.5f * v00 * (1.0f + erff(v00 * 0.70710678118654752f));
                v01 = 0.5f * v01 * (1.0f + erff(v01 * 0.70710678118654752f));
                v10 = 0.5f * v10 * (1.0f + erff(v10 * 0.70710678118654752f));
                v11 = 0.5f * v11 * (1.0f + erff(v11 * 0.70710678118654752f));
            }
            const long o0 = (long)r_top * Ntot + col;
            const long o1 = (long)(r_top + 8) * Ntot + col;
            *(__nv_bfloat162*)(Chi + o0) = __floats2bfloat162_rn(v00, v01);
            *(__nv_bfloat162*)(Chi + o1) = __floats2bfloat162_rn(v10, v11);
        }
    }
}

// ---------------------------------------------------------------------------
// Fused GEMM + bias + residual + LayerNorm.  Tile 64 x 256 (full row),
// 256 threads (8 warps: wm 0..1 x wn 0..3), BK=64, 2-stage pipeline,
// 2 CTAs/SM.  Y = LN(A @ B^T + bias + res; g, beta) -> Yf fp32 [, YHi bf16].
// smem: 2 stages x 40960 (A 8KB + B 32KB) + LN sums (512B) = 82432.
// ---------------------------------------------------------------------------
__global__ void __launch_bounds__(256, 2)
gemm_ln(const bf16* __restrict__ A, const bf16* __restrict__ B,
        const float* __restrict__ bias, const float* __restrict__ res,
        const float* __restrict__ g, const float* __restrict__ beta,
        float* __restrict__ Yf, bf16* __restrict__ YHi, int K)
{
    extern __shared__ char smem[];
    const uint32_t sb = smem_u32(smem);
    float* sSum = (float*)(smem + 81920);
    float* sSq  = (float*)(smem + 81920 + 256);

    const int tid  = threadIdx.x;
    const int lane = tid & 31, wid = tid >> 5;
    const int wm = wid & 1, wn = wid >> 1;
    const int row0 = blockIdx.x * 64;
    const uint32_t ST = 40960u;

    // loaders: A 512 chunks / 256 thr = 2 slots; B 2048 / 256 = 8 slots
    uint32_t aOff[2]; long aIdx[2];
    #pragma unroll
    for (int s = 0; s < 2; s++) {
        const int c = tid + s * 256;
        const int r = c >> 3, ch = c & 7;
        aOff[s] = (uint32_t)(r * 128 + ((ch ^ (r & 7)) << 4));
        aIdx[s] = (long)(row0 + r) * K + ch * 8;
    }
    uint32_t bOff[8]; long bIdx[8];
    #pragma unroll
    for (int s = 0; s < 8; s++) {
        const int c = tid + s * 256;
        const int r = c >> 3, ch = c & 7;
        bOff[s] = 8192u + (uint32_t)(r * 128 + ((ch ^ (r & 7)) << 4));
        bIdx[s] = (long)r * K + ch * 8;
    }

    const int CCH = K >> 6;

    // prologue: chunk 0 -> stage 0
    #pragma unroll
    for (int s = 0; s < 2; s++) cp16(sb + aOff[s], A + aIdx[s]);
    #pragma unroll
    for (int s = 0; s < 8; s++) cp16(sb + bOff[s], B + bIdx[s]);
    CP_COMMIT();

    if (tid < 64) { sSum[tid] = 0.0f; sSq[tid] = 0.0f; }

    float acc[2][8][4] = {};
    const int rl = lane & 7, tl = lane >> 3;

    for (int c = 0; c < CCH; c++) {
        if (c + 1 < CCH) {
            const uint32_t st = sb + (uint32_t)((c + 1) & 1) * ST;
            const long k0 = (long)(c + 1) * 64;
            #pragma unroll
            for (int s = 0; s < 2; s++) cp16(st + aOff[s], A + aIdx[s] + k0);
            #pragma unroll
            for (int s = 0; s < 8; s++) cp16(st + bOff[s], B + bIdx[s] + k0);
            CP_COMMIT();
            CP_WAIT(1);
        } else {
            CP_WAIT(0);
        }
        __syncthreads();

        const uint32_t base = sb + (uint32_t)(c & 1) * ST;
        #pragma unroll
        for (int ks = 0; ks < 4; ks++) {
            uint32_t aH[2][4], bH[4][4];
            #pragma unroll
            for (int i = 0; i < 2; i++) {
                const int arow = wm * 32 + i * 16 + rl + (tl & 1) * 8;
                const int ach  = ks * 2 + (tl >> 1);
                const uint32_t ad = base + (uint32_t)(arow * 128
                                  + ((ach ^ (arow & 7)) << 4));
                ldsm4(aH[i], ad);
            }
            #pragma unroll
            for (int j = 0; j < 4; j++) {
                const int brow = wn * 64 + j * 16 + rl + (tl >> 1) * 8;
                const int bch  = ks * 2 + (tl & 1);
                const uint32_t bd = base + 8192u + (uint32_t)(brow * 128
                                  + ((bch ^ (brow & 7)) << 4));
                ldsm4(bH[j], bd);
            }
            #pragma unroll
            for (int i = 0; i < 2; i++) {
                #pragma unroll
                for (int j = 0; j < 4; j++) {
                    mma_bf16(acc[i][2*j],   aH[i], &bH[j][0]);
                    mma_bf16(acc[i][2*j+1], aH[i], &bH[j][2]);
                }
            }
        }
        __syncthreads();   // WAR: stage (c&1) reads done before iter c+1's cp
    }

    // --- epilogue: v = acc + bias + res; row sums; LN; store ---
    #pragma unroll
    for (int i = 0; i < 2; i++) {
        const int rloc0 = wm * 32 + i * 16 + (lane >> 2);
        float s0 = 0.0f, q0 = 0.0f, s1 = 0.0f, q1 = 0.0f;
        #pragma unroll
        for (int j = 0; j < 8; j++) {
            const int col = wn * 64 + j * 8 + (lane & 3) * 2;
            const float b0 = bias[col], b1 = bias[col + 1];
            const long o0 = (long)(row0 + rloc0) * Dd + col;
            const long o1 = o0 + 8L * Dd;
            float v00 = acc[i][j][0] + b0 + res[o0];
            float v01 = acc[i][j][1] + b1 + res[o0 + 1];
            float v10 = acc[i][j][2] + b0 + res[o1];
            float v11 = acc[i][j][3] + b1 + res[o1 + 1];
            acc[i][j][0] = v00; acc[i][j][1] = v01;
            acc[i][j][2] = v10; acc[i][j][3] = v11;
            s0 += v00 + v01;          q0 += v00 * v00 + v01 * v01;
            s1 += v10 + v11;          q1 += v10 * v10 + v11 * v11;
        }
        #pragma unroll
        for (int o = 1; o <= 2; o <<= 1) {
            s0 += __shfl_xor_sync(0xffffffffu, s0, o);
            q0 += __shfl_xor_sync(0xffffffffu, q0, o);
            s1 += __shfl_xor_sync(0xffffffffu, s1, o);
            q1 += __shfl_xor_sync(0xffffffffu, q1, o);
        }
        if ((lane & 3) == 0) {
            atomicAdd(&sSum[rloc0], s0);     atomicAdd(&sSq[rloc0], q0);
            atomicAdd(&sSum[rloc0 + 8], s1); atomicAdd(&sSq[rloc0 + 8], q1);
        }
    }
    __syncthreads();

    #pragma unroll
    for (int i = 0; i < 2; i++) {
        const int rloc0 = wm * 32 + i * 16 + (lane >> 2);
        const float mu0  = sSum[rloc0] * (1.0f / 256.0f);
        const float var0 = sSq[rloc0] * (1.0f / 256.0f) - mu0 * mu0;
        const float in0  = rsqrtf(var0 + 1e-5f);
        const float mu1  = sSum[rloc0 + 8] * (1.0f / 256.0f);
        const float var1 = sSq[rloc0 + 8] * (1.0f / 256.0f) - mu1 * mu1;
        const float in1  = rsqrtf(var1 + 1e-5f);
        #pragma unroll
        for (int j = 0; j < 8; j++) {
            const int col = wn * 64 + j * 8 + (lane & 3) * 2;
            const float g0 = g[col], g1 = g[col + 1];
            const float e0 = beta[col], e1 = beta[col + 1];
            const long o0 = (long)(row0 + rloc0) * Dd + col;
            const long o1 = o0 + 8L * Dd;
            float y00 = (acc[i][j][0] - mu0) * in0 * g0 + e0;
            float y01 = (acc[i][j][1] - mu0) * in0 * g1 + e1;
            float y10 = (acc[i][j][2] - mu1) * in1 * g0 + e0;
            float y11 = (acc[i][j][3] - mu1) * in1 * g1 + e1;
            *(float2*)(Yf + o0) = make_float2(y00, y01);
            *(float2*)(Yf + o1) = make_float2(y10, y11);
            if (YHi) {
                *(__nv_bfloat162*)(YHi + o0) = __floats2bfloat162_rn(y00, y01);
                *(__nv_bfloat162*)(YHi + o1) = __floats2bfloat162_rn(y10, y11);
            }
        }
    }
}

// ---------------------------------------------------------------------------
// Tensor-core flash attention: 128 queries/block, 4 warps x 2 m-tiles,
// 3-stage K/V ring, one barrier/tile. K pre-scaled -> softmax is bare ex2.
// ---------------------------------------------------------------------------
__global__ void __launch_bounds__(128, 4)
attn_tc(const bf16* __restrict__ QKVh, bf16* __restrict__ OutHi)
{
    __shared__ bf16 sQ[4096];            // 128 rows hi (8 KB)
    __shared__ bf16 sK[3][2048];         // 3-stage     (12 KB)
    __shared__ bf16 sV[3][2048];         //             (12 KB)

    const int stage = blockIdx.z;
    const int qoff = stage ? 256 : 0;
    const int koff = stage ? 0 : 256;
    const int voff = stage ? 0 : 512;
    const int out_off = stage ? SEG : 0;

    const int bh = blockIdx.y;
    const int b  = bh >> 3;
    const int h  = bh & 7;
    const int q0 = blockIdx.x * 128;

    const int tid  = threadIdx.x;
    const int lane = tid & 31, warp = tid >> 5;
    const int rl = lane & 7, tl = lane >> 3;

    const uint32_t sQb = smem_u32(sQ);
    const uint32_t sKb[3] = { smem_u32(sK[0]), smem_u32(sK[1]), smem_u32(sK[2]) };
    const uint32_t sVb[3] = { smem_u32(sV[0]), smem_u32(sV[1]), smem_u32(sV[2]) };

    // --- load Q (group 0) ---
    #pragma unroll
    for (int s = 0; s < 4; s++) {
        const int c = tid + s * 128;
        const int r = c >> 2, ch = c & 3;
        const uint32_t dst = sQb + (uint32_t)(r * 64 + ((ch ^ (r & 3)) << 4));
        cp16(dst, QKVh + (long)(b * SEG + q0 + r) * NQKV + qoff + h * DK + ch * 8);
    }
    CP_COMMIT();

    const bf16* kvPtr[4];
    uint32_t kvOff[4];
    int kvArr[4];
    #pragma unroll
    for (int s = 0; s < 4; s++) {
        const int c   = tid + s * 128;
        const int arr = c >> 8;                 // 0 K, 1 V
        const int r   = (c & 255) >> 2, ch = c & 3;
        kvArr[s] = arr;
        kvOff[s] = (uint32_t)(r * 64 + ((ch ^ (r & 3)) << 4));
        const int coff = arr ? voff : koff;
        kvPtr[s] = QKVh + (long)(b * SEG + r) * NQKV + coff + h * DK + ch * 8;
    }
    const long TILE_STRIDE = 64L * NQKV;

    #pragma unroll
    for (int pc = 0; pc < 2; pc++) {
        #pragma unroll
        for (int s = 0; s < 4; s++) {
            const uint32_t dst = (kvArr[s] ? sVb[pc] : sKb[pc]) + kvOff[s];
            cp16(dst, kvPtr[s]);
            kvPtr[s] += TILE_STRIDE;
        }
        CP_COMMIT();
    }

    CP_WAIT(2);
    __syncthreads();
    uint32_t qh[2][2][4];                      // [m][ks]
    #pragma unroll
    for (int m = 0; m < 2; m++) {
        #pragma unroll
        for (int ks = 0; ks < 2; ks++) {
            const int arow = warp * 32 + m * 16 + rl + (tl & 1) * 8;
            const int ach  = ks * 2 + (tl >> 1);
            const uint32_t ad = sQb + (uint32_t)(arow * 64
                              + ((ach ^ (arow & 3)) << 4));
            ldsm4(qh[m][ks], ad);
        }
    }

    float o[2][4][4] = {};
    float lsum[2][2] = {};

    int stg = 0, pstg = 2;
    for (int t = 0; t < 16; t++) {
        if (t + 1 < 16) { CP_WAIT(1); } else { CP_WAIT(0); }
        __syncthreads();

        const uint32_t kb = sKb[stg], vb = sVb[stg];
        #pragma unroll
        for (int nb16 = 0; nb16 < 4; nb16++) {
            float s2[2][2][4] = {};
            #pragma unroll
            for (int ks = 0; ks < 2; ks++) {
                const int krow = nb16 * 16 + rl + (tl >> 1) * 8;
                const int kch  = ks * 2 + (tl & 1);
                const uint32_t ka = kb + (uint32_t)(krow * 64
                                  + ((kch ^ (krow & 3)) << 4));
                uint32_t kh[4];
                ldsm4(kh, ka);
                #pragma unroll
                for (int m = 0; m < 2; m++) {
                    mma_bf16(s2[m][0], qh[m][ks], &kh[0]);
                    mma_bf16(s2[m][1], qh[m][ks], &kh[2]);
                }
            }
            uint32_t pf[2][4];
            #pragma unroll
            for (int m = 0; m < 2; m++) {
                float p00 = ex2f(s2[m][0][0]), p01 = ex2f(s2[m][0][1]);
                float p02 = ex2f(s2[m][0][2]), p03 = ex2f(s2[m][0][3]);
                float p10 = ex2f(s2[m][1][0]), p11 = ex2f(s2[m][1][1]);
                float p12 = ex2f(s2[m][1][2]), p13 = ex2f(s2[m][1][3]);
                lsum[m][0] += p00 + p01 + p10 + p11;
                lsum[m][1] += p02 + p03 + p12 + p13;
                __nv_bfloat162 t2;
                t2 = __floats2bfloat162_rn(p00, p01); pf[m][0] = *(uint32_t*)&t2;
                t2 = __floats2bfloat162_rn(p02, p03); pf[m][1] = *(uint32_t*)&t2;
                t2 = __floats2bfloat162_rn(p10, p11); pf[m][2] = *(uint32_t*)&t2;
                t2 = __floats2bfloat162_rn(p12, p13); pf[m][3] = *(uint32_t*)&t2;
            }
            #pragma unroll
            for (int db = 0; db < 2; db++) {
                const int vrow = nb16 * 16 + rl + (tl & 1) * 8;
                const int vch  = db * 2 + (tl >> 1);
                const uint32_t va = vb + (uint32_t)(vrow * 64
                                  + ((vch ^ (vrow & 3)) << 4));
                uint32_t vf[4];
                ldsm4t(vf, va);
                #pragma unroll
                for (int m = 0; m < 2; m++) {
                    mma_bf16(o[m][db * 2],     pf[m], &vf[0]);
                    mma_bf16(o[m][db * 2 + 1], pf[m], &vf[2]);
                }
            }
        }

        if (t + 2 < 16) {
            #pragma unroll
            for (int s = 0; s < 4; s++) {
                const uint32_t dst = (kvArr[s] ? sVb[pstg] : sKb[pstg]) + kvOff[s];
                cp16(dst, kvPtr[s]);
                kvPtr[s] += TILE_STRIDE;
            }
            CP_COMMIT();
        }
        stg  = (stg  == 2) ? 0 : stg  + 1;
        pstg = (pstg == 2) ? 0 : pstg + 1;
    }

    #pragma unroll
    for (int m = 0; m < 2; m++) {
        float l0 = lsum[m][0], l1 = lsum[m][1];
        l0 += __shfl_xor_sync(0xffffffffu, l0, 1);
        l0 += __shfl_xor_sync(0xffffffffu, l0, 2);
        l1 += __shfl_xor_sync(0xffffffffu, l1, 1);
        l1 += __shfl_xor_sync(0xffffffffu, l1, 2);
        const float inv0 = 1.0f / l0;
        const float inv1 = 1.0f / l1;

        const int rloc = q0 + warp * 32 + m * 16 + (lane >> 2);
        const long row0g = (long)(b * 2 * SEG + out_off + rloc) * Dd + h * DK;
        const long row1g = row0g + 8L * Dd;
        #pragma unroll
        for (int db = 0; db < 4; db++) {
            const int col = db * 8 + (lane & 3) * 2;
            *(__nv_bfloat162*)(OutHi + row0g + col)
                = __floats2bfloat162_rn(o[m][db][0] * inv0, o[m][db][1] * inv0);
            *(__nv_bfloat162*)(OutHi + row1g + col)
                = __floats2bfloat162_rn(o[m][db][2] * inv1, o[m][db][3] * inv1);
        }
    }
}

// ---------------------------------------------------------------------------
// Launch
// ---------------------------------------------------------------------------
extern "C" void kernel_launch(void* const* d_in, const int* in_sizes, int n_in,
                              void* d_out, int out_size)
{
    const float* x   = (const float*)d_in[0];
    const float* Wq  = (const float*)d_in[1];
    const float* bq  = (const float*)d_in[2];
    const float* Wk  = (const float*)d_in[3];
    const float* bk  = (const float*)d_in[4];
    const float* Wv  = (const float*)d_in[5];
    const float* bv  = (const float*)d_in[6];
    const float* Wo  = (const float*)d_in[7];
    const float* bo  = (const float*)d_in[8];
    const float* g31 = (const float*)d_in[9];
    const float* b31 = (const float*)d_in[10];
    const float* W1  = (const float*)d_in[11];
    const float* b1  = (const float*)d_in[12];
    const float* W2  = (const float*)d_in[13];
    const float* b2  = (const float*)d_in[14];
    const float* g41 = (const float*)d_in[15];
    const float* b41 = (const float*)d_in[16];
    float* out = (float*)d_out;

    float *pH1, *pbqkv;
    bf16 *xHi, *QKVHi, *AttHi, *H1Hi, *THi;
    bf16 *WqkvT, *WoT, *W1T, *W2T;

    cudaGetSymbolAddress((void**)&pH1, g_H1);
    cudaGetSymbolAddress((void**)&pbqkv, g_bqkv);
    cudaGetSymbolAddress((void**)&xHi,   g_xHi);
    cudaGetSymbolAddress((void**)&QKVHi, g_QKVHi);
    cudaGetSymbolAddress((void**)&AttHi, g_AttHi);
    cudaGetSymbolAddress((void**)&H1Hi,  g_H1Hi);
    cudaGetSymbolAddress((void**)&THi,   g_THi);
    cudaGetSymbolAddress((void**)&WqkvT, g_WqkvT);
    cudaGetSymbolAddress((void**)&WoT, g_WoT);
    cudaGetSymbolAddress((void**)&W1T, g_W1T);
    cudaGetSymbolAddress((void**)&W2T, g_W2T);

    static bool attr_set = false;
    if (!attr_set) {
        cudaFuncSetAttribute(gemm_bf16,
            cudaFuncAttributeMaxDynamicSharedMemorySize, 98304);
        cudaFuncSetAttribute(gemm_ln,
            cudaFuncAttributeMaxDynamicSharedMemorySize, 82432);
        attr_set = true;
    }

    // weight prep + x convert
    transpose_all<<<768, dim3(32, 8)>>>(Wq, Wk, Wv, Wo, W1, W2, bq, bk, bv,
                                        WqkvT, WoT, W1T, W2T, pbqkv);
    cvt_kernel<<<(NROWS_FULL * Dd) / 1024, 256>>>(x, xHi);

    // fused QKV projection (K block scaled by KSCALE in epilogue)
    gemm_bf16<<<dim3(NROWS_HALF / 128, NQKV / 128), 256, 98304>>>(
        xHi, WqkvT, pbqkv, QKVHi, NQKV, Dd, 1, 0);

    // two-stage cross-segment attention
    attn_tc<<<dim3(SEG / 128, Bb * Hh, 2), 128>>>(QKVHi, AttHi);

    // output projection + residual(x) + LN1 (fused, 64-row tiles)
    gemm_ln<<<NROWS_FULL / 64, 256, 82432>>>(
        AttHi, WoT, bo, x, g31, b31, pH1, H1Hi, Dd);

    // W1 + gelu -> T bf16
    gemm_bf16<<<dim3(NROWS_FULL / 128, DFF / 128), 256, 98304>>>(
        H1Hi, W1T, b1, THi, DFF, Dd, 0, 1);

    // W2 + residual(H1) + LN2 (fused, 64-row tiles) -> out fp32
    gemm_ln<<<NROWS_FULL / 64, 256, 82432>>>(
        THi, W2T, b2, pH1, g41, b41, out, nullptr, DFF);
}